// round 1
// baseline (speedup 1.0000x reference)
#include <cuda_runtime.h>
#include <math.h>

#define BATCH 4
#define NPILLAR 5000
#define NPT 100
#define CPT 8
#define NX 240
#define NY 240
#define F 64      // PN_FEAT
#define C1 128    // conv hidden channels

// ---------------- scratch (device globals; no allocation allowed) ----------------
__device__ float g_pmax[BATCH * NPILLAR * F];          // 5.1 MB
__device__ float g_img [BATCH * NX * NY * F];          // 59 MB
__device__ float g_x1  [BATCH * NX * NY * C1];         // 118 MB
__device__ float g_x2  [BATCH * NX * NY * C1];         // 118 MB
__device__ int   g_winner[BATCH * NX * NY];            // 0.9 MB

// ---------------- packed f32x2 helpers (sm_103a FFMA2) ----------------
__device__ __forceinline__ unsigned long long pk2(float a, float b) {
    unsigned long long r;
    asm("mov.b64 %0, {%1,%2};" : "=l"(r) : "f"(a), "f"(b));
    return r;
}
__device__ __forceinline__ void fmaf2(unsigned long long& d, unsigned long long a, unsigned long long b) {
    asm("fma.rn.f32x2 %0, %1, %2, %0;" : "+l"(d) : "l"(a), "l"(b));
}
__device__ __forceinline__ float2 upk2(unsigned long long v) {
    float2 r;
    asm("mov.b64 {%0,%1}, %2;" : "=f"(r.x), "=f"(r.y) : "l"(v));
    return r;
}

// ---------------- 1) zero BEV image + init winner map ----------------
__global__ void zero_kernel() {
    int tid = blockIdx.x * blockDim.x + threadIdx.x;
    int stride = gridDim.x * blockDim.x;
    const int n4 = BATCH * NX * NY * F / 4;
    float4 z = make_float4(0.f, 0.f, 0.f, 0.f);
    for (int i = tid; i < n4; i += stride)
        reinterpret_cast<float4*>(g_img)[i] = z;
    for (int i = tid; i < BATCH * NX * NY; i += stride)
        g_winner[i] = -1;
}

// ---------------- 2) duplicate-cell winner: last scatter update wins = max pillar idx ----
__global__ void winner_kernel(const int* __restrict__ idxs) {
    int p = blockIdx.x * blockDim.x + threadIdx.x;
    if (p >= BATCH * NPILLAR) return;
    int b = p / NPILLAR, pl = p % NPILLAR;
    int ix = idxs[2 * p], iy = idxs[2 * p + 1];
    atomicMax(&g_winner[(b * NX + ix) * NY + iy], pl);
}

// ---------------- 3) per-point MLP + masked max (one warp per pillar) ----------------
__global__ __launch_bounds__(128) void pointnet_kernel(
    const float* __restrict__ pillars,
    const float* __restrict__ w0, const float* __restrict__ b0,
    const float* __restrict__ w1, const float* __restrict__ b1) {

    __shared__ __align__(16) float sW0[CPT][F];
    __shared__ float sB0[F];
    __shared__ __align__(16) float sW1[F][F];
    __shared__ float sB1[F];
    __shared__ __align__(16) float sH[4][F][4];   // [warp][feature][point-in-group]

    int tid = threadIdx.x;
    for (int i = tid; i < CPT * F; i += 128) ((float*)sW0)[i] = w0[i];
    for (int i = tid; i < F; i += 128) { sB0[i] = b0[i]; sB1[i] = b1[i]; }
    for (int i = tid; i < F * F; i += 128) ((float*)sW1)[i] = w1[i];
    __syncthreads();

    int warp = tid >> 5, lane = tid & 31;
    int pillar = blockIdx.x * 4 + warp;               // 20000 pillars
    const float* pb = pillars + (size_t)pillar * (NPT * CPT);

    float m0 = -3.4e38f, m1 = -3.4e38f;
    const float bb0 = sB0[2 * lane], bb1 = sB0[2 * lane + 1];
    const float cc0 = sB1[2 * lane], cc1 = sB1[2 * lane + 1];

    for (int n0 = 0; n0 < NPT; n0 += 4) {
        unsigned vmask = 0;
        // --- layer 0: h = tanh(x @ W0 + b0), staged transposed into shared ---
        #pragma unroll
        for (int r = 0; r < 4; r++) {
            const float4* pt4 = reinterpret_cast<const float4*>(pb + (size_t)(n0 + r) * CPT);
            float4 A = __ldg(pt4), Bv = __ldg(pt4 + 1);
            float x[8] = {A.x, A.y, A.z, A.w, Bv.x, Bv.y, Bv.z, Bv.w};
            float ss = 0.f;
            #pragma unroll
            for (int k = 0; k < 8; k++) ss += x[k] * x[k];
            if (ss < 1e12f) vmask |= (1u << r);       // norm < 1e6
            float a0 = bb0, a1 = bb1;
            #pragma unroll
            for (int k = 0; k < 8; k++) {
                float2 w = *reinterpret_cast<const float2*>(&sW0[k][2 * lane]);
                a0 += x[k] * w.x;
                a1 += x[k] * w.y;
            }
            sH[warp][2 * lane][r]     = tanhf(a0);
            sH[warp][2 * lane + 1][r] = tanhf(a1);
        }
        __syncwarp();
        // --- layer 1: feat = h @ W1 + b1, 4 points at once ---
        float2 f0 = make_float2(cc0, cc1), f1 = f0, f2 = f0, f3 = f0;
        #pragma unroll 8
        for (int f = 0; f < F; f++) {
            float2 w = *reinterpret_cast<const float2*>(&sW1[f][2 * lane]);
            float4 h = *reinterpret_cast<const float4*>(&sH[warp][f][0]);
            f0.x += h.x * w.x; f0.y += h.x * w.y;
            f1.x += h.y * w.x; f1.y += h.y * w.y;
            f2.x += h.z * w.x; f2.y += h.z * w.y;
            f3.x += h.w * w.x; f3.y += h.w * w.y;
        }
        m0 = fmaxf(m0, (vmask & 1u) ? f0.x : 0.f);  m1 = fmaxf(m1, (vmask & 1u) ? f0.y : 0.f);
        m0 = fmaxf(m0, (vmask & 2u) ? f1.x : 0.f);  m1 = fmaxf(m1, (vmask & 2u) ? f1.y : 0.f);
        m0 = fmaxf(m0, (vmask & 4u) ? f2.x : 0.f);  m1 = fmaxf(m1, (vmask & 4u) ? f2.y : 0.f);
        m0 = fmaxf(m0, (vmask & 8u) ? f3.x : 0.f);  m1 = fmaxf(m1, (vmask & 8u) ? f3.y : 0.f);
        __syncwarp();
    }
    g_pmax[(size_t)pillar * F + 2 * lane]     = m0;
    g_pmax[(size_t)pillar * F + 2 * lane + 1] = m1;
}

// ---------------- 4) scatter winning pillar features into BEV image ----------------
__global__ void scatter_kernel(const int* __restrict__ idxs) {
    int p = blockIdx.x;                  // 20000 blocks, 64 threads
    int f = threadIdx.x;
    int b = p / NPILLAR, pl = p % NPILLAR;
    int ix = idxs[2 * p], iy = idxs[2 * p + 1];
    int cell = (b * NX + ix) * NY + iy;
    if (g_winner[cell] == pl)
        g_img[(size_t)cell * F + f] = g_pmax[(size_t)p * F + f];
}

// ---------------- 5) 3x3 conv, COUT=128, register-tiled, FFMA2 over co-pairs ----------
// Block: 256 threads = (tco 0..15) x (tpx 0..15). Tile: 8 rows x 16 cols x 128 co.
// Thread: 8 consecutive pixels (one half-row) x 8 cos (4 packed co-pairs).
template <int CIN, bool DO_TANH>
__global__ __launch_bounds__(256, 2) void conv3x3_kernel(
    const float* __restrict__ in, const float* __restrict__ w,
    const float* __restrict__ bias, float* __restrict__ out) {

    __shared__ __align__(16) float sW[9][8][C1];     // 36864 B
    __shared__ __align__(16) float sIn[10][18][8];   //  5760 B  [row][col][ci]

    int tid = threadIdx.x;
    int tco = tid & 15, tpx = tid >> 4;
    int bb = blockIdx.z;
    int y0 = blockIdx.y * 8, x0 = blockIdx.x * 16;
    int row  = tpx >> 1;          // 0..7
    int colb = (tpx & 1) * 8;     // 0 or 8

    unsigned long long acc[4][8];
    #pragma unroll
    for (int j = 0; j < 4; j++)
        #pragma unroll
        for (int m = 0; m < 8; m++) acc[j][m] = 0ull;   // packed (0.f, 0.f)

    for (int c0 = 0; c0 < CIN; c0 += 8) {
        __syncthreads();
        // weights slab: 9 x 8ci x 128co
        #pragma unroll
        for (int i = tid; i < 9 * 8 * C1; i += 256) {
            int dydx = i >> 10;
            int rem  = i & 1023;
            int k = rem >> 7, co = rem & 127;
            sW[dydx][k][co] = w[((size_t)dydx * CIN + c0 + k) * C1 + co];
        }
        // input halo tile: 10 x 18 x 8ci (zero-padded SAME borders)
        for (int i = tid; i < 10 * 18 * 8; i += 256) {
            int k = i & 7;
            int c = (i >> 3) % 18;
            int r = i / (18 * 8);
            int gy = y0 - 1 + r, gx = x0 - 1 + c;
            float v = 0.f;
            if (gy >= 0 && gy < NX && gx >= 0 && gx < NY)
                v = in[(((size_t)bb * NX + gy) * NY + gx) * CIN + c0 + k];
            sIn[r][c][k] = v;
        }
        __syncthreads();

        #pragma unroll
        for (int dy = 0; dy < 3; dy++)
        #pragma unroll
        for (int dx = 0; dx < 3; dx++)
        #pragma unroll
        for (int k = 0; k < 8; k++) {
            unsigned long long w2[4];
            #pragma unroll
            for (int j = 0; j < 4; j++)
                w2[j] = *reinterpret_cast<const unsigned long long*>(
                            &sW[dy * 3 + dx][k][2 * tco + 32 * j]);
            #pragma unroll
            for (int m = 0; m < 8; m++) {
                float xv = sIn[row + dy][colb + m + dx][k];
                unsigned long long x2 = pk2(xv, xv);
                #pragma unroll
                for (int j = 0; j < 4; j++) fmaf2(acc[j][m], x2, w2[j]);
            }
        }
    }

    // epilogue: bias (+ tanh) + store
    #pragma unroll
    for (int j = 0; j < 4; j++) {
        int co = 2 * tco + 32 * j;
        float b0v = __ldg(&bias[co]), b1v = __ldg(&bias[co + 1]);
        #pragma unroll
        for (int m = 0; m < 8; m++) {
            float2 v = upk2(acc[j][m]);
            v.x += b0v; v.y += b1v;
            if (DO_TANH) { v.x = tanhf(v.x); v.y = tanhf(v.y); }
            int gy = y0 + row, gx = x0 + colb + m;
            *reinterpret_cast<float2*>(
                &out[(((size_t)bb * NX + gy) * NY + gx) * C1 + co]) = v;
        }
    }
}

// ---------------- 6) 1x1 conv 128->1 + ReLU ----------------
__global__ void conv1x1_kernel(const float* __restrict__ w2, const float* __restrict__ b2,
                               float* __restrict__ out) {
    __shared__ float sw[C1];
    int tid = threadIdx.x;
    if (tid < C1) sw[tid] = w2[tid];
    __syncthreads();
    int pix = blockIdx.x * 256 + tid;        // 230400 pixels = 900 blocks exactly
    const float4* p = reinterpret_cast<const float4*>(&g_x2[(size_t)pix * C1]);
    float s = 0.f;
    #pragma unroll
    for (int i = 0; i < C1 / 4; i++) {
        float4 v = p[i];
        float4 wv = *reinterpret_cast<const float4*>(&sw[4 * i]);
        s += v.x * wv.x + v.y * wv.y + v.z * wv.z + v.w * wv.w;
    }
    s += __ldg(b2);
    out[pix] = fmaxf(s, 0.f);
}

// ---------------- host launcher ----------------
extern "C" void kernel_launch(void* const* d_in, const int* in_sizes, int n_in,
                              void* d_out, int out_size) {
    const float* pillars = (const float*)d_in[0];
    const int*   idxs    = (const int*)d_in[1];
    // d_in[2], d_in[3]: nx, ny scalars (fixed 240 for this problem)
    const float* pn_w0 = (const float*)d_in[4];
    const float* pn_b0 = (const float*)d_in[5];
    const float* pn_w1 = (const float*)d_in[6];
    const float* pn_b1 = (const float*)d_in[7];
    const float* cw0   = (const float*)d_in[8];
    const float* cb0   = (const float*)d_in[9];
    const float* cw1   = (const float*)d_in[10];
    const float* cb1   = (const float*)d_in[11];
    const float* cw2   = (const float*)d_in[12];
    const float* cb2   = (const float*)d_in[13];
    float* out = (float*)d_out;

    float *p_img, *p_x1, *p_x2;
    cudaGetSymbolAddress((void**)&p_img, g_img);
    cudaGetSymbolAddress((void**)&p_x1, g_x1);
    cudaGetSymbolAddress((void**)&p_x2, g_x2);

    zero_kernel<<<2048, 256>>>();
    winner_kernel<<<(BATCH * NPILLAR + 255) / 256, 256>>>(idxs);
    pointnet_kernel<<<BATCH * NPILLAR / 4, 128>>>(pillars, pn_w0, pn_b0, pn_w1, pn_b1);
    scatter_kernel<<<BATCH * NPILLAR, 64>>>(idxs);

    dim3 cgrid(NX / 16, NY / 8, BATCH);   // (15, 30, 4)
    conv3x3_kernel<F, true><<<cgrid, 256>>>(p_img, cw0, cb0, p_x1);
    conv3x3_kernel<C1, true><<<cgrid, 256>>>(p_x1, cw1, cb1, p_x2);
    conv1x1_kernel<<<BATCH * NX * NY / 256, 256>>>(cw2, cb2, out);
}

// round 4
// speedup vs baseline: 1.7657x; 1.7657x over previous
#include <cuda_runtime.h>
#include <cuda_bf16.h>
#include <cstdint>
#include <math.h>

#define BATCH 4
#define NPILLAR 5000
#define NPT 100
#define CPT 8
#define NX 240
#define NY 240
#define F 64      // PN_FEAT
#define C1 128    // conv hidden channels

// ---------------- scratch (device globals; no allocation allowed) ----------------
__device__ float g_pmax[BATCH * NPILLAR * F];
__device__ float g_img [BATCH * NX * NY * F];
__device__ float g_x1  [BATCH * NX * NY * C1];
__device__ float g_x2  [BATCH * NX * NY * C1];
__device__ int   g_winner[BATCH * NX * NY];
// padded bf16 hi/lo weights: [tap][co][KP] with KP = 2*CIN+8
__device__ __align__(16) __nv_bfloat16 g_wb1[9 * 128 * (2 * 64 + 8)];    // conv1
__device__ __align__(16) __nv_bfloat16 g_wb2[9 * 128 * (2 * 128 + 8)];   // conv2

// ---------------- HMMA m16n8k16 bf16 (plain sm_80+ PTX; no 'a' features) --------
__device__ __forceinline__ void mma16816(float* d, const uint32_t* a, const uint32_t* b) {
    asm volatile(
        "mma.sync.aligned.m16n8k16.row.col.f32.bf16.bf16.f32 "
        "{%0,%1,%2,%3}, {%4,%5,%6,%7}, {%8,%9}, {%0,%1,%2,%3};"
        : "+f"(d[0]), "+f"(d[1]), "+f"(d[2]), "+f"(d[3])
        : "r"(a[0]), "r"(a[1]), "r"(a[2]), "r"(a[3]), "r"(b[0]), "r"(b[1]));
}

// ---------------- 1) zero BEV image + init winner map ----------------
__global__ void zero_kernel() {
    int tid = blockIdx.x * blockDim.x + threadIdx.x;
    int stride = gridDim.x * blockDim.x;
    const int n4 = BATCH * NX * NY * F / 4;
    float4 z = make_float4(0.f, 0.f, 0.f, 0.f);
    for (int i = tid; i < n4; i += stride)
        reinterpret_cast<float4*>(g_img)[i] = z;
    for (int i = tid; i < BATCH * NX * NY; i += stride)
        g_winner[i] = -1;
}

// ---------------- 2) duplicate-cell winner (last update wins = max pillar idx) ---
__global__ void winner_kernel(const int* __restrict__ idxs) {
    int p = blockIdx.x * blockDim.x + threadIdx.x;
    if (p >= BATCH * NPILLAR) return;
    int b = p / NPILLAR, pl = p % NPILLAR;
    int ix = idxs[2 * p], iy = idxs[2 * p + 1];
    atomicMax(&g_winner[(b * NX + ix) * NY + iy], pl);
}

// ---------------- 3) per-point MLP + masked max (one warp per pillar) ------------
__global__ __launch_bounds__(128) void pointnet_kernel(
    const float* __restrict__ pillars,
    const float* __restrict__ w0, const float* __restrict__ b0,
    const float* __restrict__ w1, const float* __restrict__ b1) {

    __shared__ __align__(16) float sW0[CPT][F];
    __shared__ float sB0[F];
    __shared__ __align__(16) float sW1[F][F];
    __shared__ float sB1[F];
    __shared__ __align__(16) float sH[4][F][4];

    int tid = threadIdx.x;
    for (int i = tid; i < CPT * F; i += 128) ((float*)sW0)[i] = w0[i];
    for (int i = tid; i < F; i += 128) { sB0[i] = b0[i]; sB1[i] = b1[i]; }
    for (int i = tid; i < F * F; i += 128) ((float*)sW1)[i] = w1[i];
    __syncthreads();

    int warp = tid >> 5, lane = tid & 31;
    int pillar = blockIdx.x * 4 + warp;
    const float* pb = pillars + (size_t)pillar * (NPT * CPT);

    float m0 = -3.4e38f, m1 = -3.4e38f;
    const float bb0 = sB0[2 * lane], bb1 = sB0[2 * lane + 1];
    const float cc0 = sB1[2 * lane], cc1 = sB1[2 * lane + 1];

    for (int n0 = 0; n0 < NPT; n0 += 4) {
        unsigned vmask = 0;
        #pragma unroll
        for (int r = 0; r < 4; r++) {
            const float4* pt4 = reinterpret_cast<const float4*>(pb + (size_t)(n0 + r) * CPT);
            float4 A = __ldg(pt4), Bv = __ldg(pt4 + 1);
            float x[8] = {A.x, A.y, A.z, A.w, Bv.x, Bv.y, Bv.z, Bv.w};
            float ss = 0.f;
            #pragma unroll
            for (int k = 0; k < 8; k++) ss += x[k] * x[k];
            if (ss < 1e12f) vmask |= (1u << r);
            float a0 = bb0, a1 = bb1;
            #pragma unroll
            for (int k = 0; k < 8; k++) {
                float2 w = *reinterpret_cast<const float2*>(&sW0[k][2 * lane]);
                a0 += x[k] * w.x;
                a1 += x[k] * w.y;
            }
            sH[warp][2 * lane][r]     = tanhf(a0);
            sH[warp][2 * lane + 1][r] = tanhf(a1);
        }
        __syncwarp();
        float2 f0 = make_float2(cc0, cc1), f1 = f0, f2 = f0, f3 = f0;
        #pragma unroll 8
        for (int f = 0; f < F; f++) {
            float2 w = *reinterpret_cast<const float2*>(&sW1[f][2 * lane]);
            float4 h = *reinterpret_cast<const float4*>(&sH[warp][f][0]);
            f0.x += h.x * w.x; f0.y += h.x * w.y;
            f1.x += h.y * w.x; f1.y += h.y * w.y;
            f2.x += h.z * w.x; f2.y += h.z * w.y;
            f3.x += h.w * w.x; f3.y += h.w * w.y;
        }
        m0 = fmaxf(m0, (vmask & 1u) ? f0.x : 0.f);  m1 = fmaxf(m1, (vmask & 1u) ? f0.y : 0.f);
        m0 = fmaxf(m0, (vmask & 2u) ? f1.x : 0.f);  m1 = fmaxf(m1, (vmask & 2u) ? f1.y : 0.f);
        m0 = fmaxf(m0, (vmask & 4u) ? f2.x : 0.f);  m1 = fmaxf(m1, (vmask & 4u) ? f2.y : 0.f);
        m0 = fmaxf(m0, (vmask & 8u) ? f3.x : 0.f);  m1 = fmaxf(m1, (vmask & 8u) ? f3.y : 0.f);
        __syncwarp();
    }
    g_pmax[(size_t)pillar * F + 2 * lane]     = m0;
    g_pmax[(size_t)pillar * F + 2 * lane + 1] = m1;
}

// ---------------- 4) scatter winning pillar features into BEV image --------------
__global__ void scatter_kernel(const int* __restrict__ idxs) {
    int p = blockIdx.x;
    int f = threadIdx.x;
    int b = p / NPILLAR, pl = p % NPILLAR;
    int ix = idxs[2 * p], iy = idxs[2 * p + 1];
    int cell = (b * NX + ix) * NY + iy;
    if (g_winner[cell] == pl)
        g_img[(size_t)cell * F + f] = g_pmax[(size_t)p * F + f];
}

// ---------------- 5a) weight prep: fp32 -> bf16 hi/lo, padded [tap][co][KP] ------
template <int CIN>
__global__ void wprep_kernel(const float* __restrict__ w, __nv_bfloat16* __restrict__ wb) {
    constexpr int KP = 2 * CIN + 8;
    int i = blockIdx.x * 256 + threadIdx.x;
    if (i >= 9 * 128 * CIN) return;
    int ci = i % CIN;
    int co = (i / CIN) % 128;
    int tap = i / (CIN * 128);
    float v = w[((size_t)tap * CIN + ci) * C1 + co];
    __nv_bfloat16 h = __float2bfloat16(v);
    __nv_bfloat16 l = __float2bfloat16(v - __bfloat162float(h));
    size_t base = ((size_t)tap * 128 + co) * KP;
    wb[base + ci] = h;
    wb[base + CIN + ci] = l;
    if (ci < 8) wb[base + 2 * CIN + ci] = __float2bfloat16(0.f);
}

// ---------------- 5b) 3x3 conv via HMMA bf16-split implicit GEMM -----------------
// CTA: 8x16 px tile (M=128) x 128 cout. 8 warps: (mwarp 0..3) x (nwarp 0..1).
// Warp tile 32px x 64co = 2 m-tiles x 8 n-tiles of m16n8k16.
// Halo (10x18 px, hi|lo bf16) staged once; B (weights) staged per tap.
template <int CIN>
__global__ __launch_bounds__(256) void conv3x3_hmma(
    const float* __restrict__ in, const __nv_bfloat16* __restrict__ wb,
    const float* __restrict__ bias, float* __restrict__ out) {

    constexpr int KP = 2 * CIN + 8;        // bf16 row stride (word offset 4g+q: conflict-free)
    extern __shared__ char smem[];
    __nv_bfloat16* sA = (__nv_bfloat16*)smem;                      // 180 * KP
    __nv_bfloat16* sB = (__nv_bfloat16*)(smem + 180 * KP * 2);     // 128 * KP
    float* sbias = (float*)(smem + (180 + 128) * KP * 2);

    int tid = threadIdx.x, lane = tid & 31, wid = tid >> 5;
    int bb = blockIdx.z;
    int y0 = blockIdx.y * 8, x0 = blockIdx.x * 16;
    if (tid < 128) sbias[tid] = bias[tid];

    // ---- stage halo: 180 px x CIN fp32 -> bf16 hi|lo ----
    constexpr int CH = CIN / 16;
    for (int t = tid; t < 180 * CH; t += 256) {
        int hp = t / CH, c0 = (t % CH) * 16;
        int hr = hp / 18, hc = hp % 18;
        int gy = y0 - 1 + hr, gx = x0 - 1 + hc;
        __nv_bfloat16* dhi = &sA[hp * KP + c0];
        __nv_bfloat16* dlo = dhi + CIN;
        if (gy >= 0 && gy < NX && gx >= 0 && gx < NY) {
            const float4* s = (const float4*)&in[(((size_t)bb * NX + gy) * NY + gx) * CIN + c0];
            __nv_bfloat16 hi[16], lo[16];
            #pragma unroll
            for (int j = 0; j < 4; j++) {
                float4 v = __ldg(s + j);
                float vv[4] = {v.x, v.y, v.z, v.w};
                #pragma unroll
                for (int q = 0; q < 4; q++) {
                    __nv_bfloat16 h = __float2bfloat16(vv[q]);
                    hi[j * 4 + q] = h;
                    lo[j * 4 + q] = __float2bfloat16(vv[q] - __bfloat162float(h));
                }
            }
            *(uint4*)dhi = *(uint4*)hi;  *(uint4*)(dhi + 8) = *(uint4*)(hi + 8);
            *(uint4*)dlo = *(uint4*)lo;  *(uint4*)(dlo + 8) = *(uint4*)(lo + 8);
        } else {
            uint4 z = make_uint4(0, 0, 0, 0);
            *(uint4*)dhi = z; *(uint4*)(dhi + 8) = z;
            *(uint4*)dlo = z; *(uint4*)(dlo + 8) = z;
        }
    }

    float acc[2][8][4] = {};
    const int mwarp = wid >> 1, nwarp = wid & 1;
    const int gi = lane >> 2;          // group id
    const int q2 = (lane & 3) * 2;     // k / col offset

    for (int tap = 0; tap < 9; ++tap) {
        __syncthreads();   // mma of previous tap done before sB overwrite (also fences halo on tap 0)
        {   // copy B slab for this tap (pre-padded, contiguous)
            const uint4* src = (const uint4*)(wb + (size_t)tap * 128 * KP);
            uint4* dst = (uint4*)sB;
            for (int t = tid; t < 128 * KP / 8; t += 256) dst[t] = src[t];
        }
        __syncthreads();

        const int dy = tap / 3 - 1, dx = tap % 3 - 1;
        uint32_t arow[2][2];
        #pragma unroll
        for (int mt = 0; mt < 2; mt++) {
            int r = mwarp * 2 + mt;            // CTA-tile pixel row (m = r*16 + c)
            int hr = r + 1 + dy;
            int hc0 = 1 + dx;
            arow[mt][0] = (hr * 18 + hc0 + gi) * KP;
            arow[mt][1] = (hr * 18 + hc0 + gi + 8) * KP;
        }

        #pragma unroll
        for (int seg = 0; seg < 3; ++seg) {    // (hi,hi), (lo,hi), (hi,lo)
            const int aoff = (seg == 1) ? CIN : 0;
            const int boff = (seg == 2) ? CIN : 0;
            #pragma unroll 4
            for (int k0 = 0; k0 < CIN; k0 += 16) {
                const int ka = aoff + k0 + q2;
                uint32_t a[2][4];
                #pragma unroll
                for (int mt = 0; mt < 2; mt++) {
                    a[mt][0] = *(const uint32_t*)&sA[arow[mt][0] + ka];
                    a[mt][1] = *(const uint32_t*)&sA[arow[mt][1] + ka];
                    a[mt][2] = *(const uint32_t*)&sA[arow[mt][0] + ka + 8];
                    a[mt][3] = *(const uint32_t*)&sA[arow[mt][1] + ka + 8];
                }
                const int kb = boff + k0 + q2;
                #pragma unroll
                for (int nt = 0; nt < 8; nt++) {
                    const int n = nwarp * 64 + nt * 8 + gi;
                    uint32_t b[2];
                    b[0] = *(const uint32_t*)&sB[n * KP + kb];
                    b[1] = *(const uint32_t*)&sB[n * KP + kb + 8];
                    mma16816(acc[0][nt], a[0], b);
                    mma16816(acc[1][nt], a[1], b);
                }
            }
        }
    }

    // ---- epilogue: bias + tanh + store ----
    #pragma unroll
    for (int mt = 0; mt < 2; mt++) {
        int gy = y0 + mwarp * 2 + mt;
        #pragma unroll
        for (int half = 0; half < 2; half++) {
            int gx = x0 + gi + half * 8;
            float* op = &out[(((size_t)bb * NX + gy) * NY + gx) * C1];
            #pragma unroll
            for (int nt = 0; nt < 8; nt++) {
                int n = nwarp * 64 + nt * 8 + q2;
                float2 v;
                v.x = tanhf(acc[mt][nt][half * 2 + 0] + sbias[n]);
                v.y = tanhf(acc[mt][nt][half * 2 + 1] + sbias[n + 1]);
                *(float2*)&op[n] = v;
            }
        }
    }
}

// ---------------- 6) 1x1 conv 128->1 + ReLU ----------------
__global__ void conv1x1_kernel(const float* __restrict__ w2, const float* __restrict__ b2,
                               float* __restrict__ out) {
    __shared__ float sw[C1];
    int tid = threadIdx.x;
    if (tid < C1) sw[tid] = w2[tid];
    __syncthreads();
    int pix = blockIdx.x * 256 + tid;
    const float4* p = reinterpret_cast<const float4*>(&g_x2[(size_t)pix * C1]);
    float s = 0.f;
    #pragma unroll
    for (int i = 0; i < C1 / 4; i++) {
        float4 v = p[i];
        float4 wv = *reinterpret_cast<const float4*>(&sw[4 * i]);
        s += v.x * wv.x + v.y * wv.y + v.z * wv.z + v.w * wv.w;
    }
    s += __ldg(b2);
    out[pix] = fmaxf(s, 0.f);
}

// ---------------- host launcher ----------------
extern "C" void kernel_launch(void* const* d_in, const int* in_sizes, int n_in,
                              void* d_out, int out_size) {
    const float* pillars = (const float*)d_in[0];
    const int*   idxs    = (const int*)d_in[1];
    const float* pn_w0 = (const float*)d_in[4];
    const float* pn_b0 = (const float*)d_in[5];
    const float* pn_w1 = (const float*)d_in[6];
    const float* pn_b1 = (const float*)d_in[7];
    const float* cw0   = (const float*)d_in[8];
    const float* cb0   = (const float*)d_in[9];
    const float* cw1   = (const float*)d_in[10];
    const float* cb1   = (const float*)d_in[11];
    const float* cw2   = (const float*)d_in[12];
    const float* cb2   = (const float*)d_in[13];
    float* out = (float*)d_out;

    float *p_img, *p_x1, *p_x2;
    __nv_bfloat16 *p_wb1, *p_wb2;
    cudaGetSymbolAddress((void**)&p_img, g_img);
    cudaGetSymbolAddress((void**)&p_x1, g_x1);
    cudaGetSymbolAddress((void**)&p_x2, g_x2);
    cudaGetSymbolAddress((void**)&p_wb1, g_wb1);
    cudaGetSymbolAddress((void**)&p_wb2, g_wb2);

    const int KP1 = 2 * 64 + 8, KP2 = 2 * 128 + 8;
    const int smem1 = (180 + 128) * KP1 * 2 + 512;   //  84,288 B
    const int smem2 = (180 + 128) * KP2 * 2 + 512;   // 163,136 B
    cudaFuncSetAttribute(conv3x3_hmma<64>,  cudaFuncAttributeMaxDynamicSharedMemorySize, smem1);
    cudaFuncSetAttribute(conv3x3_hmma<128>, cudaFuncAttributeMaxDynamicSharedMemorySize, smem2);

    zero_kernel<<<2048, 256>>>();
    winner_kernel<<<(BATCH * NPILLAR + 255) / 256, 256>>>(idxs);
    wprep_kernel<64> <<<(9 * 128 * 64 + 255) / 256, 256>>>(cw0, p_wb1);
    wprep_kernel<128><<<(9 * 128 * 128 + 255) / 256, 256>>>(cw1, p_wb2);
    pointnet_kernel<<<BATCH * NPILLAR / 4, 128>>>(pillars, pn_w0, pn_b0, pn_w1, pn_b1);
    scatter_kernel<<<BATCH * NPILLAR, 64>>>(idxs);

    dim3 cgrid(NX / 16, NY / 8, BATCH);   // (15, 30, 4)
    conv3x3_hmma<64> <<<cgrid, 256, smem1>>>(p_img, p_wb1, cb0, p_x1);
    conv3x3_hmma<128><<<cgrid, 256, smem2>>>(p_x1,  p_wb2, cb1, p_x2);
    conv1x1_kernel<<<BATCH * NX * NY / 256, 256>>>(cw2, cb2, out);
}

// round 5
// speedup vs baseline: 2.0387x; 1.1546x over previous
#include <cuda_runtime.h>
#include <cuda_bf16.h>
#include <cstdint>
#include <math.h>
#include <float.h>

#define BATCH 4
#define NPILLAR 5000
#define NPT 100
#define CPT 8
#define NX 240
#define NY 240
#define F 64      // PN_FEAT
#define C1 128    // conv hidden channels
#define KH 136    // padded bf16 K stride (hi 0-63 | lo 64-127 | pad)

// ---------------- scratch (device globals; no allocation allowed) ----------------
__device__ float g_pmax[BATCH * NPILLAR * F];
__device__ float g_img [BATCH * NX * NY * F];
__device__ float g_x1  [BATCH * NX * NY * C1];
__device__ float g_x2  [BATCH * NX * NY * C1];
__device__ int   g_winner[BATCH * NX * NY];
// padded bf16 hi/lo weights: [tap][co][KP] with KP = 2*CIN+8
__device__ __align__(16) __nv_bfloat16 g_wb1[9 * 128 * (2 * 64 + 8)];    // conv1
__device__ __align__(16) __nv_bfloat16 g_wb2[9 * 128 * (2 * 128 + 8)];   // conv2

// ---------------- HMMA m16n8k16 bf16 (plain sm_80+ PTX; no 'a' features) --------
__device__ __forceinline__ void mma16816(float* d, const uint32_t* a, const uint32_t* b) {
    asm volatile(
        "mma.sync.aligned.m16n8k16.row.col.f32.bf16.bf16.f32 "
        "{%0,%1,%2,%3}, {%4,%5,%6,%7}, {%8,%9}, {%0,%1,%2,%3};"
        : "+f"(d[0]), "+f"(d[1]), "+f"(d[2]), "+f"(d[3])
        : "r"(a[0]), "r"(a[1]), "r"(a[2]), "r"(a[3]), "r"(b[0]), "r"(b[1]));
}
__device__ __forceinline__ uint32_t smem_u32(const void* p) {
    uint32_t a;
    asm("{ .reg .u64 t; cvta.to.shared.u64 t, %1; cvt.u32.u64 %0, t; }" : "=r"(a) : "l"(p));
    return a;
}
__device__ __forceinline__ void cpasync16(uint32_t s, const void* g) {
    asm volatile("cp.async.cg.shared.global [%0], [%1], 16;" :: "r"(s), "l"(g));
}
#define CP_COMMIT() asm volatile("cp.async.commit_group;" ::: "memory")
#define CP_WAIT0()  asm volatile("cp.async.wait_group 0;" ::: "memory")

// ---------------- 1) zero BEV image + init winner map ----------------
__global__ void zero_kernel() {
    int tid = blockIdx.x * blockDim.x + threadIdx.x;
    int stride = gridDim.x * blockDim.x;
    const int n4 = BATCH * NX * NY * F / 4;
    float4 z = make_float4(0.f, 0.f, 0.f, 0.f);
    for (int i = tid; i < n4; i += stride)
        reinterpret_cast<float4*>(g_img)[i] = z;
    for (int i = tid; i < BATCH * NX * NY; i += stride)
        g_winner[i] = -1;
}

// ---------------- 2) duplicate-cell winner (last update wins = max pillar idx) ---
__global__ void winner_kernel(const int* __restrict__ idxs) {
    int p = blockIdx.x * blockDim.x + threadIdx.x;
    if (p >= BATCH * NPILLAR) return;
    int b = p / NPILLAR, pl = p % NPILLAR;
    int ix = idxs[2 * p], iy = idxs[2 * p + 1];
    atomicMax(&g_winner[(b * NX + ix) * NY + iy], pl);
}

// ---------------- 3) pointnet: layer0 scalar+tanh, layer1 HMMA, masked max ------
// CTA = 256 threads, 8 warps, 2 pillars (128 padded rows each).
// Row codes: 0 = valid point, 1 = invalid point (feat -> 0), 2 = padding (-inf).
__global__ __launch_bounds__(256) void pointnet_hmma(
    const float* __restrict__ pillars,
    const float* __restrict__ w0, const float* __restrict__ b0,
    const float* __restrict__ w1, const float* __restrict__ b1) {

    extern __shared__ char sm[];
    __nv_bfloat16* sH  = (__nv_bfloat16*)sm;                       // 256 * KH
    __nv_bfloat16* sW  = (__nv_bfloat16*)(sm + 256 * KH * 2);      // 64 * KH
    float* sW0  = (float*)(sm + (256 + 64) * KH * 2);              // 8*64
    float* sB0  = sW0 + 512;                                       // 64
    float* sB1  = sB0 + 64;                                        // 64
    float* sRed = sB1 + 64;                                        // 8*64
    int*   sCode = (int*)(sRed + 512);                             // 256

    int tid = threadIdx.x, lane = tid & 31, wid = tid >> 5;

    // stage weights
    for (int i = tid; i < 512; i += 256) sW0[i] = w0[i];
    if (tid < 64) { sB0[tid] = b0[tid]; sB1[tid] = b1[tid]; }
    for (int i = tid; i < 4096; i += 256) {
        int k = i >> 6, n = i & 63;
        float v = w1[i];
        __nv_bfloat16 h = __float2bfloat16(v);
        sW[n * KH + k]      = h;
        sW[n * KH + 64 + k] = __float2bfloat16(v - __bfloat162float(h));
    }
    __syncthreads();

    // ---- layer 0: one thread per row ----
    {
        int row = tid;
        int pt = row & 127;
        uint32_t* dst = (uint32_t*)&sH[row * KH];
        if (pt < NPT) {
            int pil = blockIdx.x * 2 + (row >> 7);
            const float4* px = (const float4*)(pillars + ((size_t)pil * NPT + pt) * CPT);
            float4 A = __ldg(px), B = __ldg(px + 1);
            float x[8] = {A.x, A.y, A.z, A.w, B.x, B.y, B.z, B.w};
            float ss = 0.f;
            #pragma unroll
            for (int k = 0; k < 8; k++) ss += x[k] * x[k];
            sCode[row] = (ss < 1e12f) ? 0 : 1;
            #pragma unroll
            for (int n0 = 0; n0 < 64; n0 += 16) {
                uint32_t hw[8], lw[8];
                #pragma unroll
                for (int q = 0; q < 8; q++) {
                    int n = n0 + 2 * q;
                    float a0 = sB0[n], a1 = sB0[n + 1];
                    #pragma unroll
                    for (int k = 0; k < 8; k++) {
                        a0 += x[k] * sW0[k * 64 + n];
                        a1 += x[k] * sW0[k * 64 + n + 1];
                    }
                    a0 = tanhf(a0); a1 = tanhf(a1);
                    __nv_bfloat162 hp, lp;
                    hp.x = __float2bfloat16(a0);
                    hp.y = __float2bfloat16(a1);
                    lp.x = __float2bfloat16(a0 - __bfloat162float(hp.x));
                    lp.y = __float2bfloat16(a1 - __bfloat162float(hp.y));
                    hw[q] = *(uint32_t*)&hp;
                    lw[q] = *(uint32_t*)&lp;
                }
                *(uint4*)(dst + n0 / 2)          = make_uint4(hw[0], hw[1], hw[2], hw[3]);
                *(uint4*)(dst + n0 / 2 + 4)      = make_uint4(hw[4], hw[5], hw[6], hw[7]);
                *(uint4*)(dst + 32 + n0 / 2)     = make_uint4(lw[0], lw[1], lw[2], lw[3]);
                *(uint4*)(dst + 32 + n0 / 2 + 4) = make_uint4(lw[4], lw[5], lw[6], lw[7]);
            }
        } else {
            sCode[row] = 2;
            uint4 z = make_uint4(0, 0, 0, 0);
            #pragma unroll
            for (int j = 0; j < 16; j++) *(uint4*)(dst + 4 * j) = z;
        }
    }
    __syncthreads();

    // ---- layer 1 via HMMA: warp = 32 rows x 64 cols ----
    const int gi = lane >> 2, q2 = (lane & 3) * 2;
    const int wbase = wid * 32;
    float acc[2][8][4] = {};
    #pragma unroll
    for (int seg = 0; seg < 3; ++seg) {
        const int aoff = (seg == 1) ? 64 : 0;
        const int boff = (seg == 2) ? 64 : 0;
        #pragma unroll
        for (int k0 = 0; k0 < 64; k0 += 16) {
            const int ka = aoff + k0 + q2;
            uint32_t a[2][4];
            #pragma unroll
            for (int mt = 0; mt < 2; mt++) {
                int r0 = (wbase + mt * 16 + gi) * KH;
                int r1 = r0 + 8 * KH;
                a[mt][0] = *(const uint32_t*)&sH[r0 + ka];
                a[mt][1] = *(const uint32_t*)&sH[r1 + ka];
                a[mt][2] = *(const uint32_t*)&sH[r0 + ka + 8];
                a[mt][3] = *(const uint32_t*)&sH[r1 + ka + 8];
            }
            const int kb = boff + k0 + q2;
            #pragma unroll
            for (int nt = 0; nt < 8; nt++) {
                const int n = nt * 8 + gi;
                uint32_t b[2];
                b[0] = *(const uint32_t*)&sW[n * KH + kb];
                b[1] = *(const uint32_t*)&sW[n * KH + kb + 8];
                mma16816(acc[0][nt], a[0], b);
                mma16816(acc[1][nt], a[1], b);
            }
        }
    }

    // ---- masked max reduction ----
    #pragma unroll
    for (int nt = 0; nt < 8; nt++) {
        int col = nt * 8 + q2;
        float bA = sB1[col], bB = sB1[col + 1];
        float vA = -FLT_MAX, vB = -FLT_MAX;
        #pragma unroll
        for (int mt = 0; mt < 2; mt++) {
            int r0 = wbase + mt * 16 + gi, r1 = r0 + 8;
            int c0 = sCode[r0], c1 = sCode[r1];
            float f;
            f = (c0 == 0) ? acc[mt][nt][0] + bA : ((c0 == 1) ? 0.f : -FLT_MAX);
            vA = fmaxf(vA, f);
            f = (c1 == 0) ? acc[mt][nt][2] + bA : ((c1 == 1) ? 0.f : -FLT_MAX);
            vA = fmaxf(vA, f);
            f = (c0 == 0) ? acc[mt][nt][1] + bB : ((c0 == 1) ? 0.f : -FLT_MAX);
            vB = fmaxf(vB, f);
            f = (c1 == 0) ? acc[mt][nt][3] + bB : ((c1 == 1) ? 0.f : -FLT_MAX);
            vB = fmaxf(vB, f);
        }
        #pragma unroll
        for (int off = 4; off < 32; off <<= 1) {
            vA = fmaxf(vA, __shfl_xor_sync(0xFFFFFFFFu, vA, off));
            vB = fmaxf(vB, __shfl_xor_sync(0xFFFFFFFFu, vB, off));
        }
        if (gi == 0) {
            sRed[wid * 64 + col]     = vA;
            sRed[wid * 64 + col + 1] = vB;
        }
    }
    __syncthreads();
    if (tid < 128) {
        int pil = tid >> 6, col = tid & 63;
        const float* r = &sRed[pil * 4 * 64 + col];
        float m = fmaxf(fmaxf(r[0], r[64]), fmaxf(r[128], r[192]));
        g_pmax[((size_t)blockIdx.x * 2 + pil) * F + col] = m;
    }
}

// ---------------- 4) scatter winning pillar features into BEV image --------------
__global__ void scatter_kernel(const int* __restrict__ idxs) {
    int p = blockIdx.x;
    int f = threadIdx.x;
    int b = p / NPILLAR, pl = p % NPILLAR;
    int ix = idxs[2 * p], iy = idxs[2 * p + 1];
    int cell = (b * NX + ix) * NY + iy;
    if (g_winner[cell] == pl)
        g_img[(size_t)cell * F + f] = g_pmax[(size_t)p * F + f];
}

// ---------------- 5a) weight prep: fp32 -> bf16 hi/lo, padded [tap][co][KP] ------
template <int CIN>
__global__ void wprep_kernel(const float* __restrict__ w, __nv_bfloat16* __restrict__ wb) {
    constexpr int KP = 2 * CIN + 8;
    int i = blockIdx.x * 256 + threadIdx.x;
    if (i >= 9 * 128 * CIN) return;
    int ci = i % CIN;
    int co = (i / CIN) % 128;
    int tap = i / (CIN * 128);
    float v = w[((size_t)tap * CIN + ci) * C1 + co];
    __nv_bfloat16 h = __float2bfloat16(v);
    __nv_bfloat16 l = __float2bfloat16(v - __bfloat162float(h));
    size_t base = ((size_t)tap * 128 + co) * KP;
    wb[base + ci] = h;
    wb[base + CIN + ci] = l;
    if (ci < 8) wb[base + 2 * CIN + ci] = __float2bfloat16(0.f);
}

// ---------------- 5b) 3x3 conv via HMMA bf16-split implicit GEMM -----------------
template <int CIN>
__global__ __launch_bounds__(256) void conv3x3_hmma(
    const float* __restrict__ in, const __nv_bfloat16* __restrict__ wb,
    const float* __restrict__ bias, float* __restrict__ out) {

    constexpr int KP = 2 * CIN + 8;
    extern __shared__ char smem[];
    __nv_bfloat16* sA = (__nv_bfloat16*)smem;                      // 180 * KP
    __nv_bfloat16* sB = (__nv_bfloat16*)(smem + 180 * KP * 2);     // 128 * KP
    float* sbias = (float*)(smem + (180 + 128) * KP * 2);

    int tid = threadIdx.x, lane = tid & 31, wid = tid >> 5;
    int bb = blockIdx.z;
    int y0 = blockIdx.y * 8, x0 = blockIdx.x * 16;
    if (tid < 128) sbias[tid] = bias[tid];
    uint32_t sB32 = smem_u32(sB);

    // ---- stage halo: 180 px x CIN fp32 -> bf16 hi|lo ----
    constexpr int CH = CIN / 16;
    for (int t = tid; t < 180 * CH; t += 256) {
        int hp = t / CH, c0 = (t % CH) * 16;
        int hr = hp / 18, hc = hp % 18;
        int gy = y0 - 1 + hr, gx = x0 - 1 + hc;
        __nv_bfloat16* dhi = &sA[hp * KP + c0];
        __nv_bfloat16* dlo = dhi + CIN;
        if (gy >= 0 && gy < NX && gx >= 0 && gx < NY) {
            const float4* s = (const float4*)&in[(((size_t)bb * NX + gy) * NY + gx) * CIN + c0];
            __nv_bfloat16 hi[16], lo[16];
            #pragma unroll
            for (int j = 0; j < 4; j++) {
                float4 v = __ldg(s + j);
                float vv[4] = {v.x, v.y, v.z, v.w};
                #pragma unroll
                for (int q = 0; q < 4; q++) {
                    __nv_bfloat16 h = __float2bfloat16(vv[q]);
                    hi[j * 4 + q] = h;
                    lo[j * 4 + q] = __float2bfloat16(vv[q] - __bfloat162float(h));
                }
            }
            *(uint4*)dhi = *(uint4*)hi;  *(uint4*)(dhi + 8) = *(uint4*)(hi + 8);
            *(uint4*)dlo = *(uint4*)lo;  *(uint4*)(dlo + 8) = *(uint4*)(lo + 8);
        } else {
            uint4 z = make_uint4(0, 0, 0, 0);
            *(uint4*)dhi = z; *(uint4*)(dhi + 8) = z;
            *(uint4*)dlo = z; *(uint4*)(dlo + 8) = z;
        }
    }

    float acc[2][8][4] = {};
    const int mwarp = wid >> 1, nwarp = wid & 1;
    const int gi = lane >> 2;
    const int q2 = (lane & 3) * 2;

    for (int tap = 0; tap < 9; ++tap) {
        __syncthreads();   // prev-tap mma done before sB overwrite (also fences halo)
        {   // async copy of B slab for this tap
            const __nv_bfloat16* src = wb + (size_t)tap * 128 * KP;
            for (int t = tid; t < 128 * KP / 8; t += 256)
                cpasync16(sB32 + t * 16, src + t * 8);
            CP_COMMIT();
            CP_WAIT0();
        }
        __syncthreads();

        const int dy = tap / 3 - 1, dx = tap % 3 - 1;
        uint32_t arow[2][2];
        #pragma unroll
        for (int mt = 0; mt < 2; mt++) {
            int r = mwarp * 2 + mt;
            int hr = r + 1 + dy;
            int hc0 = 1 + dx;
            arow[mt][0] = (hr * 18 + hc0 + gi) * KP;
            arow[mt][1] = (hr * 18 + hc0 + gi + 8) * KP;
        }

        #pragma unroll
        for (int seg = 0; seg < 3; ++seg) {    // (hi,hi), (lo,hi), (hi,lo)
            const int aoff = (seg == 1) ? CIN : 0;
            const int boff = (seg == 2) ? CIN : 0;
            #pragma unroll 4
            for (int k0 = 0; k0 < CIN; k0 += 16) {
                const int ka = aoff + k0 + q2;
                uint32_t a[2][4];
                #pragma unroll
                for (int mt = 0; mt < 2; mt++) {
                    a[mt][0] = *(const uint32_t*)&sA[arow[mt][0] + ka];
                    a[mt][1] = *(const uint32_t*)&sA[arow[mt][1] + ka];
                    a[mt][2] = *(const uint32_t*)&sA[arow[mt][0] + ka + 8];
                    a[mt][3] = *(const uint32_t*)&sA[arow[mt][1] + ka + 8];
                }
                const int kb = boff + k0 + q2;
                #pragma unroll
                for (int nt = 0; nt < 8; nt++) {
                    const int n = nwarp * 64 + nt * 8 + gi;
                    uint32_t b[2];
                    b[0] = *(const uint32_t*)&sB[n * KP + kb];
                    b[1] = *(const uint32_t*)&sB[n * KP + kb + 8];
                    mma16816(acc[0][nt], a[0], b);
                    mma16816(acc[1][nt], a[1], b);
                }
            }
        }
    }

    // ---- epilogue: bias + tanh + store ----
    #pragma unroll
    for (int mt = 0; mt < 2; mt++) {
        int gy = y0 + mwarp * 2 + mt;
        #pragma unroll
        for (int half = 0; half < 2; half++) {
            int gx = x0 + gi + half * 8;
            float* op = &out[(((size_t)bb * NX + gy) * NY + gx) * C1];
            #pragma unroll
            for (int nt = 0; nt < 8; nt++) {
                int n = nwarp * 64 + nt * 8 + q2;
                float2 v;
                v.x = tanhf(acc[mt][nt][half * 2 + 0] + sbias[n]);
                v.y = tanhf(acc[mt][nt][half * 2 + 1] + sbias[n + 1]);
                *(float2*)&op[n] = v;
            }
        }
    }
}

// ---------------- 6) 1x1 conv 128->1 + ReLU ----------------
__global__ void conv1x1_kernel(const float* __restrict__ w2, const float* __restrict__ b2,
                               float* __restrict__ out) {
    __shared__ float sw[C1];
    int tid = threadIdx.x;
    if (tid < C1) sw[tid] = w2[tid];
    __syncthreads();
    int pix = blockIdx.x * 256 + tid;
    const float4* p = reinterpret_cast<const float4*>(&g_x2[(size_t)pix * C1]);
    float s = 0.f;
    #pragma unroll
    for (int i = 0; i < C1 / 4; i++) {
        float4 v = p[i];
        float4 wv = *reinterpret_cast<const float4*>(&sw[4 * i]);
        s += v.x * wv.x + v.y * wv.y + v.z * wv.z + v.w * wv.w;
    }
    s += __ldg(b2);
    out[pix] = fmaxf(s, 0.f);
}

// ---------------- host launcher ----------------
extern "C" void kernel_launch(void* const* d_in, const int* in_sizes, int n_in,
                              void* d_out, int out_size) {
    const float* pillars = (const float*)d_in[0];
    const int*   idxs    = (const int*)d_in[1];
    const float* pn_w0 = (const float*)d_in[4];
    const float* pn_b0 = (const float*)d_in[5];
    const float* pn_w1 = (const float*)d_in[6];
    const float* pn_b1 = (const float*)d_in[7];
    const float* cw0   = (const float*)d_in[8];
    const float* cb0   = (const float*)d_in[9];
    const float* cw1   = (const float*)d_in[10];
    const float* cb1   = (const float*)d_in[11];
    const float* cw2   = (const float*)d_in[12];
    const float* cb2   = (const float*)d_in[13];
    float* out = (float*)d_out;

    float *p_img, *p_x1, *p_x2;
    __nv_bfloat16 *p_wb1, *p_wb2;
    cudaGetSymbolAddress((void**)&p_img, g_img);
    cudaGetSymbolAddress((void**)&p_x1, g_x1);
    cudaGetSymbolAddress((void**)&p_x2, g_x2);
    cudaGetSymbolAddress((void**)&p_wb1, g_wb1);
    cudaGetSymbolAddress((void**)&p_wb2, g_wb2);

    const int KP1 = 2 * 64 + 8, KP2 = 2 * 128 + 8;
    const int smem1 = (180 + 128) * KP1 * 2 + 512;   //  84,288 B
    const int smem2 = (180 + 128) * KP2 * 2 + 512;   // 163,136 B
    const int smemP = (256 + 64) * KH * 2 + (512 + 64 + 64 + 512) * 4 + 256 * 4;
    cudaFuncSetAttribute(conv3x3_hmma<64>,  cudaFuncAttributeMaxDynamicSharedMemorySize, smem1);
    cudaFuncSetAttribute(conv3x3_hmma<128>, cudaFuncAttributeMaxDynamicSharedMemorySize, smem2);
    cudaFuncSetAttribute(pointnet_hmma,     cudaFuncAttributeMaxDynamicSharedMemorySize, smemP);

    zero_kernel<<<2048, 256>>>();
    winner_kernel<<<(BATCH * NPILLAR + 255) / 256, 256>>>(idxs);
    wprep_kernel<64> <<<(9 * 128 * 64 + 255) / 256, 256>>>(cw0, p_wb1);
    wprep_kernel<128><<<(9 * 128 * 128 + 255) / 256, 256>>>(cw1, p_wb2);
    pointnet_hmma<<<BATCH * NPILLAR / 2, 256, smemP>>>(pillars, pn_w0, pn_b0, pn_w1, pn_b1);
    scatter_kernel<<<BATCH * NPILLAR, 64>>>(idxs);

    dim3 cgrid(NX / 16, NY / 8, BATCH);   // (15, 30, 4)
    conv3x3_hmma<64> <<<cgrid, 256, smem1>>>(p_img, p_wb1, cb0, p_x1);
    conv3x3_hmma<128><<<cgrid, 256, smem2>>>(p_x1,  p_wb2, cb1, p_x2);
    conv1x1_kernel<<<BATCH * NX * NY / 256, 256>>>(cw2, cb2, out);
}

// round 6
// speedup vs baseline: 2.1043x; 1.0321x over previous
#include <cuda_runtime.h>
#include <cuda_bf16.h>
#include <cstdint>
#include <math.h>
#include <float.h>

#define BATCH 4
#define NPILLAR 5000
#define NPT 100
#define CPT 8
#define NX 240
#define NY 240
#define F 64      // PN_FEAT
#define C1 128    // conv hidden channels
#define KH 136    // pointnet padded bf16 K stride (hi 0-63 | lo 64-127 | pad)

// ---------------- scratch (device globals; no allocation allowed) ----------------
__device__ float g_pmax[BATCH * NPILLAR * F];
__device__ float g_img [BATCH * NX * NY * F];
__device__ float g_x1  [BATCH * NX * NY * C1];
__device__ int   g_winner[BATCH * NX * NY];
// weights: [tap][part(hi/lo)][co][KB] bf16, KB = CIN+8 (pad zeroed)
__device__ __align__(16) __nv_bfloat16 g_wb1[9 * 2 * 128 * (64 + 8)];    // conv1
__device__ __align__(16) __nv_bfloat16 g_wb2[9 * 2 * 128 * (128 + 8)];   // conv2

// ---------------- HMMA m16n8k16 bf16 (plain sm_80+ PTX) --------------------------
__device__ __forceinline__ void mma16816(float* d, const uint32_t* a, const uint32_t* b) {
    asm volatile(
        "mma.sync.aligned.m16n8k16.row.col.f32.bf16.bf16.f32 "
        "{%0,%1,%2,%3}, {%4,%5,%6,%7}, {%8,%9}, {%0,%1,%2,%3};"
        : "+f"(d[0]), "+f"(d[1]), "+f"(d[2]), "+f"(d[3])
        : "r"(a[0]), "r"(a[1]), "r"(a[2]), "r"(a[3]), "r"(b[0]), "r"(b[1]));
}
__device__ __forceinline__ uint32_t smem_u32(const void* p) {
    uint32_t a;
    asm("{ .reg .u64 t; cvta.to.shared.u64 t, %1; cvt.u32.u64 %0, t; }" : "=r"(a) : "l"(p));
    return a;
}
__device__ __forceinline__ void cpasync16(uint32_t s, const void* g) {
    asm volatile("cp.async.cg.shared.global [%0], [%1], 16;" :: "r"(s), "l"(g));
}
#define CP_COMMIT() asm volatile("cp.async.commit_group;" ::: "memory")
#define CP_WAIT(n)  asm volatile("cp.async.wait_group %0;" :: "n"(n) : "memory")

// ---------------- 1) zero BEV image + init winner map ----------------
__global__ void zero_kernel() {
    int tid = blockIdx.x * blockDim.x + threadIdx.x;
    int stride = gridDim.x * blockDim.x;
    const int n4 = BATCH * NX * NY * F / 4;
    float4 z = make_float4(0.f, 0.f, 0.f, 0.f);
    for (int i = tid; i < n4; i += stride)
        reinterpret_cast<float4*>(g_img)[i] = z;
    for (int i = tid; i < BATCH * NX * NY; i += stride)
        g_winner[i] = -1;
}

// ---------------- 2) duplicate-cell winner (last update wins = max pillar idx) ---
__global__ void winner_kernel(const int* __restrict__ idxs) {
    int p = blockIdx.x * blockDim.x + threadIdx.x;
    if (p >= BATCH * NPILLAR) return;
    int b = p / NPILLAR, pl = p % NPILLAR;
    int ix = idxs[2 * p], iy = idxs[2 * p + 1];
    atomicMax(&g_winner[(b * NX + ix) * NY + iy], pl);
}

// ---------------- 3) pointnet: layer0 scalar+tanh, layer1 HMMA, masked max ------
__global__ __launch_bounds__(256) void pointnet_hmma(
    const float* __restrict__ pillars,
    const float* __restrict__ w0, const float* __restrict__ b0,
    const float* __restrict__ w1, const float* __restrict__ b1) {

    extern __shared__ char sm[];
    __nv_bfloat16* sH  = (__nv_bfloat16*)sm;                       // 256 * KH
    __nv_bfloat16* sW  = (__nv_bfloat16*)(sm + 256 * KH * 2);      // 64 * KH
    float* sW0  = (float*)(sm + (256 + 64) * KH * 2);              // 8*64
    float* sB0  = sW0 + 512;
    float* sB1  = sB0 + 64;
    float* sRed = sB1 + 64;                                        // 8*64
    int*   sCode = (int*)(sRed + 512);                             // 256

    int tid = threadIdx.x, lane = tid & 31, wid = tid >> 5;

    for (int i = tid; i < 512; i += 256) sW0[i] = w0[i];
    if (tid < 64) { sB0[tid] = b0[tid]; sB1[tid] = b1[tid]; }
    for (int i = tid; i < 4096; i += 256) {
        int k = i >> 6, n = i & 63;
        float v = w1[i];
        __nv_bfloat16 h = __float2bfloat16(v);
        sW[n * KH + k]      = h;
        sW[n * KH + 64 + k] = __float2bfloat16(v - __bfloat162float(h));
    }
    __syncthreads();

    {   // ---- layer 0: one thread per row ----
        int row = tid;
        int pt = row & 127;
        uint32_t* dst = (uint32_t*)&sH[row * KH];
        if (pt < NPT) {
            int pil = blockIdx.x * 2 + (row >> 7);
            const float4* px = (const float4*)(pillars + ((size_t)pil * NPT + pt) * CPT);
            float4 A = __ldg(px), B = __ldg(px + 1);
            float x[8] = {A.x, A.y, A.z, A.w, B.x, B.y, B.z, B.w};
            float ss = 0.f;
            #pragma unroll
            for (int k = 0; k < 8; k++) ss += x[k] * x[k];
            sCode[row] = (ss < 1e12f) ? 0 : 1;
            #pragma unroll
            for (int n0 = 0; n0 < 64; n0 += 16) {
                uint32_t hw[8], lw[8];
                #pragma unroll
                for (int q = 0; q < 8; q++) {
                    int n = n0 + 2 * q;
                    float a0 = sB0[n], a1 = sB0[n + 1];
                    #pragma unroll
                    for (int k = 0; k < 8; k++) {
                        a0 += x[k] * sW0[k * 64 + n];
                        a1 += x[k] * sW0[k * 64 + n + 1];
                    }
                    a0 = tanhf(a0); a1 = tanhf(a1);
                    __nv_bfloat162 hp, lp;
                    hp.x = __float2bfloat16(a0);
                    hp.y = __float2bfloat16(a1);
                    lp.x = __float2bfloat16(a0 - __bfloat162float(hp.x));
                    lp.y = __float2bfloat16(a1 - __bfloat162float(hp.y));
                    hw[q] = *(uint32_t*)&hp;
                    lw[q] = *(uint32_t*)&lp;
                }
                *(uint4*)(dst + n0 / 2)          = make_uint4(hw[0], hw[1], hw[2], hw[3]);
                *(uint4*)(dst + n0 / 2 + 4)      = make_uint4(hw[4], hw[5], hw[6], hw[7]);
                *(uint4*)(dst + 32 + n0 / 2)     = make_uint4(lw[0], lw[1], lw[2], lw[3]);
                *(uint4*)(dst + 32 + n0 / 2 + 4) = make_uint4(lw[4], lw[5], lw[6], lw[7]);
            }
        } else {
            sCode[row] = 2;
            uint4 z = make_uint4(0, 0, 0, 0);
            #pragma unroll
            for (int j = 0; j < 16; j++) *(uint4*)(dst + 4 * j) = z;
        }
    }
    __syncthreads();

    // ---- layer 1 via HMMA: warp = 32 rows x 64 cols ----
    const int gi = lane >> 2, q2 = (lane & 3) * 2;
    const int wbase = wid * 32;
    float acc[2][8][4] = {};
    #pragma unroll
    for (int seg = 0; seg < 3; ++seg) {
        const int aoff = (seg == 1) ? 64 : 0;
        const int boff = (seg == 2) ? 64 : 0;
        #pragma unroll
        for (int k0 = 0; k0 < 64; k0 += 16) {
            const int ka = aoff + k0 + q2;
            uint32_t a[2][4];
            #pragma unroll
            for (int mt = 0; mt < 2; mt++) {
                int r0 = (wbase + mt * 16 + gi) * KH;
                int r1 = r0 + 8 * KH;
                a[mt][0] = *(const uint32_t*)&sH[r0 + ka];
                a[mt][1] = *(const uint32_t*)&sH[r1 + ka];
                a[mt][2] = *(const uint32_t*)&sH[r0 + ka + 8];
                a[mt][3] = *(const uint32_t*)&sH[r1 + ka + 8];
            }
            const int kb = boff + k0 + q2;
            #pragma unroll
            for (int nt = 0; nt < 8; nt++) {
                const int n = nt * 8 + gi;
                uint32_t b[2];
                b[0] = *(const uint32_t*)&sW[n * KH + kb];
                b[1] = *(const uint32_t*)&sW[n * KH + kb + 8];
                mma16816(acc[0][nt], a[0], b);
                mma16816(acc[1][nt], a[1], b);
            }
        }
    }

    // ---- masked max reduction ----
    #pragma unroll
    for (int nt = 0; nt < 8; nt++) {
        int col = nt * 8 + q2;
        float bA = sB1[col], bB = sB1[col + 1];
        float vA = -FLT_MAX, vB = -FLT_MAX;
        #pragma unroll
        for (int mt = 0; mt < 2; mt++) {
            int r0 = wbase + mt * 16 + gi, r1 = r0 + 8;
            int c0 = sCode[r0], c1 = sCode[r1];
            float f;
            f = (c0 == 0) ? acc[mt][nt][0] + bA : ((c0 == 1) ? 0.f : -FLT_MAX);
            vA = fmaxf(vA, f);
            f = (c1 == 0) ? acc[mt][nt][2] + bA : ((c1 == 1) ? 0.f : -FLT_MAX);
            vA = fmaxf(vA, f);
            f = (c0 == 0) ? acc[mt][nt][1] + bB : ((c0 == 1) ? 0.f : -FLT_MAX);
            vB = fmaxf(vB, f);
            f = (c1 == 0) ? acc[mt][nt][3] + bB : ((c1 == 1) ? 0.f : -FLT_MAX);
            vB = fmaxf(vB, f);
        }
        #pragma unroll
        for (int off = 4; off < 32; off <<= 1) {
            vA = fmaxf(vA, __shfl_xor_sync(0xFFFFFFFFu, vA, off));
            vB = fmaxf(vB, __shfl_xor_sync(0xFFFFFFFFu, vB, off));
        }
        if (gi == 0) {
            sRed[wid * 64 + col]     = vA;
            sRed[wid * 64 + col + 1] = vB;
        }
    }
    __syncthreads();
    if (tid < 128) {
        int pil = tid >> 6, col = tid & 63;
        const float* r = &sRed[pil * 4 * 64 + col];
        float m = fmaxf(fmaxf(r[0], r[64]), fmaxf(r[128], r[192]));
        g_pmax[((size_t)blockIdx.x * 2 + pil) * F + col] = m;
    }
}

// ---------------- 4) scatter winning pillar features into BEV image --------------
__global__ void scatter_kernel(const int* __restrict__ idxs) {
    int p = blockIdx.x;
    int f = threadIdx.x;
    int b = p / NPILLAR, pl = p % NPILLAR;
    int ix = idxs[2 * p], iy = idxs[2 * p + 1];
    int cell = (b * NX + ix) * NY + iy;
    if (g_winner[cell] == pl)
        g_img[(size_t)cell * F + f] = g_pmax[(size_t)p * F + f];
}

// ---------------- 5a) weight prep: fp32 -> bf16 hi/lo slabs [tap][part][co][KB] --
template <int CIN>
__global__ void wprep_kernel(const float* __restrict__ w, __nv_bfloat16* __restrict__ wb) {
    constexpr int KB = CIN + 8;
    int i = blockIdx.x * 256 + threadIdx.x;
    if (i >= 9 * 128 * CIN) return;
    int ci = i % CIN;
    int co = (i / CIN) % 128;
    int tap = i / (CIN * 128);
    float v = w[((size_t)tap * CIN + ci) * C1 + co];
    __nv_bfloat16 h = __float2bfloat16(v);
    __nv_bfloat16 l = __float2bfloat16(v - __bfloat162float(h));
    size_t bhi = ((size_t)(tap * 2 + 0) * 128 + co) * KB;
    size_t blo = ((size_t)(tap * 2 + 1) * 128 + co) * KB;
    wb[bhi + ci] = h;
    wb[blo + ci] = l;
    if (ci < 8) {
        wb[bhi + CIN + ci] = __float2bfloat16(0.f);
        wb[blo + CIN + ci] = __float2bfloat16(0.f);
    }
}

// ---------------- 5b) 3x3 conv, HMMA bf16-split, pipelined B, optional 1x1 fuse --
// CTA: 8x16 px (M=128) x 128 cout. 8 warps: (mwarp 0..3) x (nwarp 0..1).
// B pipeline: fixed hi/lo buffers; prefetch lo(t) at tap entry, hi(t+1) after seg0/1.
template <int CIN, bool FUSE>
__global__ __launch_bounds__(256) void conv3x3_hmma(
    const float* __restrict__ in, const __nv_bfloat16* __restrict__ wb,
    const float* __restrict__ bias, float* __restrict__ out,
    const float* __restrict__ w2, const float* __restrict__ b2) {

    constexpr int KP = 2 * CIN + 8;     // A stride (hi|lo|pad)
    constexpr int KB = CIN + 8;         // B slab stride
    extern __shared__ char smem[];
    __nv_bfloat16* sA  = (__nv_bfloat16*)smem;                        // 180 * KP
    __nv_bfloat16* sBh = (__nv_bfloat16*)(smem + 180 * KP * 2);       // 128 * KB
    __nv_bfloat16* sBl = sBh + 128 * KB;                              // 128 * KB
    float* sbias = (float*)(smem + (180 * KP + 256 * KB) * 2);        // 128
    float* sw2   = sbias + 128;                                       // 128
    float* sRed  = sw2 + 128;                                         // 128*2

    int tid = threadIdx.x, lane = tid & 31, wid = tid >> 5;
    int bb = blockIdx.z;
    int y0 = blockIdx.y * 8, x0 = blockIdx.x * 16;
    if (tid < 128) {
        sbias[tid] = bias[tid];
        if (FUSE) sw2[tid] = w2[tid];
    }
    uint32_t sBh32 = smem_u32(sBh), sBl32 = smem_u32(sBl);
    constexpr int BCP = 128 * KB / 8;   // 16B chunks per slab

    // prologue: prefetch tap0 hi + lo
    {
        const __nv_bfloat16* src = wb;  // tap0 hi
        for (int t = tid; t < BCP; t += 256) cpasync16(sBh32 + t * 16, src + t * 8);
        CP_COMMIT();
        src = wb + 128 * KB;            // tap0 lo
        for (int t = tid; t < BCP; t += 256) cpasync16(sBl32 + t * 16, src + t * 8);
        CP_COMMIT();
    }

    // ---- stage halo: 180 px x CIN fp32 -> bf16 hi|lo ----
    constexpr int CH = CIN / 16;
    for (int t = tid; t < 180 * CH; t += 256) {
        int hp = t / CH, c0 = (t % CH) * 16;
        int hr = hp / 18, hc = hp % 18;
        int gy = y0 - 1 + hr, gx = x0 - 1 + hc;
        __nv_bfloat16* dhi = &sA[hp * KP + c0];
        __nv_bfloat16* dlo = dhi + CIN;
        if (gy >= 0 && gy < NX && gx >= 0 && gx < NY) {
            const float4* s = (const float4*)&in[(((size_t)bb * NX + gy) * NY + gx) * CIN + c0];
            __nv_bfloat16 hi[16], lo[16];
            #pragma unroll
            for (int j = 0; j < 4; j++) {
                float4 v = __ldg(s + j);
                float vv[4] = {v.x, v.y, v.z, v.w};
                #pragma unroll
                for (int q = 0; q < 4; q++) {
                    __nv_bfloat16 h = __float2bfloat16(vv[q]);
                    hi[j * 4 + q] = h;
                    lo[j * 4 + q] = __float2bfloat16(vv[q] - __bfloat162float(h));
                }
            }
            *(uint4*)dhi = *(uint4*)hi;  *(uint4*)(dhi + 8) = *(uint4*)(hi + 8);
            *(uint4*)dlo = *(uint4*)lo;  *(uint4*)(dlo + 8) = *(uint4*)(lo + 8);
        } else {
            uint4 z = make_uint4(0, 0, 0, 0);
            *(uint4*)dhi = z; *(uint4*)(dhi + 8) = z;
            *(uint4*)dlo = z; *(uint4*)(dlo + 8) = z;
        }
    }

    float acc[2][8][4] = {};
    const int mwarp = wid >> 1, nwarp = wid & 1;
    const int gi = lane >> 2;
    const int q2 = (lane & 3) * 2;

    for (int tap = 0; tap < 9; ++tap) {
        if (tap > 0) {
            __syncthreads();   // seg2(tap-1) readers done -> lo buffer reusable
            const __nv_bfloat16* src = wb + (size_t)(tap * 2 + 1) * 128 * KB;
            for (int t = tid; t < BCP; t += 256) cpasync16(sBl32 + t * 16, src + t * 8);
            CP_COMMIT();
        }
        CP_WAIT(1);            // hi(tap) ready
        __syncthreads();

        const int dy = tap / 3 - 1, dx = tap % 3 - 1;
        uint32_t arow[2][2];
        #pragma unroll
        for (int mt = 0; mt < 2; mt++) {
            int hr = mwarp * 2 + mt + 1 + dy;
            int hc0 = 1 + dx;
            arow[mt][0] = (hr * 18 + hc0 + gi) * KP;
            arow[mt][1] = (hr * 18 + hc0 + gi + 8) * KP;
        }

        // ---- seg0 (Ah x Bh) + seg1 (Al x Bh) ----
        #pragma unroll
        for (int seg = 0; seg < 2; ++seg) {
            const int aoff = (seg == 1) ? CIN : 0;
            #pragma unroll 4
            for (int k0 = 0; k0 < CIN; k0 += 16) {
                const int ka = aoff + k0 + q2;
                uint32_t a[2][4];
                #pragma unroll
                for (int mt = 0; mt < 2; mt++) {
                    a[mt][0] = *(const uint32_t*)&sA[arow[mt][0] + ka];
                    a[mt][1] = *(const uint32_t*)&sA[arow[mt][1] + ka];
                    a[mt][2] = *(const uint32_t*)&sA[arow[mt][0] + ka + 8];
                    a[mt][3] = *(const uint32_t*)&sA[arow[mt][1] + ka + 8];
                }
                const int kb = k0 + q2;
                #pragma unroll
                for (int nt = 0; nt < 8; nt++) {
                    const int n = nwarp * 64 + nt * 8 + gi;
                    uint32_t b[2];
                    b[0] = *(const uint32_t*)&sBh[n * KB + kb];
                    b[1] = *(const uint32_t*)&sBh[n * KB + kb + 8];
                    mma16816(acc[0][nt], a[0], b);
                    mma16816(acc[1][nt], a[1], b);
                }
            }
        }

        __syncthreads();       // hi readers done -> prefetch hi(tap+1)
        if (tap < 8) {
            const __nv_bfloat16* src = wb + (size_t)(tap + 1) * 2 * 128 * KB;
            for (int t = tid; t < BCP; t += 256) cpasync16(sBh32 + t * 16, src + t * 8);
            CP_COMMIT();
            CP_WAIT(1);        // lo(tap) ready
        } else {
            CP_WAIT(0);
        }
        __syncthreads();

        // ---- seg2 (Ah x Bl) ----
        #pragma unroll 4
        for (int k0 = 0; k0 < CIN; k0 += 16) {
            const int ka = k0 + q2;
            uint32_t a[2][4];
            #pragma unroll
            for (int mt = 0; mt < 2; mt++) {
                a[mt][0] = *(const uint32_t*)&sA[arow[mt][0] + ka];
                a[mt][1] = *(const uint32_t*)&sA[arow[mt][1] + ka];
                a[mt][2] = *(const uint32_t*)&sA[arow[mt][0] + ka + 8];
                a[mt][3] = *(const uint32_t*)&sA[arow[mt][1] + ka + 8];
            }
            #pragma unroll
            for (int nt = 0; nt < 8; nt++) {
                const int n = nwarp * 64 + nt * 8 + gi;
                uint32_t b[2];
                b[0] = *(const uint32_t*)&sBl[n * KB + ka];
                b[1] = *(const uint32_t*)&sBl[n * KB + ka + 8];
                mma16816(acc[0][nt], a[0], b);
                mma16816(acc[1][nt], a[1], b);
            }
        }
    }

    if (!FUSE) {
        // ---- epilogue: bias + tanh + store 128ch fp32 ----
        #pragma unroll
        for (int mt = 0; mt < 2; mt++) {
            int gy = y0 + mwarp * 2 + mt;
            #pragma unroll
            for (int half = 0; half < 2; half++) {
                int gx = x0 + gi + half * 8;
                float* op = &out[(((size_t)bb * NX + gy) * NY + gx) * C1];
                #pragma unroll
                for (int nt = 0; nt < 8; nt++) {
                    int n = nwarp * 64 + nt * 8 + q2;
                    float2 v;
                    v.x = tanhf(acc[mt][nt][half * 2 + 0] + sbias[n]);
                    v.y = tanhf(acc[mt][nt][half * 2 + 1] + sbias[n + 1]);
                    *(float2*)&op[n] = v;
                }
            }
        }
    } else {
        // ---- fused epilogue: tanh + 1x1 conv dot + relu -> out [B,NX,NY] ----
        float part[2][2] = {};
        #pragma unroll
        for (int mt = 0; mt < 2; mt++)
        #pragma unroll
        for (int half = 0; half < 2; half++)
        #pragma unroll
        for (int nt = 0; nt < 8; nt++) {
            int n = nwarp * 64 + nt * 8 + q2;
            part[mt][half] += tanhf(acc[mt][nt][half * 2 + 0] + sbias[n])     * sw2[n]
                            + tanhf(acc[mt][nt][half * 2 + 1] + sbias[n + 1]) * sw2[n + 1];
        }
        #pragma unroll
        for (int mt = 0; mt < 2; mt++)
        #pragma unroll
        for (int half = 0; half < 2; half++) {
            float v = part[mt][half];
            v += __shfl_xor_sync(0xFFFFFFFFu, v, 1);
            v += __shfl_xor_sync(0xFFFFFFFFu, v, 2);
            if ((lane & 3) == 0) {
                int px = (mwarp * 2 + mt) * 16 + gi + half * 8;
                sRed[px * 2 + nwarp] = v;
            }
        }
        __syncthreads();
        if (tid < 128) {
            float v = sRed[tid * 2] + sRed[tid * 2 + 1] + __ldg(b2);
            int gy = y0 + (tid >> 4), gx = x0 + (tid & 15);
            out[((size_t)bb * NX + gy) * NY + gx] = fmaxf(v, 0.f);
        }
    }
}

// ---------------- host launcher ----------------
extern "C" void kernel_launch(void* const* d_in, const int* in_sizes, int n_in,
                              void* d_out, int out_size) {
    const float* pillars = (const float*)d_in[0];
    const int*   idxs    = (const int*)d_in[1];
    const float* pn_w0 = (const float*)d_in[4];
    const float* pn_b0 = (const float*)d_in[5];
    const float* pn_w1 = (const float*)d_in[6];
    const float* pn_b1 = (const float*)d_in[7];
    const float* cw0   = (const float*)d_in[8];
    const float* cb0   = (const float*)d_in[9];
    const float* cw1   = (const float*)d_in[10];
    const float* cb1   = (const float*)d_in[11];
    const float* cw2   = (const float*)d_in[12];
    const float* cb2   = (const float*)d_in[13];
    float* out = (float*)d_out;

    float *p_img, *p_x1;
    __nv_bfloat16 *p_wb1, *p_wb2;
    cudaGetSymbolAddress((void**)&p_img, g_img);
    cudaGetSymbolAddress((void**)&p_x1, g_x1);
    cudaGetSymbolAddress((void**)&p_wb1, g_wb1);
    cudaGetSymbolAddress((void**)&p_wb2, g_wb2);

    const int KP1 = 2 * 64 + 8,  KB1 = 64 + 8;
    const int KP2 = 2 * 128 + 8, KB2 = 128 + 8;
    const int smem1 = (180 * KP1 + 256 * KB1) * 2 + (128 + 128 + 256) * 4;  //  88,128 B
    const int smem2 = (180 * KP2 + 256 * KB2) * 2 + (128 + 128 + 256) * 4;  // 166,720 B
    const int smemP = (256 + 64) * KH * 2 + (512 + 64 + 64 + 512) * 4 + 256 * 4;
    cudaFuncSetAttribute(conv3x3_hmma<64, false>, cudaFuncAttributeMaxDynamicSharedMemorySize, smem1);
    cudaFuncSetAttribute(conv3x3_hmma<128, true>, cudaFuncAttributeMaxDynamicSharedMemorySize, smem2);
    cudaFuncSetAttribute(pointnet_hmma,           cudaFuncAttributeMaxDynamicSharedMemorySize, smemP);

    zero_kernel<<<2048, 256>>>();
    winner_kernel<<<(BATCH * NPILLAR + 255) / 256, 256>>>(idxs);
    wprep_kernel<64> <<<(9 * 128 * 64 + 255) / 256, 256>>>(cw0, p_wb1);
    wprep_kernel<128><<<(9 * 128 * 128 + 255) / 256, 256>>>(cw1, p_wb2);
    pointnet_hmma<<<BATCH * NPILLAR / 2, 256, smemP>>>(pillars, pn_w0, pn_b0, pn_w1, pn_b1);
    scatter_kernel<<<BATCH * NPILLAR, 64>>>(idxs);

    dim3 cgrid(NX / 16, NY / 8, BATCH);   // (15, 30, 4)
    conv3x3_hmma<64, false><<<cgrid, 256, smem1>>>(p_img, p_wb1, cb0, p_x1, nullptr, nullptr);
    conv3x3_hmma<128, true><<<cgrid, 256, smem2>>>(p_x1,  p_wb2, cb1, out,  cw2,     cb2);
}

// round 7
// speedup vs baseline: 2.6397x; 1.2544x over previous
#include <cuda_runtime.h>
#include <cuda_bf16.h>
#include <cuda_fp16.h>
#include <cstdint>
#include <math.h>
#include <float.h>

#define BATCH 4
#define NPILLAR 5000
#define NPT 100
#define CPT 8
#define NX 240
#define NY 240
#define F 64      // PN_FEAT
#define C1 128    // conv hidden channels
#define KH 136    // pointnet A stride (hi 0-63 | lo 64-127 | pad)

// ---------------- scratch (device globals; no allocation allowed) ----------------
__device__ float g_pmax[BATCH * NPILLAR * F];
__device__ float g_img [BATCH * NX * NY * F];
__device__ float g_x1  [BATCH * NX * NY * C1];
__device__ int   g_winner[BATCH * NX * NY];
// fp16 weights, K-blocked layout [tap][k/8][co][8]
__device__ __align__(16) __half g_wb1[9 * 64 * 128];    // conv1 (CIN=64)
__device__ __align__(16) __half g_wb2[9 * 128 * 128];   // conv2 (CIN=128)

// ---------------- HMMA m16n8k16 (plain sm_80+ PTX) -------------------------------
__device__ __forceinline__ void mma_f16(float* d, const uint32_t* a, const uint32_t* b) {
    asm volatile(
        "mma.sync.aligned.m16n8k16.row.col.f32.f16.f16.f32 "
        "{%0,%1,%2,%3}, {%4,%5,%6,%7}, {%8,%9}, {%0,%1,%2,%3};"
        : "+f"(d[0]), "+f"(d[1]), "+f"(d[2]), "+f"(d[3])
        : "r"(a[0]), "r"(a[1]), "r"(a[2]), "r"(a[3]), "r"(b[0]), "r"(b[1]));
}
__device__ __forceinline__ void mma_bf16(float* d, const uint32_t* a, const uint32_t* b) {
    asm volatile(
        "mma.sync.aligned.m16n8k16.row.col.f32.bf16.bf16.f32 "
        "{%0,%1,%2,%3}, {%4,%5,%6,%7}, {%8,%9}, {%0,%1,%2,%3};"
        : "+f"(d[0]), "+f"(d[1]), "+f"(d[2]), "+f"(d[3])
        : "r"(a[0]), "r"(a[1]), "r"(a[2]), "r"(a[3]), "r"(b[0]), "r"(b[1]));
}
__device__ __forceinline__ uint32_t smem_u32(const void* p) {
    uint32_t a;
    asm("{ .reg .u64 t; cvta.to.shared.u64 t, %1; cvt.u32.u64 %0, t; }" : "=r"(a) : "l"(p));
    return a;
}
__device__ __forceinline__ void cpasync16(uint32_t s, const void* g) {
    asm volatile("cp.async.cg.shared.global [%0], [%1], 16;" :: "r"(s), "l"(g));
}
#define CP_COMMIT() asm volatile("cp.async.commit_group;" ::: "memory")
#define CP_WAIT(n)  asm volatile("cp.async.wait_group %0;" :: "n"(n) : "memory")

// ---------------- 1) zero BEV image + init winner map ----------------
__global__ void zero_kernel() {
    int tid = blockIdx.x * blockDim.x + threadIdx.x;
    int stride = gridDim.x * blockDim.x;
    const int n4 = BATCH * NX * NY * F / 4;
    float4 z = make_float4(0.f, 0.f, 0.f, 0.f);
    for (int i = tid; i < n4; i += stride)
        reinterpret_cast<float4*>(g_img)[i] = z;
    for (int i = tid; i < BATCH * NX * NY; i += stride)
        g_winner[i] = -1;
}

// ---------------- 2) duplicate-cell winner (last update wins = max pillar idx) ---
__global__ void winner_kernel(const int* __restrict__ idxs) {
    int p = blockIdx.x * blockDim.x + threadIdx.x;
    if (p >= BATCH * NPILLAR) return;
    int b = p / NPILLAR, pl = p % NPILLAR;
    int ix = idxs[2 * p], iy = idxs[2 * p + 1];
    atomicMax(&g_winner[(b * NX + ix) * NY + iy], pl);
}

// ---------------- 3) pointnet: layer0 scalar+tanh, layer1 HMMA(bf16 3-term) -----
// sW now K-blocked [kb/8][n][8] -> conflict-free fragment loads.
__global__ __launch_bounds__(256) void pointnet_hmma(
    const float* __restrict__ pillars,
    const float* __restrict__ w0, const float* __restrict__ b0,
    const float* __restrict__ w1, const float* __restrict__ b1) {

    extern __shared__ char sm[];
    __nv_bfloat16* sH  = (__nv_bfloat16*)sm;                       // 256 * KH
    __nv_bfloat16* sW  = (__nv_bfloat16*)(sm + 256 * KH * 2);      // 8192 (K-blocked)
    float* sW0  = (float*)(sm + 256 * KH * 2 + 8192 * 2);          // 8*64
    float* sB0  = sW0 + 512;
    float* sB1  = sB0 + 64;
    float* sRed = sB1 + 64;                                        // 8*64
    int*   sCode = (int*)(sRed + 512);                             // 256

    int tid = threadIdx.x, lane = tid & 31, wid = tid >> 5;

    for (int i = tid; i < 512; i += 256) sW0[i] = w0[i];
    if (tid < 64) { sB0[tid] = b0[tid]; sB1[tid] = b1[tid]; }
    for (int i = tid; i < 4096; i += 256) {
        int k = i >> 6, n = i & 63;
        float v = w1[i];
        __nv_bfloat16 h = __float2bfloat16(v);
        int p = (k >> 3) * 512 + n * 8 + (k & 7);
        sW[p]        = h;                                         // hi: kb = k
        sW[p + 4096] = __float2bfloat16(v - __bfloat162float(h)); // lo: kb = 64+k
    }
    __syncthreads();

    {   // ---- layer 0: one thread per row ----
        int row = tid;
        int pt = row & 127;
        uint32_t* dst = (uint32_t*)&sH[row * KH];
        if (pt < NPT) {
            int pil = blockIdx.x * 2 + (row >> 7);
            const float4* px = (const float4*)(pillars + ((size_t)pil * NPT + pt) * CPT);
            float4 A = __ldg(px), B = __ldg(px + 1);
            float x[8] = {A.x, A.y, A.z, A.w, B.x, B.y, B.z, B.w};
            float ss = 0.f;
            #pragma unroll
            for (int k = 0; k < 8; k++) ss += x[k] * x[k];
            sCode[row] = (ss < 1e12f) ? 0 : 1;
            #pragma unroll
            for (int n0 = 0; n0 < 64; n0 += 16) {
                uint32_t hw[8], lw[8];
                #pragma unroll
                for (int q = 0; q < 8; q++) {
                    int n = n0 + 2 * q;
                    float a0 = sB0[n], a1 = sB0[n + 1];
                    #pragma unroll
                    for (int k = 0; k < 8; k++) {
                        a0 += x[k] * sW0[k * 64 + n];
                        a1 += x[k] * sW0[k * 64 + n + 1];
                    }
                    a0 = tanhf(a0); a1 = tanhf(a1);
                    __nv_bfloat162 hp, lp;
                    hp.x = __float2bfloat16(a0);
                    hp.y = __float2bfloat16(a1);
                    lp.x = __float2bfloat16(a0 - __bfloat162float(hp.x));
                    lp.y = __float2bfloat16(a1 - __bfloat162float(hp.y));
                    hw[q] = *(uint32_t*)&hp;
                    lw[q] = *(uint32_t*)&lp;
                }
                *(uint4*)(dst + n0 / 2)          = make_uint4(hw[0], hw[1], hw[2], hw[3]);
                *(uint4*)(dst + n0 / 2 + 4)      = make_uint4(hw[4], hw[5], hw[6], hw[7]);
                *(uint4*)(dst + 32 + n0 / 2)     = make_uint4(lw[0], lw[1], lw[2], lw[3]);
                *(uint4*)(dst + 32 + n0 / 2 + 4) = make_uint4(lw[4], lw[5], lw[6], lw[7]);
            }
        } else {
            sCode[row] = 2;
            uint4 z = make_uint4(0, 0, 0, 0);
            #pragma unroll
            for (int j = 0; j < 16; j++) *(uint4*)(dst + 4 * j) = z;
        }
    }
    __syncthreads();

    // ---- layer 1 via HMMA (bf16 3-term): warp = 32 rows x 64 cols ----
    const int gi = lane >> 2, q2 = (lane & 3) * 2;
    const int wbase = wid * 32;
    float acc[2][8][4] = {};
    #pragma unroll
    for (int seg = 0; seg < 3; ++seg) {
        const int aoff = (seg == 1) ? 64 : 0;
        const int boff = (seg == 2) ? 64 : 0;
        #pragma unroll
        for (int k0 = 0; k0 < 64; k0 += 16) {
            const int ka = aoff + k0 + q2;
            uint32_t a[2][4];
            #pragma unroll
            for (int mt = 0; mt < 2; mt++) {
                int r0 = (wbase + mt * 16 + gi) * KH;
                int r1 = r0 + 8 * KH;
                a[mt][0] = *(const uint32_t*)&sH[r0 + ka];
                a[mt][1] = *(const uint32_t*)&sH[r1 + ka];
                a[mt][2] = *(const uint32_t*)&sH[r0 + ka + 8];
                a[mt][3] = *(const uint32_t*)&sH[r1 + ka + 8];
            }
            const __nv_bfloat16* wp = &sW[((boff + k0) >> 3) * 512 + q2];
            #pragma unroll
            for (int nt = 0; nt < 8; nt++) {
                const int n = nt * 8 + gi;
                uint32_t b[2];
                b[0] = *(const uint32_t*)&wp[n * 8];
                b[1] = *(const uint32_t*)&wp[n * 8 + 512];
                mma_bf16(acc[0][nt], a[0], b);
                mma_bf16(acc[1][nt], a[1], b);
            }
        }
    }

    // ---- masked max reduction ----
    #pragma unroll
    for (int nt = 0; nt < 8; nt++) {
        int col = nt * 8 + q2;
        float bA = sB1[col], bB = sB1[col + 1];
        float vA = -FLT_MAX, vB = -FLT_MAX;
        #pragma unroll
        for (int mt = 0; mt < 2; mt++) {
            int r0 = wbase + mt * 16 + gi, r1 = r0 + 8;
            int c0 = sCode[r0], c1 = sCode[r1];
            float f;
            f = (c0 == 0) ? acc[mt][nt][0] + bA : ((c0 == 1) ? 0.f : -FLT_MAX);
            vA = fmaxf(vA, f);
            f = (c1 == 0) ? acc[mt][nt][2] + bA : ((c1 == 1) ? 0.f : -FLT_MAX);
            vA = fmaxf(vA, f);
            f = (c0 == 0) ? acc[mt][nt][1] + bB : ((c0 == 1) ? 0.f : -FLT_MAX);
            vB = fmaxf(vB, f);
            f = (c1 == 0) ? acc[mt][nt][3] + bB : ((c1 == 1) ? 0.f : -FLT_MAX);
            vB = fmaxf(vB, f);
        }
        #pragma unroll
        for (int off = 4; off < 32; off <<= 1) {
            vA = fmaxf(vA, __shfl_xor_sync(0xFFFFFFFFu, vA, off));
            vB = fmaxf(vB, __shfl_xor_sync(0xFFFFFFFFu, vB, off));
        }
        if (gi == 0) {
            sRed[wid * 64 + col]     = vA;
            sRed[wid * 64 + col + 1] = vB;
        }
    }
    __syncthreads();
    if (tid < 128) {
        int pil = tid >> 6, col = tid & 63;
        const float* r = &sRed[pil * 4 * 64 + col];
        float m = fmaxf(fmaxf(r[0], r[64]), fmaxf(r[128], r[192]));
        g_pmax[((size_t)blockIdx.x * 2 + pil) * F + col] = m;
    }
}

// ---------------- 4) scatter winning pillar features into BEV image --------------
__global__ void scatter_kernel(const int* __restrict__ idxs) {
    int p = blockIdx.x;
    int f = threadIdx.x;
    int b = p / NPILLAR, pl = p % NPILLAR;
    int ix = idxs[2 * p], iy = idxs[2 * p + 1];
    int cell = (b * NX + ix) * NY + iy;
    if (g_winner[cell] == pl)
        g_img[(size_t)cell * F + f] = g_pmax[(size_t)p * F + f];
}

// ---------------- 5a) weight prep: fp32 -> fp16, K-blocked [tap][ci/8][co][8] ----
template <int CIN>
__global__ void wprep_kernel(const float* __restrict__ w, __half* __restrict__ wb) {
    int i = blockIdx.x * 256 + threadIdx.x;
    if (i >= 9 * 128 * CIN) return;
    int ci = i % CIN;
    int co = (i / CIN) % 128;
    int tap = i / (CIN * 128);
    float v = w[((size_t)tap * CIN + ci) * C1 + co];
    wb[((size_t)tap * (CIN / 8) + (ci >> 3)) * 1024 + co * 8 + (ci & 7)] = __float2half_rn(v);
}

// ---------------- 5b) 3x3 conv, HMMA fp16 2-term, conflict-free B, pipelined -----
// CTA: 8x16 px (M=128) x 128 cout. 8 warps: (mwarp 0..3) x (nwarp 0..1).
// B: single fp16 slab per tap, K-blocked, double-buffered prefetch.
template <int CIN, bool FUSE, int MINB>
__global__ __launch_bounds__(256, MINB) void conv3x3_hmma(
    const float* __restrict__ in, const __half* __restrict__ wb,
    const float* __restrict__ bias, float* __restrict__ out,
    const float* __restrict__ w2, const float* __restrict__ b2) {

    constexpr int KP = 2 * CIN + 8;     // A stride in halves (hi|lo|pad)
    constexpr int SLAB = CIN * 128;     // B slab halves (K-blocked)
    extern __shared__ char smem[];
    __half* sA = (__half*)smem;                                   // 180 * KP
    __half* sB = (__half*)(smem + 180 * KP * 2);                  // 2 * SLAB
    float* sbias = (float*)(smem + (180 * KP + 2 * SLAB) * 2);    // 128
    float* sw2   = sbias + 128;                                   // 128
    float* sRed  = sw2 + 128;                                     // 256

    int tid = threadIdx.x, lane = tid & 31, wid = tid >> 5;
    int bb = blockIdx.z;
    int y0 = blockIdx.y * 8, x0 = blockIdx.x * 16;
    if (tid < 128) {
        sbias[tid] = bias[tid];
        if (FUSE) sw2[tid] = w2[tid];
    }
    uint32_t sB32 = smem_u32(sB);
    constexpr int BCP = SLAB / 8;       // 16B chunks per slab

    // prologue: prefetch tap0 into buffer 0
    for (int t = tid; t < BCP; t += 256) cpasync16(sB32 + t * 16, wb + t * 8);
    CP_COMMIT();

    // ---- stage halo: 180 px x CIN fp32 -> fp16 hi|lo ----
    constexpr int CH = CIN / 16;
    for (int t = tid; t < 180 * CH; t += 256) {
        int hp = t / CH, c0 = (t % CH) * 16;
        int hr = hp / 18, hc = hp % 18;
        int gy = y0 - 1 + hr, gx = x0 - 1 + hc;
        __half* dhi = &sA[hp * KP + c0];
        __half* dlo = dhi + CIN;
        if (gy >= 0 && gy < NX && gx >= 0 && gx < NY) {
            const float4* s = (const float4*)&in[(((size_t)bb * NX + gy) * NY + gx) * CIN + c0];
            __half hi[16], lo[16];
            #pragma unroll
            for (int j = 0; j < 4; j++) {
                float4 v = __ldg(s + j);
                float vv[4] = {v.x, v.y, v.z, v.w};
                #pragma unroll
                for (int q = 0; q < 4; q++) {
                    __half h = __float2half_rn(vv[q]);
                    hi[j * 4 + q] = h;
                    lo[j * 4 + q] = __float2half_rn(vv[q] - __half2float(h));
                }
            }
            *(uint4*)dhi = *(uint4*)hi;  *(uint4*)(dhi + 8) = *(uint4*)(hi + 8);
            *(uint4*)dlo = *(uint4*)lo;  *(uint4*)(dlo + 8) = *(uint4*)(lo + 8);
        } else {
            uint4 z = make_uint4(0, 0, 0, 0);
            *(uint4*)dhi = z; *(uint4*)(dhi + 8) = z;
            *(uint4*)dlo = z; *(uint4*)(dlo + 8) = z;
        }
    }

    float acc[2][8][4] = {};
    const int mwarp = wid >> 1, nwarp = wid & 1;
    const int gi = lane >> 2;
    const int q2 = (lane & 3) * 2;

    for (int tap = 0; tap < 9; ++tap) {
        CP_WAIT(0);            // tap's slab landed
        __syncthreads();       // + all readers of tap-1 done
        if (tap < 8) {         // prefetch next tap into the other buffer
            const __half* src = wb + (size_t)(tap + 1) * SLAB;
            uint32_t dst = sB32 + ((tap + 1) & 1) * SLAB * 2;
            for (int t = tid; t < BCP; t += 256) cpasync16(dst + t * 16, src + t * 8);
            CP_COMMIT();
        }
        const __half* sBc = sB + (tap & 1) * SLAB;

        const int dy = tap / 3 - 1, dx = tap % 3 - 1;
        uint32_t arow[2][2];
        #pragma unroll
        for (int mt = 0; mt < 2; mt++) {
            int hr = mwarp * 2 + mt + 1 + dy;
            int hc0 = 1 + dx;
            arow[mt][0] = (hr * 18 + hc0 + gi) * KP;
            arow[mt][1] = (hr * 18 + hc0 + gi + 8) * KP;
        }

        // ---- seg0 (Ah x B) + seg1 (Al x B) ----
        #pragma unroll
        for (int seg = 0; seg < 2; ++seg) {
            const int aoff = (seg == 1) ? CIN : 0;
            #pragma unroll 4
            for (int k0 = 0; k0 < CIN; k0 += 16) {
                const int ka = aoff + k0 + q2;
                uint32_t a[2][4];
                #pragma unroll
                for (int mt = 0; mt < 2; mt++) {
                    a[mt][0] = *(const uint32_t*)&sA[arow[mt][0] + ka];
                    a[mt][1] = *(const uint32_t*)&sA[arow[mt][1] + ka];
                    a[mt][2] = *(const uint32_t*)&sA[arow[mt][0] + ka + 8];
                    a[mt][3] = *(const uint32_t*)&sA[arow[mt][1] + ka + 8];
                }
                const __half* bp = sBc + (k0 >> 3) * 1024 + q2;
                #pragma unroll
                for (int nt = 0; nt < 8; nt++) {
                    const int n = nwarp * 64 + nt * 8 + gi;
                    uint32_t b[2];
                    b[0] = *(const uint32_t*)&bp[n * 8];
                    b[1] = *(const uint32_t*)&bp[n * 8 + 1024];
                    mma_f16(acc[0][nt], a[0], b);
                    mma_f16(acc[1][nt], a[1], b);
                }
            }
        }
    }

    if (!FUSE) {
        // ---- epilogue: bias + tanh + store 128ch fp32 ----
        #pragma unroll
        for (int mt = 0; mt < 2; mt++) {
            int gy = y0 + mwarp * 2 + mt;
            #pragma unroll
            for (int half = 0; half < 2; half++) {
                int gx = x0 + gi + half * 8;
                float* op = &out[(((size_t)bb * NX + gy) * NY + gx) * C1];
                #pragma unroll
                for (int nt = 0; nt < 8; nt++) {
                    int n = nwarp * 64 + nt * 8 + q2;
                    float2 v;
                    v.x = tanhf(acc[mt][nt][half * 2 + 0] + sbias[n]);
                    v.y = tanhf(acc[mt][nt][half * 2 + 1] + sbias[n + 1]);
                    *(float2*)&op[n] = v;
                }
            }
        }
    } else {
        // ---- fused epilogue: tanh + 1x1 conv dot + relu -> out [B,NX,NY] ----
        float part[2][2] = {};
        #pragma unroll
        for (int mt = 0; mt < 2; mt++)
        #pragma unroll
        for (int half = 0; half < 2; half++)
        #pragma unroll
        for (int nt = 0; nt < 8; nt++) {
            int n = nwarp * 64 + nt * 8 + q2;
            part[mt][half] += tanhf(acc[mt][nt][half * 2 + 0] + sbias[n])     * sw2[n]
                            + tanhf(acc[mt][nt][half * 2 + 1] + sbias[n + 1]) * sw2[n + 1];
        }
        #pragma unroll
        for (int mt = 0; mt < 2; mt++)
        #pragma unroll
        for (int half = 0; half < 2; half++) {
            float v = part[mt][half];
            v += __shfl_xor_sync(0xFFFFFFFFu, v, 1);
            v += __shfl_xor_sync(0xFFFFFFFFu, v, 2);
            if ((lane & 3) == 0) {
                int px = (mwarp * 2 + mt) * 16 + gi + half * 8;
                sRed[px * 2 + nwarp] = v;
            }
        }
        __syncthreads();
        if (tid < 128) {
            float v = sRed[tid * 2] + sRed[tid * 2 + 1] + __ldg(b2);
            int gy = y0 + (tid >> 4), gx = x0 + (tid & 15);
            out[((size_t)bb * NX + gy) * NY + gx] = fmaxf(v, 0.f);
        }
    }
}

// ---------------- host launcher ----------------
extern "C" void kernel_launch(void* const* d_in, const int* in_sizes, int n_in,
                              void* d_out, int out_size) {
    const float* pillars = (const float*)d_in[0];
    const int*   idxs    = (const int*)d_in[1];
    const float* pn_w0 = (const float*)d_in[4];
    const float* pn_b0 = (const float*)d_in[5];
    const float* pn_w1 = (const float*)d_in[6];
    const float* pn_b1 = (const float*)d_in[7];
    const float* cw0   = (const float*)d_in[8];
    const float* cb0   = (const float*)d_in[9];
    const float* cw1   = (const float*)d_in[10];
    const float* cb1   = (const float*)d_in[11];
    const float* cw2   = (const float*)d_in[12];
    const float* cb2   = (const float*)d_in[13];
    float* out = (float*)d_out;

    float *p_img, *p_x1;
    __half *p_wb1, *p_wb2;
    cudaGetSymbolAddress((void**)&p_img, g_img);
    cudaGetSymbolAddress((void**)&p_x1, g_x1);
    cudaGetSymbolAddress((void**)&p_wb1, g_wb1);
    cudaGetSymbolAddress((void**)&p_wb2, g_wb2);

    const int smem1 = (180 * (2 * 64 + 8) + 2 * 64 * 128) * 2 + 512 * 4;    //  83,776 B
    const int smem2 = (180 * (2 * 128 + 8) + 2 * 128 * 128) * 2 + 512 * 4;  // 162,624 B
    const int smemP = 256 * KH * 2 + 8192 * 2 + (512 + 64 + 64 + 512) * 4 + 256 * 4;
    cudaFuncSetAttribute((const void*)conv3x3_hmma<64, false, 2>,
                         cudaFuncAttributeMaxDynamicSharedMemorySize, smem1);
    cudaFuncSetAttribute((const void*)conv3x3_hmma<128, true, 1>,
                         cudaFuncAttributeMaxDynamicSharedMemorySize, smem2);
    cudaFuncSetAttribute((const void*)pointnet_hmma,
                         cudaFuncAttributeMaxDynamicSharedMemorySize, smemP);

    zero_kernel<<<2048, 256>>>();
    winner_kernel<<<(BATCH * NPILLAR + 255) / 256, 256>>>(idxs);
    wprep_kernel<64> <<<(9 * 128 * 64 + 255) / 256, 256>>>(cw0, p_wb1);
    wprep_kernel<128><<<(9 * 128 * 128 + 255) / 256, 256>>>(cw1, p_wb2);
    pointnet_hmma<<<BATCH * NPILLAR / 2, 256, smemP>>>(pillars, pn_w0, pn_b0, pn_w1, pn_b1);
    scatter_kernel<<<BATCH * NPILLAR, 64>>>(idxs);

    dim3 cgrid(NX / 16, NY / 8, BATCH);   // (15, 30, 4)
    conv3x3_hmma<64, false, 2><<<cgrid, 256, smem1>>>(p_img, p_wb1, cb0, p_x1, nullptr, nullptr);
    conv3x3_hmma<128, true, 1><<<cgrid, 256, smem2>>>(p_x1,  p_wb2, cb1, out,  cw2,     cb2);
}

// round 8
// speedup vs baseline: 2.8511x; 1.0801x over previous
#include <cuda_runtime.h>
#include <cuda_fp16.h>
#include <cstdint>
#include <math.h>
#include <float.h>

#define BATCH 4
#define NPILLAR 5000
#define NPT 100
#define CPT 8
#define NX 240
#define NY 240
#define F 64      // PN_FEAT
#define C1 128    // conv hidden channels
#define KH 136    // pointnet A stride in halves (hi 0-63 | lo 64-127 | pad)

// ---------------- scratch (device globals; no allocation allowed) ----------------
__device__ float g_pmax[BATCH * NPILLAR * F];
__device__ float g_img [BATCH * NX * NY * F];
__device__ float g_x1  [BATCH * NX * NY * C1];
__device__ int   g_winner[BATCH * NX * NY];
// fp16 weights, K-blocked layout [tap][k/8][co][8]
__device__ __align__(16) __half g_wb1[9 * 64 * 128];    // conv1 (CIN=64)
__device__ __align__(16) __half g_wb2[9 * 128 * 128];   // conv2 (CIN=128)

// ---------------- HMMA m16n8k16 fp16 + ldmatrix (plain sm_75/80 PTX) -------------
__device__ __forceinline__ void mma_f16(float* d, const uint32_t* a, const uint32_t* b) {
    asm volatile(
        "mma.sync.aligned.m16n8k16.row.col.f32.f16.f16.f32 "
        "{%0,%1,%2,%3}, {%4,%5,%6,%7}, {%8,%9}, {%0,%1,%2,%3};"
        : "+f"(d[0]), "+f"(d[1]), "+f"(d[2]), "+f"(d[3])
        : "r"(a[0]), "r"(a[1]), "r"(a[2]), "r"(a[3]), "r"(b[0]), "r"(b[1]));
}
__device__ __forceinline__ void ldsm_x4(uint32_t* r, uint32_t addr) {
    asm volatile("ldmatrix.sync.aligned.m8n8.x4.shared.b16 {%0,%1,%2,%3}, [%4];"
        : "=r"(r[0]), "=r"(r[1]), "=r"(r[2]), "=r"(r[3]) : "r"(addr));
}
__device__ __forceinline__ uint32_t smem_u32(const void* p) {
    uint32_t a;
    asm("{ .reg .u64 t; cvta.to.shared.u64 t, %1; cvt.u32.u64 %0, t; }" : "=r"(a) : "l"(p));
    return a;
}
__device__ __forceinline__ void cpasync16(uint32_t s, const void* g) {
    asm volatile("cp.async.cg.shared.global [%0], [%1], 16;" :: "r"(s), "l"(g));
}
#define CP_COMMIT() asm volatile("cp.async.commit_group;" ::: "memory")
#define CP_WAIT(n)  asm volatile("cp.async.wait_group %0;" :: "n"(n) : "memory")

// ---------------- 1) zero BEV image + init winner map ----------------
__global__ void zero_kernel() {
    int tid = blockIdx.x * blockDim.x + threadIdx.x;
    int stride = gridDim.x * blockDim.x;
    const int n4 = BATCH * NX * NY * F / 4;
    float4 z = make_float4(0.f, 0.f, 0.f, 0.f);
    for (int i = tid; i < n4; i += stride)
        reinterpret_cast<float4*>(g_img)[i] = z;
    for (int i = tid; i < BATCH * NX * NY; i += stride)
        g_winner[i] = -1;
}

// ---------------- 2) duplicate-cell winner (last update wins = max pillar idx) ---
__global__ void winner_kernel(const int* __restrict__ idxs) {
    int p = blockIdx.x * blockDim.x + threadIdx.x;
    if (p >= BATCH * NPILLAR) return;
    int b = p / NPILLAR, pl = p % NPILLAR;
    int ix = idxs[2 * p], iy = idxs[2 * p + 1];
    atomicMax(&g_winner[(b * NX + ix) * NY + iy], pl);
}

// ---------------- 3) pointnet: layer0 scalar+tanh, layer1 HMMA fp16 2-term ------
__global__ __launch_bounds__(256) void pointnet_hmma(
    const float* __restrict__ pillars,
    const float* __restrict__ w0, const float* __restrict__ b0,
    const float* __restrict__ w1, const float* __restrict__ b1) {

    extern __shared__ char sm[];
    __half* sH = (__half*)sm;                               // 256 * KH
    __half* sW = (__half*)(sm + 256 * KH * 2);              // 4096 (K-blocked [k/8][n][8])
    float* sW0  = (float*)(sm + 256 * KH * 2 + 8192);       // 8*64
    float* sB0  = sW0 + 512;
    float* sB1  = sB0 + 64;
    float* sRed = sB1 + 64;                                 // 8*64
    int*   sCode = (int*)(sRed + 512);                      // 256

    int tid = threadIdx.x, lane = tid & 31, wid = tid >> 5;

    for (int i = tid; i < 512; i += 256) sW0[i] = w0[i];
    if (tid < 64) { sB0[tid] = b0[tid]; sB1[tid] = b1[tid]; }
    for (int i = tid; i < 4096; i += 256) {
        int k = i >> 6, n = i & 63;
        sW[(k >> 3) * 512 + n * 8 + (k & 7)] = __float2half_rn(w1[i]);
    }
    __syncthreads();

    {   // ---- layer 0: one thread per row ----
        int row = tid;
        int pt = row & 127;
        uint32_t* dst = (uint32_t*)&sH[row * KH];
        if (pt < NPT) {
            int pil = blockIdx.x * 2 + (row >> 7);
            const float4* px = (const float4*)(pillars + ((size_t)pil * NPT + pt) * CPT);
            float4 A = __ldg(px), B = __ldg(px + 1);
            float x[8] = {A.x, A.y, A.z, A.w, B.x, B.y, B.z, B.w};
            float ss = 0.f;
            #pragma unroll
            for (int k = 0; k < 8; k++) ss += x[k] * x[k];
            sCode[row] = (ss < 1e12f) ? 0 : 1;
            #pragma unroll
            for (int n0 = 0; n0 < 64; n0 += 16) {
                uint32_t hw[8], lw[8];
                #pragma unroll
                for (int q = 0; q < 8; q++) {
                    int n = n0 + 2 * q;
                    float a0 = sB0[n], a1 = sB0[n + 1];
                    #pragma unroll
                    for (int k = 0; k < 8; k++) {
                        a0 += x[k] * sW0[k * 64 + n];
                        a1 += x[k] * sW0[k * 64 + n + 1];
                    }
                    a0 = tanhf(a0); a1 = tanhf(a1);
                    __half2 hp, lp;
                    hp.x = __float2half_rn(a0);
                    hp.y = __float2half_rn(a1);
                    lp.x = __float2half_rn(a0 - __half2float(hp.x));
                    lp.y = __float2half_rn(a1 - __half2float(hp.y));
                    hw[q] = *(uint32_t*)&hp;
                    lw[q] = *(uint32_t*)&lp;
                }
                *(uint4*)(dst + n0 / 2)          = make_uint4(hw[0], hw[1], hw[2], hw[3]);
                *(uint4*)(dst + n0 / 2 + 4)      = make_uint4(hw[4], hw[5], hw[6], hw[7]);
                *(uint4*)(dst + 32 + n0 / 2)     = make_uint4(lw[0], lw[1], lw[2], lw[3]);
                *(uint4*)(dst + 32 + n0 / 2 + 4) = make_uint4(lw[4], lw[5], lw[6], lw[7]);
            }
        } else {
            sCode[row] = 2;
            uint4 z = make_uint4(0, 0, 0, 0);
            #pragma unroll
            for (int j = 0; j < 16; j++) *(uint4*)(dst + 4 * j) = z;
        }
    }
    __syncthreads();

    // ---- layer 1 via HMMA fp16 (2 segments): warp = 32 rows x 64 cols ----
    const int gi = lane >> 2, q2 = (lane & 3) * 2;
    const int wbase = wid * 32;
    float acc[2][8][4] = {};
    #pragma unroll
    for (int seg = 0; seg < 2; ++seg) {
        const int aoff = (seg == 1) ? 64 : 0;
        #pragma unroll
        for (int k0 = 0; k0 < 64; k0 += 16) {
            const int ka = aoff + k0 + q2;
            uint32_t a[2][4];
            #pragma unroll
            for (int mt = 0; mt < 2; mt++) {
                int r0 = (wbase + mt * 16 + gi) * KH;
                int r1 = r0 + 8 * KH;
                a[mt][0] = *(const uint32_t*)&sH[r0 + ka];
                a[mt][1] = *(const uint32_t*)&sH[r1 + ka];
                a[mt][2] = *(const uint32_t*)&sH[r0 + ka + 8];
                a[mt][3] = *(const uint32_t*)&sH[r1 + ka + 8];
            }
            const __half* wp = &sW[(k0 >> 3) * 512 + q2];
            #pragma unroll
            for (int nt = 0; nt < 8; nt++) {
                const int n = nt * 8 + gi;
                uint32_t b[2];
                b[0] = *(const uint32_t*)&wp[n * 8];
                b[1] = *(const uint32_t*)&wp[n * 8 + 512];
                mma_f16(acc[0][nt], a[0], b);
                mma_f16(acc[1][nt], a[1], b);
            }
        }
    }

    // ---- masked max reduction ----
    #pragma unroll
    for (int nt = 0; nt < 8; nt++) {
        int col = nt * 8 + q2;
        float bA = sB1[col], bB = sB1[col + 1];
        float vA = -FLT_MAX, vB = -FLT_MAX;
        #pragma unroll
        for (int mt = 0; mt < 2; mt++) {
            int r0 = wbase + mt * 16 + gi, r1 = r0 + 8;
            int c0 = sCode[r0], c1 = sCode[r1];
            float f;
            f = (c0 == 0) ? acc[mt][nt][0] + bA : ((c0 == 1) ? 0.f : -FLT_MAX);
            vA = fmaxf(vA, f);
            f = (c1 == 0) ? acc[mt][nt][2] + bA : ((c1 == 1) ? 0.f : -FLT_MAX);
            vA = fmaxf(vA, f);
            f = (c0 == 0) ? acc[mt][nt][1] + bB : ((c0 == 1) ? 0.f : -FLT_MAX);
            vB = fmaxf(vB, f);
            f = (c1 == 0) ? acc[mt][nt][3] + bB : ((c1 == 1) ? 0.f : -FLT_MAX);
            vB = fmaxf(vB, f);
        }
        #pragma unroll
        for (int off = 4; off < 32; off <<= 1) {
            vA = fmaxf(vA, __shfl_xor_sync(0xFFFFFFFFu, vA, off));
            vB = fmaxf(vB, __shfl_xor_sync(0xFFFFFFFFu, vB, off));
        }
        if (gi == 0) {
            sRed[wid * 64 + col]     = vA;
            sRed[wid * 64 + col + 1] = vB;
        }
    }
    __syncthreads();
    if (tid < 128) {
        int pil = tid >> 6, col = tid & 63;
        const float* r = &sRed[pil * 4 * 64 + col];
        float m = fmaxf(fmaxf(r[0], r[64]), fmaxf(r[128], r[192]));
        g_pmax[((size_t)blockIdx.x * 2 + pil) * F + col] = m;
    }
}

// ---------------- 4) scatter winning pillar features into BEV image --------------
__global__ void scatter_kernel(const int* __restrict__ idxs) {
    int p = blockIdx.x;
    int f = threadIdx.x;
    int b = p / NPILLAR, pl = p % NPILLAR;
    int ix = idxs[2 * p], iy = idxs[2 * p + 1];
    int cell = (b * NX + ix) * NY + iy;
    if (g_winner[cell] == pl)
        g_img[(size_t)cell * F + f] = g_pmax[(size_t)p * F + f];
}

// ---------------- 5a) weight prep: fp32 -> fp16, K-blocked [tap][ci/8][co][8] ----
template <int CIN>
__global__ void wprep_kernel(const float* __restrict__ w, __half* __restrict__ wb) {
    int i = blockIdx.x * 256 + threadIdx.x;
    if (i >= 9 * 128 * CIN) return;
    int ci = i % CIN;
    int co = (i / CIN) % 128;
    int tap = i / (CIN * 128);
    float v = w[((size_t)tap * CIN + ci) * C1 + co];
    wb[((size_t)tap * (CIN / 8) + (ci >> 3)) * 1024 + co * 8 + (ci & 7)] = __float2half_rn(v);
}

// ---------------- 5b) 3x3 conv, HMMA fp16 2-term, ldmatrix frags, pipelined B ----
// CTA: 8x16 px (M=128) x 128 cout. 8 warps: (mwarp 0..3) x (nwarp 0..1).
template <int CIN, bool FUSE, int MINB>
__global__ __launch_bounds__(256, MINB) void conv3x3_hmma(
    const float* __restrict__ in, const __half* __restrict__ wb,
    const float* __restrict__ bias, float* __restrict__ out,
    const float* __restrict__ w2, const float* __restrict__ b2) {

    constexpr int KP = 2 * CIN + 8;     // A stride in halves (hi|lo|pad)
    constexpr int SLAB = CIN * 128;     // B slab halves (K-blocked)
    extern __shared__ char smem[];
    __half* sA = (__half*)smem;                                   // 180 * KP
    __half* sB = (__half*)(smem + 180 * KP * 2);                  // 2 * SLAB
    float* sbias = (float*)(smem + (180 * KP + 2 * SLAB) * 2);    // 128
    float* sw2   = sbias + 128;                                   // 128
    float* sRed  = sw2 + 128;                                     // 256

    int tid = threadIdx.x, lane = tid & 31, wid = tid >> 5;
    int bb = blockIdx.z;
    int y0 = blockIdx.y * 8, x0 = blockIdx.x * 16;
    if (tid < 128) {
        sbias[tid] = bias[tid];
        if (FUSE) sw2[tid] = w2[tid];
    }
    uint32_t sA32 = smem_u32(sA), sB32 = smem_u32(sB);
    constexpr int BCP = SLAB / 8;       // 16B chunks per slab

    // prologue: prefetch tap0 into buffer 0
    for (int t = tid; t < BCP; t += 256) cpasync16(sB32 + t * 16, wb + t * 8);
    CP_COMMIT();

    // ---- stage halo: 180 px x CIN fp32 -> fp16 hi|lo ----
    constexpr int CH = CIN / 16;
    for (int t = tid; t < 180 * CH; t += 256) {
        int hp = t / CH, c0 = (t % CH) * 16;
        int hr = hp / 18, hc = hp % 18;
        int gy = y0 - 1 + hr, gx = x0 - 1 + hc;
        __half* dhi = &sA[hp * KP + c0];
        __half* dlo = dhi + CIN;
        if (gy >= 0 && gy < NX && gx >= 0 && gx < NY) {
            const float4* s = (const float4*)&in[(((size_t)bb * NX + gy) * NY + gx) * CIN + c0];
            __half hi[16], lo[16];
            #pragma unroll
            for (int j = 0; j < 4; j++) {
                float4 v = __ldg(s + j);
                float vv[4] = {v.x, v.y, v.z, v.w};
                #pragma unroll
                for (int q = 0; q < 4; q++) {
                    __half h = __float2half_rn(vv[q]);
                    hi[j * 4 + q] = h;
                    lo[j * 4 + q] = __float2half_rn(vv[q] - __half2float(h));
                }
            }
            *(uint4*)dhi = *(uint4*)hi;  *(uint4*)(dhi + 8) = *(uint4*)(hi + 8);
            *(uint4*)dlo = *(uint4*)lo;  *(uint4*)(dlo + 8) = *(uint4*)(lo + 8);
        } else {
            uint4 z = make_uint4(0, 0, 0, 0);
            *(uint4*)dhi = z; *(uint4*)(dhi + 8) = z;
            *(uint4*)dlo = z; *(uint4*)(dlo + 8) = z;
        }
    }

    float acc[2][8][4] = {};
    const int mwarp = wid >> 1, nwarp = wid & 1;
    const int gi = lane >> 2;
    const int q2 = (lane & 3) * 2;
    // ldmatrix lane decomposition
    const int le = lane & 7;            // row within 8x8 tile
    const int lt = lane >> 3;           // tile index 0..3

    // B ldmatrix lane base (per j pair of n-tiles), buffer-relative bytes:
    // tile order: (n lo, kb), (n lo, kb+1), (n hi, kb), (n hi, kb+1)
    uint32_t bBase[4];
    #pragma unroll
    for (int j = 0; j < 4; j++) {
        int n_lane = nwarp * 64 + j * 16 + (lt >> 1) * 8 + le;
        bBase[j] = (lt & 1) * 2048 + n_lane * 16;
    }

    for (int tap = 0; tap < 9; ++tap) {
        CP_WAIT(0);            // tap's slab landed
        __syncthreads();       // + all readers of tap-1 done
        if (tap < 8) {         // prefetch next tap into the other buffer
            const __half* src = wb + (size_t)(tap + 1) * SLAB;
            uint32_t dst = sB32 + ((tap + 1) & 1) * SLAB * 2;
            for (int t = tid; t < BCP; t += 256) cpasync16(dst + t * 16, src + t * 8);
            CP_COMMIT();
        }
        const uint32_t sBc32 = sB32 + (tap & 1) * SLAB * 2;

        const int dy = tap / 3 - 1, dx = tap % 3 - 1;
        // A ldmatrix lane bases per m-tile:
        // tile order: (m lo, k lo)=a0, (m hi, k lo)=a1, (m lo, k hi)=a2, (m hi, k hi)=a3
        uint32_t aBase[2];
        #pragma unroll
        for (int mt = 0; mt < 2; mt++) {
            int hr = mwarp * 2 + mt + 1 + dy;
            int pxrow = hr * 18 + (1 + dx) + le + (lt & 1) * 8;
            aBase[mt] = sA32 + (pxrow * KP + (lt >> 1) * 8) * 2;
        }

        // ---- seg0 (Ah x B) + seg1 (Al x B) ----
        #pragma unroll
        for (int seg = 0; seg < 2; ++seg) {
            const int aoff = (seg == 1) ? CIN : 0;
            #pragma unroll 4
            for (int k0 = 0; k0 < CIN; k0 += 16) {
                uint32_t a[2][4];
                ldsm_x4(a[0], aBase[0] + (aoff + k0) * 2);
                ldsm_x4(a[1], aBase[1] + (aoff + k0) * 2);
                const uint32_t boff = sBc32 + (k0 >> 3) * 2048;
                #pragma unroll
                for (int j = 0; j < 4; j++) {
                    uint32_t b[4];
                    ldsm_x4(b, boff + bBase[j]);
                    mma_f16(acc[0][2 * j],     a[0], b);
                    mma_f16(acc[1][2 * j],     a[1], b);
                    mma_f16(acc[0][2 * j + 1], a[0], b + 2);
                    mma_f16(acc[1][2 * j + 1], a[1], b + 2);
                }
            }
        }
    }

    if (!FUSE) {
        // ---- epilogue: bias + tanh + store 128ch fp32 ----
        #pragma unroll
        for (int mt = 0; mt < 2; mt++) {
            int gy = y0 + mwarp * 2 + mt;
            #pragma unroll
            for (int half = 0; half < 2; half++) {
                int gx = x0 + gi + half * 8;
                float* op = &out[(((size_t)bb * NX + gy) * NY + gx) * C1];
                #pragma unroll
                for (int nt = 0; nt < 8; nt++) {
                    int n = nwarp * 64 + nt * 8 + q2;
                    float2 v;
                    v.x = tanhf(acc[mt][nt][half * 2 + 0] + sbias[n]);
                    v.y = tanhf(acc[mt][nt][half * 2 + 1] + sbias[n + 1]);
                    *(float2*)&op[n] = v;
                }
            }
        }
    } else {
        // ---- fused epilogue: tanh + 1x1 conv dot + relu -> out [B,NX,NY] ----
        float part[2][2] = {};
        #pragma unroll
        for (int mt = 0; mt < 2; mt++)
        #pragma unroll
        for (int half = 0; half < 2; half++)
        #pragma unroll
        for (int nt = 0; nt < 8; nt++) {
            int n = nwarp * 64 + nt * 8 + q2;
            part[mt][half] += tanhf(acc[mt][nt][half * 2 + 0] + sbias[n])     * sw2[n]
                            + tanhf(acc[mt][nt][half * 2 + 1] + sbias[n + 1]) * sw2[n + 1];
        }
        #pragma unroll
        for (int mt = 0; mt < 2; mt++)
        #pragma unroll
        for (int half = 0; half < 2; half++) {
            float v = part[mt][half];
            v += __shfl_xor_sync(0xFFFFFFFFu, v, 1);
            v += __shfl_xor_sync(0xFFFFFFFFu, v, 2);
            if ((lane & 3) == 0) {
                int px = (mwarp * 2 + mt) * 16 + gi + half * 8;
                sRed[px * 2 + nwarp] = v;
            }
        }
        __syncthreads();
        if (tid < 128) {
            float v = sRed[tid * 2] + sRed[tid * 2 + 1] + __ldg(b2);
            int gy = y0 + (tid >> 4), gx = x0 + (tid & 15);
            out[((size_t)bb * NX + gy) * NY + gx] = fmaxf(v, 0.f);
        }
    }
}

// ---------------- host launcher ----------------
extern "C" void kernel_launch(void* const* d_in, const int* in_sizes, int n_in,
                              void* d_out, int out_size) {
    const float* pillars = (const float*)d_in[0];
    const int*   idxs    = (const int*)d_in[1];
    const float* pn_w0 = (const float*)d_in[4];
    const float* pn_b0 = (const float*)d_in[5];
    const float* pn_w1 = (const float*)d_in[6];
    const float* pn_b1 = (const float*)d_in[7];
    const float* cw0   = (const float*)d_in[8];
    const float* cb0   = (const float*)d_in[9];
    const float* cw1   = (const float*)d_in[10];
    const float* cb1   = (const float*)d_in[11];
    const float* cw2   = (const float*)d_in[12];
    const float* cb2   = (const float*)d_in[13];
    float* out = (float*)d_out;

    float *p_img, *p_x1;
    __half *p_wb1, *p_wb2;
    cudaGetSymbolAddress((void**)&p_img, g_img);
    cudaGetSymbolAddress((void**)&p_x1, g_x1);
    cudaGetSymbolAddress((void**)&p_wb1, g_wb1);
    cudaGetSymbolAddress((void**)&p_wb2, g_wb2);

    const int smem1 = (180 * (2 * 64 + 8) + 2 * 64 * 128) * 2 + 512 * 4;    //  83,776 B
    const int smem2 = (180 * (2 * 128 + 8) + 2 * 128 * 128) * 2 + 512 * 4;  // 162,624 B
    const int smemP = 256 * KH * 2 + 8192 + (512 + 64 + 64 + 512) * 4 + 256 * 4;
    cudaFuncSetAttribute((const void*)conv3x3_hmma<64, false, 2>,
                         cudaFuncAttributeMaxDynamicSharedMemorySize, smem1);
    cudaFuncSetAttribute((const void*)conv3x3_hmma<128, true, 1>,
                         cudaFuncAttributeMaxDynamicSharedMemorySize, smem2);
    cudaFuncSetAttribute((const void*)pointnet_hmma,
                         cudaFuncAttributeMaxDynamicSharedMemorySize, smemP);

    zero_kernel<<<2048, 256>>>();
    winner_kernel<<<(BATCH * NPILLAR + 255) / 256, 256>>>(idxs);
    wprep_kernel<64> <<<(9 * 128 * 64 + 255) / 256, 256>>>(cw0, p_wb1);
    wprep_kernel<128><<<(9 * 128 * 128 + 255) / 256, 256>>>(cw1, p_wb2);
    pointnet_hmma<<<BATCH * NPILLAR / 2, 256, smemP>>>(pillars, pn_w0, pn_b0, pn_w1, pn_b1);
    scatter_kernel<<<BATCH * NPILLAR, 64>>>(idxs);

    dim3 cgrid(NX / 16, NY / 8, BATCH);   // (15, 30, 4)
    conv3x3_hmma<64, false, 2><<<cgrid, 256, smem1>>>(p_img, p_wb1, cb0, p_x1, nullptr, nullptr);
    conv3x3_hmma<128, true, 1><<<cgrid, 256, smem2>>>(p_x1,  p_wb2, cb1, out,  cw2,     cb2);
}

// round 9
// speedup vs baseline: 5.2043x; 1.8254x over previous
#include <cuda_runtime.h>
#include <cuda_fp16.h>
#include <cstdint>
#include <math.h>
#include <float.h>

#define BATCH 4
#define NPILLAR 5000
#define NPT 100
#define CPT 8
#define NX 240
#define NY 240
#define F 64      // PN_FEAT
#define C1 128    // conv hidden channels
#define KH 72     // pointnet sH stride in halves (64 + 8 pad)

// ---------------- scratch (device globals; no allocation allowed) ----------------
__device__ float g_pmax[BATCH * NPILLAR * F];
__device__ __align__(16) __half g_img[BATCH * NX * NY * F];    // fp16 BEV image
__device__ __align__(16) __half g_x1 [BATCH * NX * NY * C1];   // fp16 conv1 output
__device__ int g_winner[BATCH * NX * NY];
// fp16 weights, K-blocked layout [tap][k/8][co][8]
__device__ __align__(16) __half g_wb1[9 * 64 * 128];    // conv1 (CIN=64)
__device__ __align__(16) __half g_wb2[9 * 128 * 128];   // conv2 (CIN=128)

// ---------------- HMMA m16n8k16 fp16 + ldmatrix (plain sm_75/80 PTX) -------------
__device__ __forceinline__ void mma_f16(float* d, const uint32_t* a, const uint32_t* b) {
    asm volatile(
        "mma.sync.aligned.m16n8k16.row.col.f32.f16.f16.f32 "
        "{%0,%1,%2,%3}, {%4,%5,%6,%7}, {%8,%9}, {%0,%1,%2,%3};"
        : "+f"(d[0]), "+f"(d[1]), "+f"(d[2]), "+f"(d[3])
        : "r"(a[0]), "r"(a[1]), "r"(a[2]), "r"(a[3]), "r"(b[0]), "r"(b[1]));
}
__device__ __forceinline__ void ldsm_x4(uint32_t* r, uint32_t addr) {
    asm volatile("ldmatrix.sync.aligned.m8n8.x4.shared.b16 {%0,%1,%2,%3}, [%4];"
        : "=r"(r[0]), "=r"(r[1]), "=r"(r[2]), "=r"(r[3]) : "r"(addr));
}
__device__ __forceinline__ uint32_t smem_u32(const void* p) {
    uint32_t a;
    asm("{ .reg .u64 t; cvta.to.shared.u64 t, %1; cvt.u32.u64 %0, t; }" : "=r"(a) : "l"(p));
    return a;
}
__device__ __forceinline__ void cpasync16(uint32_t s, const void* g) {
    asm volatile("cp.async.cg.shared.global [%0], [%1], 16;" :: "r"(s), "l"(g));
}
#define CP_COMMIT() asm volatile("cp.async.commit_group;" ::: "memory")
#define CP_WAIT(n)  asm volatile("cp.async.wait_group %0;" :: "n"(n) : "memory")

// ---------------- 1) zero BEV image (fp16) + init winner map ----------------
__global__ void zero_kernel() {
    int tid = blockIdx.x * blockDim.x + threadIdx.x;
    int stride = gridDim.x * blockDim.x;
    const int n8 = BATCH * NX * NY * F / 8;     // uint4 = 8 halves
    uint4 z = make_uint4(0, 0, 0, 0);
    for (int i = tid; i < n8; i += stride)
        reinterpret_cast<uint4*>(g_img)[i] = z;
    for (int i = tid; i < BATCH * NX * NY; i += stride)
        g_winner[i] = -1;
}

// ---------------- 2) duplicate-cell winner (last update wins = max pillar idx) ---
__global__ void winner_kernel(const int* __restrict__ idxs) {
    int p = blockIdx.x * blockDim.x + threadIdx.x;
    if (p >= BATCH * NPILLAR) return;
    int b = p / NPILLAR, pl = p % NPILLAR;
    int ix = idxs[2 * p], iy = idxs[2 * p + 1];
    atomicMax(&g_winner[(b * NX + ix) * NY + iy], pl);
}

// ---------------- 3) pointnet: layer0 scalar+tanh, layer1 HMMA fp16 single ------
__global__ __launch_bounds__(256) void pointnet_hmma(
    const float* __restrict__ pillars,
    const float* __restrict__ w0, const float* __restrict__ b0,
    const float* __restrict__ w1, const float* __restrict__ b1) {

    extern __shared__ char sm[];
    __half* sH = (__half*)sm;                               // 256 * KH
    __half* sW = (__half*)(sm + 256 * KH * 2);              // 4096 (K-blocked [k/8][n][8])
    float* sW0  = (float*)(sm + 256 * KH * 2 + 8192);       // 8*64
    float* sB0  = sW0 + 512;
    float* sB1  = sB0 + 64;
    float* sRed = sB1 + 64;                                 // 8*64
    int*   sCode = (int*)(sRed + 512);                      // 256

    int tid = threadIdx.x, lane = tid & 31, wid = tid >> 5;

    for (int i = tid; i < 512; i += 256) sW0[i] = w0[i];
    if (tid < 64) { sB0[tid] = b0[tid]; sB1[tid] = b1[tid]; }
    for (int i = tid; i < 4096; i += 256) {
        int k = i >> 6, n = i & 63;
        sW[(k >> 3) * 512 + n * 8 + (k & 7)] = __float2half_rn(w1[i]);
    }
    __syncthreads();

    {   // ---- layer 0: one thread per row ----
        int row = tid;
        int pt = row & 127;
        uint32_t* dst = (uint32_t*)&sH[row * KH];
        if (pt < NPT) {
            int pil = blockIdx.x * 2 + (row >> 7);
            const float4* px = (const float4*)(pillars + ((size_t)pil * NPT + pt) * CPT);
            float4 A = __ldg(px), B = __ldg(px + 1);
            float x[8] = {A.x, A.y, A.z, A.w, B.x, B.y, B.z, B.w};
            float ss = 0.f;
            #pragma unroll
            for (int k = 0; k < 8; k++) ss += x[k] * x[k];
            sCode[row] = (ss < 1e12f) ? 0 : 1;
            #pragma unroll
            for (int n0 = 0; n0 < 64; n0 += 16) {
                uint32_t hw[8];
                #pragma unroll
                for (int q = 0; q < 8; q++) {
                    int n = n0 + 2 * q;
                    float a0 = sB0[n], a1 = sB0[n + 1];
                    #pragma unroll
                    for (int k = 0; k < 8; k++) {
                        a0 += x[k] * sW0[k * 64 + n];
                        a1 += x[k] * sW0[k * 64 + n + 1];
                    }
                    __half2 hp;
                    hp.x = __float2half_rn(tanhf(a0));
                    hp.y = __float2half_rn(tanhf(a1));
                    hw[q] = *(uint32_t*)&hp;
                }
                *(uint4*)(dst + n0 / 2)     = make_uint4(hw[0], hw[1], hw[2], hw[3]);
                *(uint4*)(dst + n0 / 2 + 4) = make_uint4(hw[4], hw[5], hw[6], hw[7]);
            }
        } else {
            sCode[row] = 2;
            uint4 z = make_uint4(0, 0, 0, 0);
            #pragma unroll
            for (int j = 0; j < 8; j++) *(uint4*)(dst + 4 * j) = z;
        }
    }
    __syncthreads();

    // ---- layer 1 via HMMA fp16 (single term): warp = 32 rows x 64 cols ----
    const int gi = lane >> 2, q2 = (lane & 3) * 2;
    const int wbase = wid * 32;
    float acc[2][8][4] = {};
    #pragma unroll
    for (int k0 = 0; k0 < 64; k0 += 16) {
        const int ka = k0 + q2;
        uint32_t a[2][4];
        #pragma unroll
        for (int mt = 0; mt < 2; mt++) {
            int r0 = (wbase + mt * 16 + gi) * KH;
            int r1 = r0 + 8 * KH;
            a[mt][0] = *(const uint32_t*)&sH[r0 + ka];
            a[mt][1] = *(const uint32_t*)&sH[r1 + ka];
            a[mt][2] = *(const uint32_t*)&sH[r0 + ka + 8];
            a[mt][3] = *(const uint32_t*)&sH[r1 + ka + 8];
        }
        const __half* wp = &sW[(k0 >> 3) * 512 + q2];
        #pragma unroll
        for (int nt = 0; nt < 8; nt++) {
            const int n = nt * 8 + gi;
            uint32_t b[2];
            b[0] = *(const uint32_t*)&wp[n * 8];
            b[1] = *(const uint32_t*)&wp[n * 8 + 512];
            mma_f16(acc[0][nt], a[0], b);
            mma_f16(acc[1][nt], a[1], b);
        }
    }

    // ---- masked max reduction ----
    #pragma unroll
    for (int nt = 0; nt < 8; nt++) {
        int col = nt * 8 + q2;
        float bA = sB1[col], bB = sB1[col + 1];
        float vA = -FLT_MAX, vB = -FLT_MAX;
        #pragma unroll
        for (int mt = 0; mt < 2; mt++) {
            int r0 = wbase + mt * 16 + gi, r1 = r0 + 8;
            int c0 = sCode[r0], c1 = sCode[r1];
            float f;
            f = (c0 == 0) ? acc[mt][nt][0] + bA : ((c0 == 1) ? 0.f : -FLT_MAX);
            vA = fmaxf(vA, f);
            f = (c1 == 0) ? acc[mt][nt][2] + bA : ((c1 == 1) ? 0.f : -FLT_MAX);
            vA = fmaxf(vA, f);
            f = (c0 == 0) ? acc[mt][nt][1] + bB : ((c0 == 1) ? 0.f : -FLT_MAX);
            vB = fmaxf(vB, f);
            f = (c1 == 0) ? acc[mt][nt][3] + bB : ((c1 == 1) ? 0.f : -FLT_MAX);
            vB = fmaxf(vB, f);
        }
        #pragma unroll
        for (int off = 4; off < 32; off <<= 1) {
            vA = fmaxf(vA, __shfl_xor_sync(0xFFFFFFFFu, vA, off));
            vB = fmaxf(vB, __shfl_xor_sync(0xFFFFFFFFu, vB, off));
        }
        if (gi == 0) {
            sRed[wid * 64 + col]     = vA;
            sRed[wid * 64 + col + 1] = vB;
        }
    }
    __syncthreads();
    if (tid < 128) {
        int pil = tid >> 6, col = tid & 63;
        const float* r = &sRed[pil * 4 * 64 + col];
        float m = fmaxf(fmaxf(r[0], r[64]), fmaxf(r[128], r[192]));
        g_pmax[((size_t)blockIdx.x * 2 + pil) * F + col] = m;
    }
}

// ---------------- 4) scatter winning pillar features into fp16 BEV image ---------
__global__ void scatter_kernel(const int* __restrict__ idxs) {
    int p = blockIdx.x;
    int f = threadIdx.x;
    int b = p / NPILLAR, pl = p % NPILLAR;
    int ix = idxs[2 * p], iy = idxs[2 * p + 1];
    int cell = (b * NX + ix) * NY + iy;
    if (g_winner[cell] == pl)
        g_img[(size_t)cell * F + f] = __float2half_rn(g_pmax[(size_t)p * F + f]);
}

// ---------------- 5a) weight prep: fp32 -> fp16, K-blocked [tap][ci/8][co][8] ----
template <int CIN>
__global__ void wprep_kernel(const float* __restrict__ w, __half* __restrict__ wb) {
    int i = blockIdx.x * 256 + threadIdx.x;
    if (i >= 9 * 128 * CIN) return;
    int ci = i % CIN;
    int co = (i / CIN) % 128;
    int tap = i / (CIN * 128);
    float v = w[((size_t)tap * CIN + ci) * C1 + co];
    wb[((size_t)tap * (CIN / 8) + (ci >> 3)) * 1024 + co * 8 + (ci & 7)] = __float2half_rn(v);
}

// ---------------- 5b) 3x3 conv, HMMA fp16 single-term, fp16 in, pipelined B ------
// CTA: 8x16 px (M=128) x 128 cout. 8 warps: (mwarp 0..3) x (nwarp 0..1).
// FUSE=false: out = fp16 (conv1->g_x1). FUSE=true: tanh+1x1+relu -> fp32 out.
template <int CIN, bool FUSE, int MINB>
__global__ __launch_bounds__(256, MINB) void conv3x3_hmma(
    const __half* __restrict__ in, const __half* __restrict__ wb,
    const float* __restrict__ bias, void* __restrict__ out_,
    const float* __restrict__ w2, const float* __restrict__ b2) {

    constexpr int KP = CIN + 8;         // A stride in halves
    constexpr int SLAB = CIN * 128;     // B slab halves (K-blocked)
    extern __shared__ char smem[];
    __half* sA = (__half*)smem;                                   // 180 * KP
    __half* sB = (__half*)(smem + 180 * KP * 2);                  // 2 * SLAB
    float* sbias = (float*)(smem + (180 * KP + 2 * SLAB) * 2);    // 128
    float* sw2   = sbias + 128;                                   // 128
    float* sRed  = sw2 + 128;                                     // 256

    int tid = threadIdx.x, lane = tid & 31, wid = tid >> 5;
    int bb = blockIdx.z;
    int y0 = blockIdx.y * 8, x0 = blockIdx.x * 16;
    if (tid < 128) {
        sbias[tid] = bias[tid];
        if (FUSE) sw2[tid] = w2[tid];
    }
    uint32_t sA32 = smem_u32(sA), sB32 = smem_u32(sB);
    constexpr int BCP = SLAB / 8;       // 16B chunks per slab

    // prologue: prefetch tap0 B into buffer 0
    for (int t = tid; t < BCP; t += 256) cpasync16(sB32 + t * 16, wb + t * 8);
    CP_COMMIT();

    // ---- stage halo: 180 px x CIN fp16, straight async copy (zero OOB) ----
    constexpr int CH8 = CIN / 8;        // 16B chunks per pixel
    for (int t = tid; t < 180 * CH8; t += 256) {
        int hp = t / CH8, c0 = (t % CH8) * 8;
        int hr = hp / 18, hc = hp % 18;
        int gy = y0 - 1 + hr, gx = x0 - 1 + hc;
        if (gy >= 0 && gy < NX && gx >= 0 && gx < NY)
            cpasync16(sA32 + (hp * KP + c0) * 2,
                      in + (((size_t)bb * NX + gy) * NY + gx) * CIN + c0);
        else
            *(uint4*)&sA[hp * KP + c0] = make_uint4(0, 0, 0, 0);
    }
    CP_COMMIT();

    float acc[2][8][4] = {};
    const int mwarp = wid >> 1, nwarp = wid & 1;
    const int gi = lane >> 2;
    const int q2 = (lane & 3) * 2;
    const int le = lane & 7;            // ldmatrix row within 8x8 tile
    const int lt = lane >> 3;           // ldmatrix tile index 0..3

    // B ldmatrix lane base (per j pair of n-tiles), buffer-relative bytes
    uint32_t bBase[4];
    #pragma unroll
    for (int j = 0; j < 4; j++) {
        int n_lane = nwarp * 64 + j * 16 + (lt >> 1) * 8 + le;
        bBase[j] = (lt & 1) * 2048 + n_lane * 16;
    }

    for (int tap = 0; tap < 9; ++tap) {
        CP_WAIT(0);            // tap's B slab (+halo on tap 0) landed
        __syncthreads();       // + all readers of tap-1 done
        if (tap < 8) {         // prefetch next tap into the other buffer
            const __half* src = wb + (size_t)(tap + 1) * SLAB;
            uint32_t dst = sB32 + ((tap + 1) & 1) * SLAB * 2;
            for (int t = tid; t < BCP; t += 256) cpasync16(dst + t * 16, src + t * 8);
            CP_COMMIT();
        }
        const uint32_t sBc32 = sB32 + (tap & 1) * SLAB * 2;

        const int dy = tap / 3 - 1, dx = tap % 3 - 1;
        uint32_t aBase[2];
        #pragma unroll
        for (int mt = 0; mt < 2; mt++) {
            int hr = mwarp * 2 + mt + 1 + dy;
            int pxrow = hr * 18 + (1 + dx) + le + (lt & 1) * 8;
            aBase[mt] = sA32 + (pxrow * KP + (lt >> 1) * 8) * 2;
        }

        // ---- single segment: A(fp16) x B(fp16) ----
        #pragma unroll 4
        for (int k0 = 0; k0 < CIN; k0 += 16) {
            uint32_t a[2][4];
            ldsm_x4(a[0], aBase[0] + k0 * 2);
            ldsm_x4(a[1], aBase[1] + k0 * 2);
            const uint32_t boff = sBc32 + (k0 >> 3) * 2048;
            #pragma unroll
            for (int j = 0; j < 4; j++) {
                uint32_t b[4];
                ldsm_x4(b, boff + bBase[j]);
                mma_f16(acc[0][2 * j],     a[0], b);
                mma_f16(acc[1][2 * j],     a[1], b);
                mma_f16(acc[0][2 * j + 1], a[0], b + 2);
                mma_f16(acc[1][2 * j + 1], a[1], b + 2);
            }
        }
    }

    if (!FUSE) {
        // ---- epilogue: bias + tanh -> fp16 store (feeds conv2) ----
        __half* out = (__half*)out_;
        #pragma unroll
        for (int mt = 0; mt < 2; mt++) {
            int gy = y0 + mwarp * 2 + mt;
            #pragma unroll
            for (int half = 0; half < 2; half++) {
                int gx = x0 + gi + half * 8;
                __half* op = &out[(((size_t)bb * NX + gy) * NY + gx) * C1];
                #pragma unroll
                for (int nt = 0; nt < 8; nt++) {
                    int n = nwarp * 64 + nt * 8 + q2;
                    __half2 v;
                    v.x = __float2half_rn(tanhf(acc[mt][nt][half * 2 + 0] + sbias[n]));
                    v.y = __float2half_rn(tanhf(acc[mt][nt][half * 2 + 1] + sbias[n + 1]));
                    *(__half2*)&op[n] = v;
                }
            }
        }
    } else {
        // ---- fused epilogue: tanh + 1x1 conv dot + relu -> fp32 out [B,NX,NY] ----
        float* out = (float*)out_;
        float part[2][2] = {};
        #pragma unroll
        for (int mt = 0; mt < 2; mt++)
        #pragma unroll
        for (int half = 0; half < 2; half++)
        #pragma unroll
        for (int nt = 0; nt < 8; nt++) {
            int n = nwarp * 64 + nt * 8 + q2;
            part[mt][half] += tanhf(acc[mt][nt][half * 2 + 0] + sbias[n])     * sw2[n]
                            + tanhf(acc[mt][nt][half * 2 + 1] + sbias[n + 1]) * sw2[n + 1];
        }
        #pragma unroll
        for (int mt = 0; mt < 2; mt++)
        #pragma unroll
        for (int half = 0; half < 2; half++) {
            float v = part[mt][half];
            v += __shfl_xor_sync(0xFFFFFFFFu, v, 1);
            v += __shfl_xor_sync(0xFFFFFFFFu, v, 2);
            if ((lane & 3) == 0) {
                int px = (mwarp * 2 + mt) * 16 + gi + half * 8;
                sRed[px * 2 + nwarp] = v;
            }
        }
        __syncthreads();
        if (tid < 128) {
            float v = sRed[tid * 2] + sRed[tid * 2 + 1] + __ldg(b2);
            int gy = y0 + (tid >> 4), gx = x0 + (tid & 15);
            out[((size_t)bb * NX + gy) * NY + gx] = fmaxf(v, 0.f);
        }
    }
}

// ---------------- host launcher ----------------
extern "C" void kernel_launch(void* const* d_in, const int* in_sizes, int n_in,
                              void* d_out, int out_size) {
    const float* pillars = (const float*)d_in[0];
    const int*   idxs    = (const int*)d_in[1];
    const float* pn_w0 = (const float*)d_in[4];
    const float* pn_b0 = (const float*)d_in[5];
    const float* pn_w1 = (const float*)d_in[6];
    const float* pn_b1 = (const float*)d_in[7];
    const float* cw0   = (const float*)d_in[8];
    const float* cb0   = (const float*)d_in[9];
    const float* cw1   = (const float*)d_in[10];
    const float* cb1   = (const float*)d_in[11];
    const float* cw2   = (const float*)d_in[12];
    const float* cb2   = (const float*)d_in[13];
    float* out = (float*)d_out;

    __half *p_img, *p_x1, *p_wb1, *p_wb2;
    cudaGetSymbolAddress((void**)&p_img, g_img);
    cudaGetSymbolAddress((void**)&p_x1, g_x1);
    cudaGetSymbolAddress((void**)&p_wb1, g_wb1);
    cudaGetSymbolAddress((void**)&p_wb2, g_wb2);

    const int smem1 = (180 * (64 + 8)  + 2 * 64 * 128)  * 2 + 512 * 4;  //  60,736 B
    const int smem2 = (180 * (128 + 8) + 2 * 128 * 128) * 2 + 512 * 4;  // 116,544 B
    const int smemP = 256 * KH * 2 + 8192 + (512 + 64 + 64 + 512) * 4 + 256 * 4;
    cudaFuncSetAttribute((const void*)conv3x3_hmma<64, false, 2>,
                         cudaFuncAttributeMaxDynamicSharedMemorySize, smem1);
    cudaFuncSetAttribute((const void*)conv3x3_hmma<128, true, 1>,
                         cudaFuncAttributeMaxDynamicSharedMemorySize, smem2);
    cudaFuncSetAttribute((const void*)pointnet_hmma,
                         cudaFuncAttributeMaxDynamicSharedMemorySize, smemP);

    zero_kernel<<<2048, 256>>>();
    winner_kernel<<<(BATCH * NPILLAR + 255) / 256, 256>>>(idxs);
    wprep_kernel<64> <<<(9 * 128 * 64 + 255) / 256, 256>>>(cw0, p_wb1);
    wprep_kernel<128><<<(9 * 128 * 128 + 255) / 256, 256>>>(cw1, p_wb2);
    pointnet_hmma<<<BATCH * NPILLAR / 2, 256, smemP>>>(pillars, pn_w0, pn_b0, pn_w1, pn_b1);
    scatter_kernel<<<BATCH * NPILLAR, 64>>>(idxs);

    dim3 cgrid(NX / 16, NY / 8, BATCH);   // (15, 30, 4)
    conv3x3_hmma<64, false, 2><<<cgrid, 256, smem1>>>(p_img, p_wb1, cb0, p_x1, nullptr, nullptr);
    conv3x3_hmma<128, true, 1><<<cgrid, 256, smem2>>>(p_x1,  p_wb2, cb1, out,  cw2,     cb2);
}

// round 10
// speedup vs baseline: 5.7461x; 1.1041x over previous
#include <cuda_runtime.h>
#include <cuda_fp16.h>
#include <cstdint>
#include <math.h>
#include <float.h>

#define BATCH 4
#define NPILLAR 5000
#define NPT 100
#define CPT 8
#define NX 240
#define NY 240
#define F 64      // PN_FEAT
#define C1 128    // conv hidden channels
#define KH 72     // pointnet sH stride in halves (64 + 8 pad)

// ---------------- scratch (device globals; no allocation allowed) ----------------
__device__ __align__(16) __half g_img[BATCH * NX * NY * F];    // fp16 BEV image
__device__ __align__(16) __half g_x1 [BATCH * NX * NY * C1];   // fp16 conv1 output
__device__ int g_winner[BATCH * NX * NY];
// fp16 weights, K-blocked layout [tap][k/8][co][8]
__device__ __align__(16) __half g_wb1[9 * 64 * 128];    // conv1 (CIN=64)
__device__ __align__(16) __half g_wb2[9 * 128 * 128];   // conv2 (CIN=128)

// ---------------- HMMA m16n8k16 fp16 + ldmatrix (plain sm_75/80 PTX) -------------
__device__ __forceinline__ void mma_f16(float* d, const uint32_t* a, const uint32_t* b) {
    asm volatile(
        "mma.sync.aligned.m16n8k16.row.col.f32.f16.f16.f32 "
        "{%0,%1,%2,%3}, {%4,%5,%6,%7}, {%8,%9}, {%0,%1,%2,%3};"
        : "+f"(d[0]), "+f"(d[1]), "+f"(d[2]), "+f"(d[3])
        : "r"(a[0]), "r"(a[1]), "r"(a[2]), "r"(a[3]), "r"(b[0]), "r"(b[1]));
}
__device__ __forceinline__ void ldsm_x4(uint32_t* r, uint32_t addr) {
    asm volatile("ldmatrix.sync.aligned.m8n8.x4.shared.b16 {%0,%1,%2,%3}, [%4];"
        : "=r"(r[0]), "=r"(r[1]), "=r"(r[2]), "=r"(r[3]) : "r"(addr));
}
__device__ __forceinline__ uint32_t smem_u32(const void* p) {
    uint32_t a;
    asm("{ .reg .u64 t; cvta.to.shared.u64 t, %1; cvt.u32.u64 %0, t; }" : "=r"(a) : "l"(p));
    return a;
}
__device__ __forceinline__ void cpasync16(uint32_t s, const void* g) {
    asm volatile("cp.async.cg.shared.global [%0], [%1], 16;" :: "r"(s), "l"(g));
}
#define CP_COMMIT() asm volatile("cp.async.commit_group;" ::: "memory")
#define CP_WAIT(n)  asm volatile("cp.async.wait_group %0;" :: "n"(n) : "memory")
// fast tanh (MUFU.TANH) — used ONLY in pointnet layer0 (deepest stage, error averages out)
__device__ __forceinline__ float tanh_fast(float x) {
    float y;
    asm("tanh.approx.f32 %0, %1;" : "=f"(y) : "f"(x));
    return y;
}

// ---------------- 1) zero BEV image (fp16) + init winner map ----------------
__global__ void zero_kernel() {
    int tid = blockIdx.x * blockDim.x + threadIdx.x;
    int stride = gridDim.x * blockDim.x;
    const int n8 = BATCH * NX * NY * F / 8;     // uint4 = 8 halves
    uint4 z = make_uint4(0, 0, 0, 0);
    for (int i = tid; i < n8; i += stride)
        reinterpret_cast<uint4*>(g_img)[i] = z;
    for (int i = tid; i < BATCH * NX * NY; i += stride)
        g_winner[i] = -1;
}

// ---------------- 2) duplicate-cell winner (last update wins = max pillar idx) ---
__global__ void winner_kernel(const int* __restrict__ idxs) {
    int p = blockIdx.x * blockDim.x + threadIdx.x;
    if (p >= BATCH * NPILLAR) return;
    int b = p / NPILLAR, pl = p % NPILLAR;
    int ix = idxs[2 * p], iy = idxs[2 * p + 1];
    atomicMax(&g_winner[(b * NX + ix) * NY + iy], pl);
}

// ---------------- 3) pointnet + fused scatter ------------------------------------
// layer0 scalar + tanh.approx, layer1 HMMA fp16, masked max, winner-checked
// direct fp16 write into g_img. CTA = 2 pillars (256 padded rows).
__global__ __launch_bounds__(256) void pointnet_hmma(
    const float* __restrict__ pillars, const int* __restrict__ idxs,
    const float* __restrict__ w0, const float* __restrict__ b0,
    const float* __restrict__ w1, const float* __restrict__ b1) {

    extern __shared__ char sm[];
    __half* sH = (__half*)sm;                               // 256 * KH
    __half* sW = (__half*)(sm + 256 * KH * 2);              // 4096 (K-blocked [k/8][n][8])
    float* sW0  = (float*)(sm + 256 * KH * 2 + 8192);       // 8*64
    float* sB0  = sW0 + 512;
    float* sB1  = sB0 + 64;
    float* sRed = sB1 + 64;                                 // 8*64
    int*   sCode = (int*)(sRed + 512);                      // 256

    int tid = threadIdx.x, lane = tid & 31, wid = tid >> 5;

    for (int i = tid; i < 512; i += 256) sW0[i] = w0[i];
    if (tid < 64) { sB0[tid] = b0[tid]; sB1[tid] = b1[tid]; }
    for (int i = tid; i < 4096; i += 256) {
        int k = i >> 6, n = i & 63;
        sW[(k >> 3) * 512 + n * 8 + (k & 7)] = __float2half_rn(w1[i]);
    }
    __syncthreads();

    {   // ---- layer 0: one thread per row ----
        int row = tid;
        int pt = row & 127;
        uint32_t* dst = (uint32_t*)&sH[row * KH];
        if (pt < NPT) {
            int pil = blockIdx.x * 2 + (row >> 7);
            const float4* px = (const float4*)(pillars + ((size_t)pil * NPT + pt) * CPT);
            float4 A = __ldg(px), B = __ldg(px + 1);
            float x[8] = {A.x, A.y, A.z, A.w, B.x, B.y, B.z, B.w};
            float ss = 0.f;
            #pragma unroll
            for (int k = 0; k < 8; k++) ss += x[k] * x[k];
            sCode[row] = (ss < 1e12f) ? 0 : 1;
            #pragma unroll
            for (int n0 = 0; n0 < 64; n0 += 16) {
                uint32_t hw[8];
                #pragma unroll
                for (int q = 0; q < 8; q++) {
                    int n = n0 + 2 * q;
                    float a0 = sB0[n], a1 = sB0[n + 1];
                    #pragma unroll
                    for (int k = 0; k < 8; k++) {
                        a0 += x[k] * sW0[k * 64 + n];
                        a1 += x[k] * sW0[k * 64 + n + 1];
                    }
                    __half2 hp;
                    hp.x = __float2half_rn(tanh_fast(a0));
                    hp.y = __float2half_rn(tanh_fast(a1));
                    hw[q] = *(uint32_t*)&hp;
                }
                *(uint4*)(dst + n0 / 2)     = make_uint4(hw[0], hw[1], hw[2], hw[3]);
                *(uint4*)(dst + n0 / 2 + 4) = make_uint4(hw[4], hw[5], hw[6], hw[7]);
            }
        } else {
            sCode[row] = 2;
            uint4 z = make_uint4(0, 0, 0, 0);
            #pragma unroll
            for (int j = 0; j < 8; j++) *(uint4*)(dst + 4 * j) = z;
        }
    }
    __syncthreads();

    // ---- layer 1 via HMMA fp16: warp = 32 rows x 64 cols ----
    const int gi = lane >> 2, q2 = (lane & 3) * 2;
    const int wbase = wid * 32;
    float acc[2][8][4] = {};
    #pragma unroll
    for (int k0 = 0; k0 < 64; k0 += 16) {
        const int ka = k0 + q2;
        uint32_t a[2][4];
        #pragma unroll
        for (int mt = 0; mt < 2; mt++) {
            int r0 = (wbase + mt * 16 + gi) * KH;
            int r1 = r0 + 8 * KH;
            a[mt][0] = *(const uint32_t*)&sH[r0 + ka];
            a[mt][1] = *(const uint32_t*)&sH[r1 + ka];
            a[mt][2] = *(const uint32_t*)&sH[r0 + ka + 8];
            a[mt][3] = *(const uint32_t*)&sH[r1 + ka + 8];
        }
        const __half* wp = &sW[(k0 >> 3) * 512 + q2];
        #pragma unroll
        for (int nt = 0; nt < 8; nt++) {
            const int n = nt * 8 + gi;
            uint32_t b[2];
            b[0] = *(const uint32_t*)&wp[n * 8];
            b[1] = *(const uint32_t*)&wp[n * 8 + 512];
            mma_f16(acc[0][nt], a[0], b);
            mma_f16(acc[1][nt], a[1], b);
        }
    }

    // ---- masked max reduction ----
    #pragma unroll
    for (int nt = 0; nt < 8; nt++) {
        int col = nt * 8 + q2;
        float bA = sB1[col], bB = sB1[col + 1];
        float vA = -FLT_MAX, vB = -FLT_MAX;
        #pragma unroll
        for (int mt = 0; mt < 2; mt++) {
            int r0 = wbase + mt * 16 + gi, r1 = r0 + 8;
            int c0 = sCode[r0], c1 = sCode[r1];
            float f;
            f = (c0 == 0) ? acc[mt][nt][0] + bA : ((c0 == 1) ? 0.f : -FLT_MAX);
            vA = fmaxf(vA, f);
            f = (c1 == 0) ? acc[mt][nt][2] + bA : ((c1 == 1) ? 0.f : -FLT_MAX);
            vA = fmaxf(vA, f);
            f = (c0 == 0) ? acc[mt][nt][1] + bB : ((c0 == 1) ? 0.f : -FLT_MAX);
            vB = fmaxf(vB, f);
            f = (c1 == 0) ? acc[mt][nt][3] + bB : ((c1 == 1) ? 0.f : -FLT_MAX);
            vB = fmaxf(vB, f);
        }
        #pragma unroll
        for (int off = 4; off < 32; off <<= 1) {
            vA = fmaxf(vA, __shfl_xor_sync(0xFFFFFFFFu, vA, off));
            vB = fmaxf(vB, __shfl_xor_sync(0xFFFFFFFFu, vB, off));
        }
        if (gi == 0) {
            sRed[wid * 64 + col]     = vA;
            sRed[wid * 64 + col + 1] = vB;
        }
    }
    __syncthreads();

    // ---- fused scatter: winner-checked direct fp16 write into BEV image ----
    if (tid < 128) {
        int pil = tid >> 6, col = tid & 63;
        const float* r = &sRed[pil * 4 * 64 + col];
        float m = fmaxf(fmaxf(r[0], r[64]), fmaxf(r[128], r[192]));
        int p = blockIdx.x * 2 + pil;               // global pillar index
        int b = p / NPILLAR, pl = p % NPILLAR;
        int ix = __ldg(&idxs[2 * p]), iy = __ldg(&idxs[2 * p + 1]);
        int cell = (b * NX + ix) * NY + iy;
        if (g_winner[cell] == pl)
            g_img[(size_t)cell * F + col] = __float2half_rn(m);
    }
}

// ---------------- 5a) weight prep: fp32 -> fp16, K-blocked [tap][ci/8][co][8] ----
template <int CIN>
__global__ void wprep_kernel(const float* __restrict__ w, __half* __restrict__ wb) {
    int i = blockIdx.x * 256 + threadIdx.x;
    if (i >= 9 * 128 * CIN) return;
    int ci = i % CIN;
    int co = (i / CIN) % 128;
    int tap = i / (CIN * 128);
    float v = w[((size_t)tap * CIN + ci) * C1 + co];
    wb[((size_t)tap * (CIN / 8) + (ci >> 3)) * 1024 + co * 8 + (ci & 7)] = __float2half_rn(v);
}

// ---------------- 5b) 3x3 conv, HMMA fp16, fp16 in, pipelined B ------------------
// CTA: 8x16 px (M=128) x 128 cout. 8 warps: (mwarp 0..3) x (nwarp 0..1).
// FUSE=false: out = fp16 (conv1->g_x1). FUSE=true: tanh+1x1+relu -> fp32 out.
template <int CIN, bool FUSE, int MINB>
__global__ __launch_bounds__(256, MINB) void conv3x3_hmma(
    const __half* __restrict__ in, const __half* __restrict__ wb,
    const float* __restrict__ bias, void* __restrict__ out_,
    const float* __restrict__ w2, const float* __restrict__ b2) {

    constexpr int KP = CIN + 8;         // A stride in halves
    constexpr int SLAB = CIN * 128;     // B slab halves (K-blocked)
    extern __shared__ char smem[];
    __half* sA = (__half*)smem;                                   // 180 * KP
    __half* sB = (__half*)(smem + 180 * KP * 2);                  // 2 * SLAB
    float* sbias = (float*)(smem + (180 * KP + 2 * SLAB) * 2);    // 128
    float* sw2   = sbias + 128;                                   // 128
    float* sRed  = sw2 + 128;                                     // 256

    int tid = threadIdx.x, lane = tid & 31, wid = tid >> 5;
    int bb = blockIdx.z;
    int y0 = blockIdx.y * 8, x0 = blockIdx.x * 16;
    if (tid < 128) {
        sbias[tid] = bias[tid];
        if (FUSE) sw2[tid] = w2[tid];
    }
    uint32_t sA32 = smem_u32(sA), sB32 = smem_u32(sB);
    constexpr int BCP = SLAB / 8;       // 16B chunks per slab

    // prologue: prefetch tap0 B into buffer 0
    for (int t = tid; t < BCP; t += 256) cpasync16(sB32 + t * 16, wb + t * 8);
    CP_COMMIT();

    // ---- stage halo: 180 px x CIN fp16, straight async copy (zero OOB) ----
    constexpr int CH8 = CIN / 8;        // 16B chunks per pixel
    for (int t = tid; t < 180 * CH8; t += 256) {
        int hp = t / CH8, c0 = (t % CH8) * 8;
        int hr = hp / 18, hc = hp % 18;
        int gy = y0 - 1 + hr, gx = x0 - 1 + hc;
        if (gy >= 0 && gy < NX && gx >= 0 && gx < NY)
            cpasync16(sA32 + (hp * KP + c0) * 2,
                      in + (((size_t)bb * NX + gy) * NY + gx) * CIN + c0);
        else
            *(uint4*)&sA[hp * KP + c0] = make_uint4(0, 0, 0, 0);
    }
    CP_COMMIT();

    float acc[2][8][4] = {};
    const int mwarp = wid >> 1, nwarp = wid & 1;
    const int gi = lane >> 2;
    const int q2 = (lane & 3) * 2;
    const int le = lane & 7;            // ldmatrix row within 8x8 tile
    const int lt = lane >> 3;           // ldmatrix tile index 0..3

    // B ldmatrix lane base (per j pair of n-tiles), buffer-relative bytes
    uint32_t bBase[4];
    #pragma unroll
    for (int j = 0; j < 4; j++) {
        int n_lane = nwarp * 64 + j * 16 + (lt >> 1) * 8 + le;
        bBase[j] = (lt & 1) * 2048 + n_lane * 16;
    }

    for (int tap = 0; tap < 9; ++tap) {
        CP_WAIT(0);            // tap's B slab (+halo on tap 0) landed
        __syncthreads();       // + all readers of tap-1 done
        if (tap < 8) {         // prefetch next tap into the other buffer
            const __half* src = wb + (size_t)(tap + 1) * SLAB;
            uint32_t dst = sB32 + ((tap + 1) & 1) * SLAB * 2;
            for (int t = tid; t < BCP; t += 256) cpasync16(dst + t * 16, src + t * 8);
            CP_COMMIT();
        }
        const uint32_t sBc32 = sB32 + (tap & 1) * SLAB * 2;

        const int dy = tap / 3 - 1, dx = tap % 3 - 1;
        uint32_t aBase[2];
        #pragma unroll
        for (int mt = 0; mt < 2; mt++) {
            int hr = mwarp * 2 + mt + 1 + dy;
            int pxrow = hr * 18 + (1 + dx) + le + (lt & 1) * 8;
            aBase[mt] = sA32 + (pxrow * KP + (lt >> 1) * 8) * 2;
        }

        // ---- single segment: A(fp16) x B(fp16) ----
        #pragma unroll 4
        for (int k0 = 0; k0 < CIN; k0 += 16) {
            uint32_t a[2][4];
            ldsm_x4(a[0], aBase[0] + k0 * 2);
            ldsm_x4(a[1], aBase[1] + k0 * 2);
            const uint32_t boff = sBc32 + (k0 >> 3) * 2048;
            #pragma unroll
            for (int j = 0; j < 4; j++) {
                uint32_t b[4];
                ldsm_x4(b, boff + bBase[j]);
                mma_f16(acc[0][2 * j],     a[0], b);
                mma_f16(acc[1][2 * j],     a[1], b);
                mma_f16(acc[0][2 * j + 1], a[0], b + 2);
                mma_f16(acc[1][2 * j + 1], a[1], b + 2);
            }
        }
    }

    if (!FUSE) {
        // ---- epilogue: bias + tanh -> fp16 store (feeds conv2) ----
        __half* out = (__half*)out_;
        #pragma unroll
        for (int mt = 0; mt < 2; mt++) {
            int gy = y0 + mwarp * 2 + mt;
            #pragma unroll
            for (int half = 0; half < 2; half++) {
                int gx = x0 + gi + half * 8;
                __half* op = &out[(((size_t)bb * NX + gy) * NY + gx) * C1];
                #pragma unroll
                for (int nt = 0; nt < 8; nt++) {
                    int n = nwarp * 64 + nt * 8 + q2;
                    __half2 v;
                    v.x = __float2half_rn(tanhf(acc[mt][nt][half * 2 + 0] + sbias[n]));
                    v.y = __float2half_rn(tanhf(acc[mt][nt][half * 2 + 1] + sbias[n + 1]));
                    *(__half2*)&op[n] = v;
                }
            }
        }
    } else {
        // ---- fused epilogue: tanh + 1x1 conv dot + relu -> fp32 out [B,NX,NY] ----
        float* out = (float*)out_;
        float part[2][2] = {};
        #pragma unroll
        for (int mt = 0; mt < 2; mt++)
        #pragma unroll
        for (int half = 0; half < 2; half++)
        #pragma unroll
        for (int nt = 0; nt < 8; nt++) {
            int n = nwarp * 64 + nt * 8 + q2;
            part[mt][half] += tanhf(acc[mt][nt][half * 2 + 0] + sbias[n])     * sw2[n]
                            + tanhf(acc[mt][nt][half * 2 + 1] + sbias[n + 1]) * sw2[n + 1];
        }
        #pragma unroll
        for (int mt = 0; mt < 2; mt++)
        #pragma unroll
        for (int half = 0; half < 2; half++) {
            float v = part[mt][half];
            v += __shfl_xor_sync(0xFFFFFFFFu, v, 1);
            v += __shfl_xor_sync(0xFFFFFFFFu, v, 2);
            if ((lane & 3) == 0) {
                int px = (mwarp * 2 + mt) * 16 + gi + half * 8;
                sRed[px * 2 + nwarp] = v;
            }
        }
        __syncthreads();
        if (tid < 128) {
            float v = sRed[tid * 2] + sRed[tid * 2 + 1] + __ldg(b2);
            int gy = y0 + (tid >> 4), gx = x0 + (tid & 15);
            out[((size_t)bb * NX + gy) * NY + gx] = fmaxf(v, 0.f);
        }
    }
}

// ---------------- host launcher ----------------
extern "C" void kernel_launch(void* const* d_in, const int* in_sizes, int n_in,
                              void* d_out, int out_size) {
    const float* pillars = (const float*)d_in[0];
    const int*   idxs    = (const int*)d_in[1];
    const float* pn_w0 = (const float*)d_in[4];
    const float* pn_b0 = (const float*)d_in[5];
    const float* pn_w1 = (const float*)d_in[6];
    const float* pn_b1 = (const float*)d_in[7];
    const float* cw0   = (const float*)d_in[8];
    const float* cb0   = (const float*)d_in[9];
    const float* cw1   = (const float*)d_in[10];
    const float* cb1   = (const float*)d_in[11];
    const float* cw2   = (const float*)d_in[12];
    const float* cb2   = (const float*)d_in[13];
    float* out = (float*)d_out;

    __half *p_img, *p_x1, *p_wb1, *p_wb2;
    cudaGetSymbolAddress((void**)&p_img, g_img);
    cudaGetSymbolAddress((void**)&p_x1, g_x1);
    cudaGetSymbolAddress((void**)&p_wb1, g_wb1);
    cudaGetSymbolAddress((void**)&p_wb2, g_wb2);

    const int smem1 = (180 * (64 + 8)  + 2 * 64 * 128)  * 2 + 512 * 4;  //  60,736 B
    const int smem2 = (180 * (128 + 8) + 2 * 128 * 128) * 2 + 512 * 4;  // 116,544 B
    const int smemP = 256 * KH * 2 + 8192 + (512 + 64 + 64 + 512) * 4 + 256 * 4;
    cudaFuncSetAttribute((const void*)conv3x3_hmma<64, false, 2>,
                         cudaFuncAttributeMaxDynamicSharedMemorySize, smem1);
    cudaFuncSetAttribute((const void*)conv3x3_hmma<128, true, 1>,
                         cudaFuncAttributeMaxDynamicSharedMemorySize, smem2);
    cudaFuncSetAttribute((const void*)pointnet_hmma,
                         cudaFuncAttributeMaxDynamicSharedMemorySize, smemP);

    zero_kernel<<<2048, 256>>>();
    winner_kernel<<<(BATCH * NPILLAR + 255) / 256, 256>>>(idxs);
    wprep_kernel<64> <<<(9 * 128 * 64 + 255) / 256, 256>>>(cw0, p_wb1);
    wprep_kernel<128><<<(9 * 128 * 128 + 255) / 256, 256>>>(cw1, p_wb2);
    pointnet_hmma<<<BATCH * NPILLAR / 2, 256, smemP>>>(pillars, idxs,
                                                       pn_w0, pn_b0, pn_w1, pn_b1);

    dim3 cgrid(NX / 16, NY / 8, BATCH);   // (15, 30, 4)
    conv3x3_hmma<64, false, 2><<<cgrid, 256, smem1>>>(p_img, p_wb1, cb0, p_x1, nullptr, nullptr);
    conv3x3_hmma<128, true, 1><<<cgrid, 256, smem2>>>(p_x1,  p_wb2, cb1, out,  cw2,     cb2);
}

// round 11
// speedup vs baseline: 6.2625x; 1.0899x over previous
#include <cuda_runtime.h>
#include <cuda_fp16.h>
#include <cstdint>
#include <math.h>
#include <float.h>

#define BATCH 4
#define NPILLAR 5000
#define NPT 100
#define CPT 8
#define NX 240
#define NY 240
#define F 64      // PN_FEAT
#define C1 128    // conv hidden channels

// ---------------- scratch (device globals; no allocation allowed) ----------------
__device__ __align__(16) __half g_img[BATCH * NX * NY * F];    // fp16 BEV image
__device__ __align__(16) __half g_x1 [BATCH * NX * NY * C1];   // fp16 conv1 output
__device__ int g_winner[BATCH * NX * NY];
// fp16 weights, K-blocked layout [tap][k/8][co][8]
__device__ __align__(16) __half g_wb1[9 * 64 * 128];    // conv1 (CIN=64)
__device__ __align__(16) __half g_wb2[9 * 128 * 128];   // conv2 (CIN=128)

// ---------------- HMMA + ldmatrix (plain sm_75/80 PTX) ---------------------------
__device__ __forceinline__ void mma_f16(float* d, const uint32_t* a, const uint32_t* b) {
    asm volatile(
        "mma.sync.aligned.m16n8k16.row.col.f32.f16.f16.f32 "
        "{%0,%1,%2,%3}, {%4,%5,%6,%7}, {%8,%9}, {%0,%1,%2,%3};"
        : "+f"(d[0]), "+f"(d[1]), "+f"(d[2]), "+f"(d[3])
        : "r"(a[0]), "r"(a[1]), "r"(a[2]), "r"(a[3]), "r"(b[0]), "r"(b[1]));
}
__device__ __forceinline__ void mma_f16_k8(float* d, const uint32_t* a, uint32_t b) {
    asm volatile(
        "mma.sync.aligned.m16n8k8.row.col.f32.f16.f16.f32 "
        "{%0,%1,%2,%3}, {%4,%5}, {%6}, {%0,%1,%2,%3};"
        : "+f"(d[0]), "+f"(d[1]), "+f"(d[2]), "+f"(d[3])
        : "r"(a[0]), "r"(a[1]), "r"(b));
}
__device__ __forceinline__ void ldsm_x4(uint32_t* r, uint32_t addr) {
    asm volatile("ldmatrix.sync.aligned.m8n8.x4.shared.b16 {%0,%1,%2,%3}, [%4];"
        : "=r"(r[0]), "=r"(r[1]), "=r"(r[2]), "=r"(r[3]) : "r"(addr));
}
__device__ __forceinline__ uint32_t smem_u32(const void* p) {
    uint32_t a;
    asm("{ .reg .u64 t; cvta.to.shared.u64 t, %1; cvt.u32.u64 %0, t; }" : "=r"(a) : "l"(p));
    return a;
}
__device__ __forceinline__ void cpasync16(uint32_t s, const void* g) {
    asm volatile("cp.async.cg.shared.global [%0], [%1], 16;" :: "r"(s), "l"(g));
}
#define CP_COMMIT() asm volatile("cp.async.commit_group;" ::: "memory")
#define CP_WAIT(n)  asm volatile("cp.async.wait_group %0;" :: "n"(n) : "memory")
// fast tanh (MUFU.TANH)
__device__ __forceinline__ float tanh_fast(float x) {
    float y;
    asm("tanh.approx.f32 %0, %1;" : "=f"(y) : "f"(x));
    return y;
}
__device__ __forceinline__ uint32_t pkh2(float a, float b) {
    __half2 h;
    h.x = __float2half_rn(a);
    h.y = __float2half_rn(b);
    return *(uint32_t*)&h;
}

// ---------------- 1) zero BEV image (fp16) + init winner map ----------------
__global__ void zero_kernel() {
    int tid = blockIdx.x * blockDim.x + threadIdx.x;
    int stride = gridDim.x * blockDim.x;
    const int n8 = BATCH * NX * NY * F / 8;
    uint4 z = make_uint4(0, 0, 0, 0);
    for (int i = tid; i < n8; i += stride)
        reinterpret_cast<uint4*>(g_img)[i] = z;
    for (int i = tid; i < BATCH * NX * NY; i += stride)
        g_winner[i] = -1;
}

// ---------------- 2) duplicate-cell winner (last update wins = max pillar idx) ---
__global__ void winner_kernel(const int* __restrict__ idxs) {
    int p = blockIdx.x * blockDim.x + threadIdx.x;
    if (p >= BATCH * NPILLAR) return;
    int b = p / NPILLAR, pl = p % NPILLAR;
    int ix = idxs[2 * p], iy = idxs[2 * p + 1];
    atomicMax(&g_winner[(b * NX + ix) * NY + iy], pl);
}

// ---------------- 3) pointnet, all-HMMA, register-chained, fused scatter ---------
// layer0: m16n8k8 (X fp16 [row][8]); tanh+repack in registers (D-frag == A-frag);
// layer1: m16n8k16; masked max; winner-checked fp16 write into g_img.
// CTA = 2 pillars = 256 padded rows; warp = 32 rows.
__global__ __launch_bounds__(256) void pointnet_hmma(
    const float* __restrict__ pillars, const int* __restrict__ idxs,
    const float* __restrict__ w0, const float* __restrict__ b0,
    const float* __restrict__ w1, const float* __restrict__ b1) {

    extern __shared__ char sm[];
    __half* sX   = (__half*)sm;                       // 256 * 8  (4096 B)
    __half* sW0h = (__half*)(sm + 4096);              // 64 * 8   (1024 B)  [n][k]
    __half* sW   = (__half*)(sm + 5120);              // 4096     (8192 B)  [kb][n][8]
    float* sB0  = (float*)(sm + 13312);               // 64
    float* sB1  = sB0 + 64;                           // 64
    float* sRed = sB1 + 64;                           // 512
    int*   sCode = (int*)(sRed + 512);                // 256

    int tid = threadIdx.x, lane = tid & 31, wid = tid >> 5;

    if (tid < 64) { sB0[tid] = b0[tid]; sB1[tid] = b1[tid]; }
    for (int i = tid; i < 512; i += 256) {            // w0: [k=8][n=64] -> [n][k]
        int k = i >> 6, n = i & 63;
        sW0h[n * 8 + k] = __float2half_rn(w0[i]);
    }
    for (int i = tid; i < 4096; i += 256) {           // w1: [k=64][n=64] -> K-blocked
        int k = i >> 6, n = i & 63;
        sW[(k >> 3) * 512 + n * 8 + (k & 7)] = __float2half_rn(w1[i]);
    }

    {   // ---- stage X: one thread per row, fp16 [row][8] ----
        int row = tid;
        int pt = row & 127;
        if (pt < NPT) {
            int pil = blockIdx.x * 2 + (row >> 7);
            const float4* px = (const float4*)(pillars + ((size_t)pil * NPT + pt) * CPT);
            float4 A = __ldg(px), B = __ldg(px + 1);
            float x[8] = {A.x, A.y, A.z, A.w, B.x, B.y, B.z, B.w};
            float ss = 0.f;
            #pragma unroll
            for (int k = 0; k < 8; k++) ss += x[k] * x[k];
            sCode[row] = (ss < 1e12f) ? 0 : 1;
            uint4 v;
            v.x = pkh2(x[0], x[1]); v.y = pkh2(x[2], x[3]);
            v.z = pkh2(x[4], x[5]); v.w = pkh2(x[6], x[7]);
            *(uint4*)&sX[row * 8] = v;
        } else {
            sCode[row] = 2;
            *(uint4*)&sX[row * 8] = make_uint4(0, 0, 0, 0);
        }
    }
    __syncthreads();

    const int gi = lane >> 2, q2 = (lane & 3) * 2;
    const int wbase = wid * 32;

    // ---- layer 0: m16n8k8, acc initialized with bias ----
    float acc0[2][8][4];
    uint32_t ax[2][2];
    #pragma unroll
    for (int mt = 0; mt < 2; mt++) {
        ax[mt][0] = *(const uint32_t*)&sX[(wbase + mt * 16 + gi) * 8 + q2];
        ax[mt][1] = *(const uint32_t*)&sX[(wbase + mt * 16 + 8 + gi) * 8 + q2];
    }
    #pragma unroll
    for (int nt = 0; nt < 8; nt++) {
        float bA = sB0[nt * 8 + q2], bB = sB0[nt * 8 + q2 + 1];
        uint32_t b = *(const uint32_t*)&sW0h[(nt * 8 + gi) * 8 + q2];
        #pragma unroll
        for (int mt = 0; mt < 2; mt++) {
            acc0[mt][nt][0] = bA; acc0[mt][nt][1] = bB;
            acc0[mt][nt][2] = bA; acc0[mt][nt][3] = bB;
            mma_f16_k8(acc0[mt][nt], ax[mt], b);
        }
    }

    // ---- tanh + repack: D-fragment (m,n) == A-fragment (m,k) for next MMA ----
    uint32_t aH[2][4][4];
    #pragma unroll
    for (int mt = 0; mt < 2; mt++)
    #pragma unroll
    for (int j = 0; j < 4; j++) {
        aH[mt][j][0] = pkh2(tanh_fast(acc0[mt][2 * j][0]),     tanh_fast(acc0[mt][2 * j][1]));
        aH[mt][j][1] = pkh2(tanh_fast(acc0[mt][2 * j][2]),     tanh_fast(acc0[mt][2 * j][3]));
        aH[mt][j][2] = pkh2(tanh_fast(acc0[mt][2 * j + 1][0]), tanh_fast(acc0[mt][2 * j + 1][1]));
        aH[mt][j][3] = pkh2(tanh_fast(acc0[mt][2 * j + 1][2]), tanh_fast(acc0[mt][2 * j + 1][3]));
    }

    // ---- layer 1: m16n8k16, A from registers ----
    float acc[2][8][4] = {};
    #pragma unroll
    for (int j = 0; j < 4; j++) {
        const __half* wp = &sW[(2 * j) * 512 + q2];
        #pragma unroll
        for (int nt = 0; nt < 8; nt++) {
            const int n = nt * 8 + gi;
            uint32_t b[2];
            b[0] = *(const uint32_t*)&wp[n * 8];
            b[1] = *(const uint32_t*)&wp[n * 8 + 512];
            mma_f16(acc[0][nt], aH[0][j], b);
            mma_f16(acc[1][nt], aH[1][j], b);
        }
    }

    // ---- masked max reduction ----
    #pragma unroll
    for (int nt = 0; nt < 8; nt++) {
        int col = nt * 8 + q2;
        float bA = sB1[col], bB = sB1[col + 1];
        float vA = -FLT_MAX, vB = -FLT_MAX;
        #pragma unroll
        for (int mt = 0; mt < 2; mt++) {
            int r0 = wbase + mt * 16 + gi, r1 = r0 + 8;
            int c0 = sCode[r0], c1 = sCode[r1];
            float f;
            f = (c0 == 0) ? acc[mt][nt][0] + bA : ((c0 == 1) ? 0.f : -FLT_MAX);
            vA = fmaxf(vA, f);
            f = (c1 == 0) ? acc[mt][nt][2] + bA : ((c1 == 1) ? 0.f : -FLT_MAX);
            vA = fmaxf(vA, f);
            f = (c0 == 0) ? acc[mt][nt][1] + bB : ((c0 == 1) ? 0.f : -FLT_MAX);
            vB = fmaxf(vB, f);
            f = (c1 == 0) ? acc[mt][nt][3] + bB : ((c1 == 1) ? 0.f : -FLT_MAX);
            vB = fmaxf(vB, f);
        }
        #pragma unroll
        for (int off = 4; off < 32; off <<= 1) {
            vA = fmaxf(vA, __shfl_xor_sync(0xFFFFFFFFu, vA, off));
            vB = fmaxf(vB, __shfl_xor_sync(0xFFFFFFFFu, vB, off));
        }
        if (gi == 0) {
            sRed[wid * 64 + col]     = vA;
            sRed[wid * 64 + col + 1] = vB;
        }
    }
    __syncthreads();

    // ---- fused scatter: winner-checked direct fp16 write into BEV image ----
    if (tid < 128) {
        int pil = tid >> 6, col = tid & 63;
        const float* r = &sRed[pil * 4 * 64 + col];
        float m = fmaxf(fmaxf(r[0], r[64]), fmaxf(r[128], r[192]));
        int p = blockIdx.x * 2 + pil;
        int b = p / NPILLAR, pl = p % NPILLAR;
        int ix = __ldg(&idxs[2 * p]), iy = __ldg(&idxs[2 * p + 1]);
        int cell = (b * NX + ix) * NY + iy;
        if (g_winner[cell] == pl)
            g_img[(size_t)cell * F + col] = __float2half_rn(m);
    }
}

// ---------------- 5a) weight prep: fp32 -> fp16, K-blocked [tap][ci/8][co][8] ----
template <int CIN>
__global__ void wprep_kernel(const float* __restrict__ w, __half* __restrict__ wb) {
    int i = blockIdx.x * 256 + threadIdx.x;
    if (i >= 9 * 128 * CIN) return;
    int ci = i % CIN;
    int co = (i / CIN) % 128;
    int tap = i / (CIN * 128);
    float v = w[((size_t)tap * CIN + ci) * C1 + co];
    wb[((size_t)tap * (CIN / 8) + (ci >> 3)) * 1024 + co * 8 + (ci & 7)] = __float2half_rn(v);
}

// ---------------- 5b) 3x3 conv, HMMA fp16, fp16 in, pipelined B ------------------
template <int CIN, bool FUSE, int MINB>
__global__ __launch_bounds__(256, MINB) void conv3x3_hmma(
    const __half* __restrict__ in, const __half* __restrict__ wb,
    const float* __restrict__ bias, void* __restrict__ out_,
    const float* __restrict__ w2, const float* __restrict__ b2) {

    constexpr int KP = CIN + 8;         // A stride in halves
    constexpr int SLAB = CIN * 128;     // B slab halves (K-blocked)
    extern __shared__ char smem[];
    __half* sA = (__half*)smem;                                   // 180 * KP
    __half* sB = (__half*)(smem + 180 * KP * 2);                  // 2 * SLAB
    float* sbias = (float*)(smem + (180 * KP + 2 * SLAB) * 2);    // 128
    float* sw2   = sbias + 128;                                   // 128
    float* sRed  = sw2 + 128;                                     // 256

    int tid = threadIdx.x, lane = tid & 31, wid = tid >> 5;
    int bb = blockIdx.z;
    int y0 = blockIdx.y * 8, x0 = blockIdx.x * 16;
    if (tid < 128) {
        sbias[tid] = bias[tid];
        if (FUSE) sw2[tid] = w2[tid];
    }
    uint32_t sA32 = smem_u32(sA), sB32 = smem_u32(sB);
    constexpr int BCP = SLAB / 8;

    // prologue: prefetch tap0 B into buffer 0
    for (int t = tid; t < BCP; t += 256) cpasync16(sB32 + t * 16, wb + t * 8);
    CP_COMMIT();

    // ---- stage halo: 180 px x CIN fp16, straight async copy (zero OOB) ----
    constexpr int CH8 = CIN / 8;
    for (int t = tid; t < 180 * CH8; t += 256) {
        int hp = t / CH8, c0 = (t % CH8) * 8;
        int hr = hp / 18, hc = hp % 18;
        int gy = y0 - 1 + hr, gx = x0 - 1 + hc;
        if (gy >= 0 && gy < NX && gx >= 0 && gx < NY)
            cpasync16(sA32 + (hp * KP + c0) * 2,
                      in + (((size_t)bb * NX + gy) * NY + gx) * CIN + c0);
        else
            *(uint4*)&sA[hp * KP + c0] = make_uint4(0, 0, 0, 0);
    }
    CP_COMMIT();

    float acc[2][8][4] = {};
    const int mwarp = wid >> 1, nwarp = wid & 1;
    const int gi = lane >> 2;
    const int q2 = (lane & 3) * 2;
    const int le = lane & 7;
    const int lt = lane >> 3;

    uint32_t bBase[4];
    #pragma unroll
    for (int j = 0; j < 4; j++) {
        int n_lane = nwarp * 64 + j * 16 + (lt >> 1) * 8 + le;
        bBase[j] = (lt & 1) * 2048 + n_lane * 16;
    }

    for (int tap = 0; tap < 9; ++tap) {
        CP_WAIT(0);
        __syncthreads();
        if (tap < 8) {
            const __half* src = wb + (size_t)(tap + 1) * SLAB;
            uint32_t dst = sB32 + ((tap + 1) & 1) * SLAB * 2;
            for (int t = tid; t < BCP; t += 256) cpasync16(dst + t * 16, src + t * 8);
            CP_COMMIT();
        }
        const uint32_t sBc32 = sB32 + (tap & 1) * SLAB * 2;

        const int dy = tap / 3 - 1, dx = tap % 3 - 1;
        uint32_t aBase[2];
        #pragma unroll
        for (int mt = 0; mt < 2; mt++) {
            int hr = mwarp * 2 + mt + 1 + dy;
            int pxrow = hr * 18 + (1 + dx) + le + (lt & 1) * 8;
            aBase[mt] = sA32 + (pxrow * KP + (lt >> 1) * 8) * 2;
        }

        #pragma unroll 4
        for (int k0 = 0; k0 < CIN; k0 += 16) {
            uint32_t a[2][4];
            ldsm_x4(a[0], aBase[0] + k0 * 2);
            ldsm_x4(a[1], aBase[1] + k0 * 2);
            const uint32_t boff = sBc32 + (k0 >> 3) * 2048;
            #pragma unroll
            for (int j = 0; j < 4; j++) {
                uint32_t b[4];
                ldsm_x4(b, boff + bBase[j]);
                mma_f16(acc[0][2 * j],     a[0], b);
                mma_f16(acc[1][2 * j],     a[1], b);
                mma_f16(acc[0][2 * j + 1], a[0], b + 2);
                mma_f16(acc[1][2 * j + 1], a[1], b + 2);
            }
        }
    }

    if (!FUSE) {
        // ---- epilogue: bias + fast tanh -> fp16 store (feeds conv2) ----
        __half* out = (__half*)out_;
        #pragma unroll
        for (int mt = 0; mt < 2; mt++) {
            int gy = y0 + mwarp * 2 + mt;
            #pragma unroll
            for (int half = 0; half < 2; half++) {
                int gx = x0 + gi + half * 8;
                __half* op = &out[(((size_t)bb * NX + gy) * NY + gx) * C1];
                #pragma unroll
                for (int nt = 0; nt < 8; nt++) {
                    int n = nwarp * 64 + nt * 8 + q2;
                    __half2 v;
                    v.x = __float2half_rn(tanh_fast(acc[mt][nt][half * 2 + 0] + sbias[n]));
                    v.y = __float2half_rn(tanh_fast(acc[mt][nt][half * 2 + 1] + sbias[n + 1]));
                    *(__half2*)&op[n] = v;
                }
            }
        }
    } else {
        // ---- fused epilogue: fast tanh + 1x1 conv dot + relu -> fp32 out ----
        float* out = (float*)out_;
        float part[2][2] = {};
        #pragma unroll
        for (int mt = 0; mt < 2; mt++)
        #pragma unroll
        for (int half = 0; half < 2; half++)
        #pragma unroll
        for (int nt = 0; nt < 8; nt++) {
            int n = nwarp * 64 + nt * 8 + q2;
            part[mt][half] += tanh_fast(acc[mt][nt][half * 2 + 0] + sbias[n])     * sw2[n]
                            + tanh_fast(acc[mt][nt][half * 2 + 1] + sbias[n + 1]) * sw2[n + 1];
        }
        #pragma unroll
        for (int mt = 0; mt < 2; mt++)
        #pragma unroll
        for (int half = 0; half < 2; half++) {
            float v = part[mt][half];
            v += __shfl_xor_sync(0xFFFFFFFFu, v, 1);
            v += __shfl_xor_sync(0xFFFFFFFFu, v, 2);
            if ((lane & 3) == 0) {
                int px = (mwarp * 2 + mt) * 16 + gi + half * 8;
                sRed[px * 2 + nwarp] = v;
            }
        }
        __syncthreads();
        if (tid < 128) {
            float v = sRed[tid * 2] + sRed[tid * 2 + 1] + __ldg(b2);
            int gy = y0 + (tid >> 4), gx = x0 + (tid & 15);
            out[((size_t)bb * NX + gy) * NY + gx] = fmaxf(v, 0.f);
        }
    }
}

// ---------------- host launcher ----------------
extern "C" void kernel_launch(void* const* d_in, const int* in_sizes, int n_in,
                              void* d_out, int out_size) {
    const float* pillars = (const float*)d_in[0];
    const int*   idxs    = (const int*)d_in[1];
    const float* pn_w0 = (const float*)d_in[4];
    const float* pn_b0 = (const float*)d_in[5];
    const float* pn_w1 = (const float*)d_in[6];
    const float* pn_b1 = (const float*)d_in[7];
    const float* cw0   = (const float*)d_in[8];
    const float* cb0   = (const float*)d_in[9];
    const float* cw1   = (const float*)d_in[10];
    const float* cb1   = (const float*)d_in[11];
    const float* cw2   = (const float*)d_in[12];
    const float* cb2   = (const float*)d_in[13];
    float* out = (float*)d_out;

    __half *p_img, *p_x1, *p_wb1, *p_wb2;
    cudaGetSymbolAddress((void**)&p_img, g_img);
    cudaGetSymbolAddress((void**)&p_x1, g_x1);
    cudaGetSymbolAddress((void**)&p_wb1, g_wb1);
    cudaGetSymbolAddress((void**)&p_wb2, g_wb2);

    const int smem1 = (180 * (64 + 8)  + 2 * 64 * 128)  * 2 + 512 * 4;  //  60,736 B
    const int smem2 = (180 * (128 + 8) + 2 * 128 * 128) * 2 + 512 * 4;  // 116,544 B
    const int smemP = 13312 + (64 + 64 + 512) * 4 + 256 * 4;            //  ~17 KB
    cudaFuncSetAttribute((const void*)conv3x3_hmma<64, false, 2>,
                         cudaFuncAttributeMaxDynamicSharedMemorySize, smem1);
    cudaFuncSetAttribute((const void*)conv3x3_hmma<128, true, 1>,
                         cudaFuncAttributeMaxDynamicSharedMemorySize, smem2);

    zero_kernel<<<2048, 256>>>();
    winner_kernel<<<(BATCH * NPILLAR + 255) / 256, 256>>>(idxs);
    wprep_kernel<64> <<<(9 * 128 * 64 + 255) / 256, 256>>>(cw0, p_wb1);
    wprep_kernel<128><<<(9 * 128 * 128 + 255) / 256, 256>>>(cw1, p_wb2);
    pointnet_hmma<<<BATCH * NPILLAR / 2, 256, smemP>>>(pillars, idxs,
                                                       pn_w0, pn_b0, pn_w1, pn_b1);

    dim3 cgrid(NX / 16, NY / 8, BATCH);   // (15, 30, 4)
    conv3x3_hmma<64, false, 2><<<cgrid, 256, smem1>>>(p_img, p_wb1, cb0, p_x1, nullptr, nullptr);
    conv3x3_hmma<128, true, 1><<<cgrid, 256, smem2>>>(p_x1,  p_wb2, cb1, out,  cw2,     cb2);
}

// round 12
// speedup vs baseline: 6.7112x; 1.0716x over previous
#include <cuda_runtime.h>
#include <cuda_fp16.h>
#include <cstdint>
#include <math.h>
#include <float.h>

#define BATCH 4
#define NPILLAR 5000
#define NPT 100
#define CPT 8
#define NX 240
#define NY 240
#define F 64      // PN_FEAT
#define C1 128    // conv hidden channels

// ---------------- scratch (device globals; no allocation allowed) ----------------
__device__ __align__(16) __half g_img[BATCH * NX * NY * F];    // fp16 BEV image
__device__ __align__(16) __half g_x1 [BATCH * NX * NY * C1];   // fp16 conv1 output
__device__ int g_winner[BATCH * NX * NY];
// fp16 weights, K-blocked layout [tap][k/8][co][8]
__device__ __align__(16) __half g_wb1[9 * 64 * 128];    // conv1 (CIN=64)
__device__ __align__(16) __half g_wb2[9 * 128 * 128];   // conv2 (CIN=128)

// ---------------- HMMA + ldmatrix (plain sm_75/80 PTX) ---------------------------
__device__ __forceinline__ void mma_f16(float* d, const uint32_t* a, const uint32_t* b) {
    asm volatile(
        "mma.sync.aligned.m16n8k16.row.col.f32.f16.f16.f32 "
        "{%0,%1,%2,%3}, {%4,%5,%6,%7}, {%8,%9}, {%0,%1,%2,%3};"
        : "+f"(d[0]), "+f"(d[1]), "+f"(d[2]), "+f"(d[3])
        : "r"(a[0]), "r"(a[1]), "r"(a[2]), "r"(a[3]), "r"(b[0]), "r"(b[1]));
}
__device__ __forceinline__ void mma_f16_k8(float* d, const uint32_t* a, uint32_t b) {
    asm volatile(
        "mma.sync.aligned.m16n8k8.row.col.f32.f16.f16.f32 "
        "{%0,%1,%2,%3}, {%4,%5}, {%6}, {%0,%1,%2,%3};"
        : "+f"(d[0]), "+f"(d[1]), "+f"(d[2]), "+f"(d[3])
        : "r"(a[0]), "r"(a[1]), "r"(b));
}
__device__ __forceinline__ void ldsm_x4(uint32_t* r, uint32_t addr) {
    asm volatile("ldmatrix.sync.aligned.m8n8.x4.shared.b16 {%0,%1,%2,%3}, [%4];"
        : "=r"(r[0]), "=r"(r[1]), "=r"(r[2]), "=r"(r[3]) : "r"(addr));
}
__device__ __forceinline__ uint32_t smem_u32(const void* p) {
    uint32_t a;
    asm("{ .reg .u64 t; cvta.to.shared.u64 t, %1; cvt.u32.u64 %0, t; }" : "=r"(a) : "l"(p));
    return a;
}
__device__ __forceinline__ void cpasync16(uint32_t s, const void* g) {
    asm volatile("cp.async.cg.shared.global [%0], [%1], 16;" :: "r"(s), "l"(g));
}
#define CP_COMMIT() asm volatile("cp.async.commit_group;" ::: "memory")
#define CP_WAIT(n)  asm volatile("cp.async.wait_group %0;" :: "n"(n) : "memory")
__device__ __forceinline__ float tanh_fast(float x) {
    float y;
    asm("tanh.approx.f32 %0, %1;" : "=f"(y) : "f"(x));
    return y;
}
__device__ __forceinline__ uint32_t pkh2(float a, float b) {
    __half2 h;
    h.x = __float2half_rn(a);
    h.y = __float2half_rn(b);
    return *(uint32_t*)&h;
}

// ---------------- 1) prep: zero BEV image + init winner + conv weight prep -------
__global__ void prep_kernel(const float* __restrict__ cw0, const float* __restrict__ cw1) {
    int tid = blockIdx.x * blockDim.x + threadIdx.x;
    int stride = gridDim.x * blockDim.x;
    const int n8 = BATCH * NX * NY * F / 8;
    uint4 z = make_uint4(0, 0, 0, 0);
    for (int i = tid; i < n8; i += stride)
        reinterpret_cast<uint4*>(g_img)[i] = z;
    for (int i = tid; i < BATCH * NX * NY; i += stride)
        g_winner[i] = -1;
    for (int i = tid; i < 9 * 128 * 64; i += stride) {      // conv1 weights
        int ci = i % 64, co = (i / 64) % 128, tap = i / (64 * 128);
        float v = cw0[((size_t)tap * 64 + ci) * C1 + co];
        g_wb1[((size_t)tap * 8 + (ci >> 3)) * 1024 + co * 8 + (ci & 7)] = __float2half_rn(v);
    }
    for (int i = tid; i < 9 * 128 * 128; i += stride) {     // conv2 weights
        int ci = i % 128, co = (i / 128) % 128, tap = i / (128 * 128);
        float v = cw1[((size_t)tap * 128 + ci) * C1 + co];
        g_wb2[((size_t)tap * 16 + (ci >> 3)) * 1024 + co * 8 + (ci & 7)] = __float2half_rn(v);
    }
}

// ---------------- 2) duplicate-cell winner (last update wins = max pillar idx) ---
__global__ void winner_kernel(const int* __restrict__ idxs) {
    int p = blockIdx.x * blockDim.x + threadIdx.x;
    if (p >= BATCH * NPILLAR) return;
    int b = p / NPILLAR, pl = p % NPILLAR;
    int ix = idxs[2 * p], iy = idxs[2 * p + 1];
    atomicMax(&g_winner[(b * NX + ix) * NY + iy], pl);
}

// ---------------- 3) pointnet, all-HMMA, 8 pillars/CTA, fused scatter ------------
__global__ __launch_bounds__(256) void pointnet_hmma(
    const float* __restrict__ pillars, const int* __restrict__ idxs,
    const float* __restrict__ w0, const float* __restrict__ b0,
    const float* __restrict__ w1, const float* __restrict__ b1) {

    extern __shared__ char sm[];
    __half* sX   = (__half*)sm;                       // 256 * 8  (4096 B)
    __half* sW0h = (__half*)(sm + 4096);              // 64 * 8   (1024 B)  [n][k]
    __half* sW   = (__half*)(sm + 5120);              // 4096     (8192 B)  [kb][n][8]
    float* sB0  = (float*)(sm + 13312);               // 64
    float* sB1  = sB0 + 64;                           // 64
    float* sRed = sB1 + 64;                           // 512
    int*   sCode = (int*)(sRed + 512);                // 256

    int tid = threadIdx.x, lane = tid & 31, wid = tid >> 5;

    if (tid < 64) { sB0[tid] = b0[tid]; sB1[tid] = b1[tid]; }
    for (int i = tid; i < 512; i += 256) {            // w0: [k=8][n=64] -> [n][k]
        int k = i >> 6, n = i & 63;
        sW0h[n * 8 + k] = __float2half_rn(w0[i]);
    }
    for (int i = tid; i < 4096; i += 256) {           // w1 -> K-blocked
        int k = i >> 6, n = i & 63;
        sW[(k >> 3) * 512 + n * 8 + (k & 7)] = __float2half_rn(w1[i]);
    }
    __syncthreads();

    const int gi = lane >> 2, q2 = (lane & 3) * 2;
    const int wbase = wid * 32;

    for (int it = 0; it < 4; ++it) {
        const int pbase = blockIdx.x * 8 + it * 2;

        {   // ---- stage X: one thread per row, fp16 [row][8] ----
            int row = tid;
            int pt = row & 127;
            if (pt < NPT) {
                int pil = pbase + (row >> 7);
                const float4* px = (const float4*)(pillars + ((size_t)pil * NPT + pt) * CPT);
                float4 A = __ldg(px), B = __ldg(px + 1);
                float x[8] = {A.x, A.y, A.z, A.w, B.x, B.y, B.z, B.w};
                float ss = 0.f;
                #pragma unroll
                for (int k = 0; k < 8; k++) ss += x[k] * x[k];
                sCode[row] = (ss < 1e12f) ? 0 : 1;
                uint4 v;
                v.x = pkh2(x[0], x[1]); v.y = pkh2(x[2], x[3]);
                v.z = pkh2(x[4], x[5]); v.w = pkh2(x[6], x[7]);
                *(uint4*)&sX[row * 8] = v;
            } else {
                sCode[row] = 2;
                *(uint4*)&sX[row * 8] = make_uint4(0, 0, 0, 0);
            }
        }
        __syncthreads();

        // ---- layer 0: m16n8k8, acc initialized with bias ----
        float acc0[2][8][4];
        uint32_t ax[2][2];
        #pragma unroll
        for (int mt = 0; mt < 2; mt++) {
            ax[mt][0] = *(const uint32_t*)&sX[(wbase + mt * 16 + gi) * 8 + q2];
            ax[mt][1] = *(const uint32_t*)&sX[(wbase + mt * 16 + 8 + gi) * 8 + q2];
        }
        #pragma unroll
        for (int nt = 0; nt < 8; nt++) {
            float bA = sB0[nt * 8 + q2], bB = sB0[nt * 8 + q2 + 1];
            uint32_t b = *(const uint32_t*)&sW0h[(nt * 8 + gi) * 8 + q2];
            #pragma unroll
            for (int mt = 0; mt < 2; mt++) {
                acc0[mt][nt][0] = bA; acc0[mt][nt][1] = bB;
                acc0[mt][nt][2] = bA; acc0[mt][nt][3] = bB;
                mma_f16_k8(acc0[mt][nt], ax[mt], b);
            }
        }

        // ---- tanh + repack in registers (D-frag == A-frag) ----
        uint32_t aH[2][4][4];
        #pragma unroll
        for (int mt = 0; mt < 2; mt++)
        #pragma unroll
        for (int j = 0; j < 4; j++) {
            aH[mt][j][0] = pkh2(tanh_fast(acc0[mt][2 * j][0]),     tanh_fast(acc0[mt][2 * j][1]));
            aH[mt][j][1] = pkh2(tanh_fast(acc0[mt][2 * j][2]),     tanh_fast(acc0[mt][2 * j][3]));
            aH[mt][j][2] = pkh2(tanh_fast(acc0[mt][2 * j + 1][0]), tanh_fast(acc0[mt][2 * j + 1][1]));
            aH[mt][j][3] = pkh2(tanh_fast(acc0[mt][2 * j + 1][2]), tanh_fast(acc0[mt][2 * j + 1][3]));
        }

        // ---- layer 1: m16n8k16, A from registers ----
        float acc[2][8][4] = {};
        #pragma unroll
        for (int j = 0; j < 4; j++) {
            const __half* wp = &sW[(2 * j) * 512 + q2];
            #pragma unroll
            for (int nt = 0; nt < 8; nt++) {
                const int n = nt * 8 + gi;
                uint32_t b[2];
                b[0] = *(const uint32_t*)&wp[n * 8];
                b[1] = *(const uint32_t*)&wp[n * 8 + 512];
                mma_f16(acc[0][nt], aH[0][j], b);
                mma_f16(acc[1][nt], aH[1][j], b);
            }
        }

        // ---- masked max reduction ----
        #pragma unroll
        for (int nt = 0; nt < 8; nt++) {
            int col = nt * 8 + q2;
            float bA = sB1[col], bB = sB1[col + 1];
            float vA = -FLT_MAX, vB = -FLT_MAX;
            #pragma unroll
            for (int mt = 0; mt < 2; mt++) {
                int r0 = wbase + mt * 16 + gi, r1 = r0 + 8;
                int c0 = sCode[r0], c1 = sCode[r1];
                float f;
                f = (c0 == 0) ? acc[mt][nt][0] + bA : ((c0 == 1) ? 0.f : -FLT_MAX);
                vA = fmaxf(vA, f);
                f = (c1 == 0) ? acc[mt][nt][2] + bA : ((c1 == 1) ? 0.f : -FLT_MAX);
                vA = fmaxf(vA, f);
                f = (c0 == 0) ? acc[mt][nt][1] + bB : ((c0 == 1) ? 0.f : -FLT_MAX);
                vB = fmaxf(vB, f);
                f = (c1 == 0) ? acc[mt][nt][3] + bB : ((c1 == 1) ? 0.f : -FLT_MAX);
                vB = fmaxf(vB, f);
            }
            #pragma unroll
            for (int off = 4; off < 32; off <<= 1) {
                vA = fmaxf(vA, __shfl_xor_sync(0xFFFFFFFFu, vA, off));
                vB = fmaxf(vB, __shfl_xor_sync(0xFFFFFFFFu, vB, off));
            }
            if (gi == 0) {
                sRed[wid * 64 + col]     = vA;
                sRed[wid * 64 + col + 1] = vB;
            }
        }
        __syncthreads();

        // ---- fused scatter: winner-checked direct fp16 write into BEV image ----
        if (tid < 128) {
            int pil = tid >> 6, col = tid & 63;
            const float* r = &sRed[pil * 4 * 64 + col];
            float m = fmaxf(fmaxf(r[0], r[64]), fmaxf(r[128], r[192]));
            int p = pbase + pil;
            int b = p / NPILLAR, pl = p % NPILLAR;
            int ix = __ldg(&idxs[2 * p]), iy = __ldg(&idxs[2 * p + 1]);
            int cell = (b * NX + ix) * NY + iy;
            if (g_winner[cell] == pl)
                g_img[(size_t)cell * F + col] = __float2half_rn(m);
        }
    }
}

// ---------------- 5) 3x3 conv, HMMA fp16, 3-buffer half-tap B ring ---------------
// CTA: 8x16 px (M=128) x 128 cout. 8 warps: (mwarp 0..3) x (nwarp 0..1).
// B staged per HALF-tap (CIN/2 x 128 cout) in a 3-slot ring -> conv2 fits 2 CTA/SM.
template <int CIN, bool FUSE>
__global__ __launch_bounds__(256, 2) void conv3x3_hmma(
    const __half* __restrict__ in, const __half* __restrict__ wb,
    const float* __restrict__ bias, void* __restrict__ out_,
    const float* __restrict__ w2, const float* __restrict__ b2) {

    constexpr int KP = CIN + 8;             // A stride in halves
    constexpr int HSLAB = CIN * 64;         // half-tap slab halves (K-blocked)
    constexpr int HB = HSLAB * 2;           // slab bytes
    constexpr int NH = 18;                  // 9 taps x 2 halves
    extern __shared__ char smem[];
    __half* sA = (__half*)smem;                                   // 180 * KP
    __half* sB = (__half*)(smem + 180 * KP * 2);                  // 3 * HSLAB
    float* sbias = (float*)(smem + (180 * KP + 3 * HSLAB) * 2);   // 128
    float* sw2   = sbias + 128;                                   // 128
    float* sRed  = sw2 + 128;                                     // 256

    int tid = threadIdx.x, lane = tid & 31, wid = tid >> 5;
    int bb = blockIdx.z;
    int y0 = blockIdx.y * 8, x0 = blockIdx.x * 16;
    if (tid < 128) {
        sbias[tid] = bias[tid];
        if (FUSE) sw2[tid] = w2[tid];
    }
    uint32_t sA32 = smem_u32(sA), sB32 = smem_u32(sB);
    constexpr int BCPH = HSLAB / 8;         // 16B chunks per half slab

    // ---- prologue: halo + half0 (group), half1 (group) ----
    constexpr int CH8 = CIN / 8;
    for (int t = tid; t < 180 * CH8; t += 256) {
        int hp = t / CH8, c0 = (t % CH8) * 8;
        int hr = hp / 18, hc = hp % 18;
        int gy = y0 - 1 + hr, gx = x0 - 1 + hc;
        if (gy >= 0 && gy < NX && gx >= 0 && gx < NY)
            cpasync16(sA32 + (hp * KP + c0) * 2,
                      in + (((size_t)bb * NX + gy) * NY + gx) * CIN + c0);
        else
            *(uint4*)&sA[hp * KP + c0] = make_uint4(0, 0, 0, 0);
    }
    for (int t = tid; t < BCPH; t += 256) cpasync16(sB32 + t * 16, wb + t * 8);
    CP_COMMIT();                            // group: halo + half0
    for (int t = tid; t < BCPH; t += 256) cpasync16(sB32 + HB + t * 16, wb + HSLAB + t * 8);
    CP_COMMIT();                            // group: half1

    float acc[2][8][4] = {};
    const int mwarp = wid >> 1, nwarp = wid & 1;
    const int gi = lane >> 2;
    const int q2 = (lane & 3) * 2;
    const int le = lane & 7;
    const int lt = lane >> 3;

    uint32_t bBase[4];
    #pragma unroll
    for (int j = 0; j < 4; j++) {
        int n_lane = nwarp * 64 + j * 16 + (lt >> 1) * 8 + le;
        bBase[j] = (lt & 1) * 2048 + n_lane * 16;
    }

    for (int h = 0; h < NH; ++h) {
        __syncthreads();                    // all consumers of half h-1 done
        if (h + 2 < NH) {                   // prefetch half h+2 into ring slot
            const __half* src = wb + (size_t)(h + 2) * HSLAB;
            uint32_t dst = sB32 + ((h + 2) % 3) * HB;
            for (int t = tid; t < BCPH; t += 256) cpasync16(dst + t * 16, src + t * 8);
            CP_COMMIT();
        }
        if (h + 2 < NH)      CP_WAIT(2);    // half h landed (h+1, h+2 may pend)
        else if (h + 1 < NH) CP_WAIT(1);
        else                 CP_WAIT(0);
        __syncthreads();

        const int tap = h >> 1, kh = h & 1;
        const uint32_t sBc32 = sB32 + (h % 3) * HB;
        const int dy = tap / 3 - 1, dx = tap % 3 - 1;
        uint32_t aBase[2];
        #pragma unroll
        for (int mt = 0; mt < 2; mt++) {
            int hr = mwarp * 2 + mt + 1 + dy;
            int pxrow = hr * 18 + (1 + dx) + le + (lt & 1) * 8;
            aBase[mt] = sA32 + (pxrow * KP + (lt >> 1) * 8 + kh * (CIN / 2)) * 2;
        }

        #pragma unroll
        for (int k0 = 0; k0 < CIN / 2; k0 += 16) {
            uint32_t a[2][4];
            ldsm_x4(a[0], aBase[0] + k0 * 2);
            ldsm_x4(a[1], aBase[1] + k0 * 2);
            const uint32_t boff = sBc32 + (k0 >> 3) * 2048;
            #pragma unroll
            for (int j = 0; j < 4; j++) {
                uint32_t b[4];
                ldsm_x4(b, boff + bBase[j]);
                mma_f16(acc[0][2 * j],     a[0], b);
                mma_f16(acc[1][2 * j],     a[1], b);
                mma_f16(acc[0][2 * j + 1], a[0], b + 2);
                mma_f16(acc[1][2 * j + 1], a[1], b + 2);
            }
        }
    }

    if (!FUSE) {
        // ---- epilogue: bias + fast tanh -> fp16 store (feeds conv2) ----
        __half* out = (__half*)out_;
        #pragma unroll
        for (int mt = 0; mt < 2; mt++) {
            int gy = y0 + mwarp * 2 + mt;
            #pragma unroll
            for (int half = 0; half < 2; half++) {
                int gx = x0 + gi + half * 8;
                __half* op = &out[(((size_t)bb * NX + gy) * NY + gx) * C1];
                #pragma unroll
                for (int nt = 0; nt < 8; nt++) {
                    int n = nwarp * 64 + nt * 8 + q2;
                    __half2 v;
                    v.x = __float2half_rn(tanh_fast(acc[mt][nt][half * 2 + 0] + sbias[n]));
                    v.y = __float2half_rn(tanh_fast(acc[mt][nt][half * 2 + 1] + sbias[n + 1]));
                    *(__half2*)&op[n] = v;
                }
            }
        }
    } else {
        // ---- fused epilogue: fast tanh + 1x1 conv dot + relu -> fp32 out ----
        float* out = (float*)out_;
        float part[2][2] = {};
        #pragma unroll
        for (int mt = 0; mt < 2; mt++)
        #pragma unroll
        for (int half = 0; half < 2; half++)
        #pragma unroll
        for (int nt = 0; nt < 8; nt++) {
            int n = nwarp * 64 + nt * 8 + q2;
            part[mt][half] += tanh_fast(acc[mt][nt][half * 2 + 0] + sbias[n])     * sw2[n]
                            + tanh_fast(acc[mt][nt][half * 2 + 1] + sbias[n + 1]) * sw2[n + 1];
        }
        #pragma unroll
        for (int mt = 0; mt < 2; mt++)
        #pragma unroll
        for (int half = 0; half < 2; half++) {
            float v = part[mt][half];
            v += __shfl_xor_sync(0xFFFFFFFFu, v, 1);
            v += __shfl_xor_sync(0xFFFFFFFFu, v, 2);
            if ((lane & 3) == 0) {
                int px = (mwarp * 2 + mt) * 16 + gi + half * 8;
                sRed[px * 2 + nwarp] = v;
            }
        }
        __syncthreads();
        if (tid < 128) {
            float v = sRed[tid * 2] + sRed[tid * 2 + 1] + __ldg(b2);
            int gy = y0 + (tid >> 4), gx = x0 + (tid & 15);
            out[((size_t)bb * NX + gy) * NY + gx] = fmaxf(v, 0.f);
        }
    }
}

// ---------------- host launcher ----------------
extern "C" void kernel_launch(void* const* d_in, const int* in_sizes, int n_in,
                              void* d_out, int out_size) {
    const float* pillars = (const float*)d_in[0];
    const int*   idxs    = (const int*)d_in[1];
    const float* pn_w0 = (const float*)d_in[4];
    const float* pn_b0 = (const float*)d_in[5];
    const float* pn_w1 = (const float*)d_in[6];
    const float* pn_b1 = (const float*)d_in[7];
    const float* cw0   = (const float*)d_in[8];
    const float* cb0   = (const float*)d_in[9];
    const float* cw1   = (const float*)d_in[10];
    const float* cb1   = (const float*)d_in[11];
    const float* cw2   = (const float*)d_in[12];
    const float* cb2   = (const float*)d_in[13];
    float* out = (float*)d_out;

    __half *p_img, *p_x1, *p_wb1, *p_wb2;
    cudaGetSymbolAddress((void**)&p_img, g_img);
    cudaGetSymbolAddress((void**)&p_x1, g_x1);
    cudaGetSymbolAddress((void**)&p_wb1, g_wb1);
    cudaGetSymbolAddress((void**)&p_wb2, g_wb2);

    const int smem1 = (180 * (64 + 8)  + 3 * 64 * 64)  * 2 + 512 * 4;   //  52,544 B
    const int smem2 = (180 * (128 + 8) + 3 * 128 * 64) * 2 + 512 * 4;   // 100,160 B
    const int smemP = 13312 + (64 + 64 + 512) * 4 + 256 * 4;            //  ~17 KB
    cudaFuncSetAttribute((const void*)conv3x3_hmma<64, false>,
                         cudaFuncAttributeMaxDynamicSharedMemorySize, smem1);
    cudaFuncSetAttribute((const void*)conv3x3_hmma<128, true>,
                         cudaFuncAttributeMaxDynamicSharedMemorySize, smem2);

    prep_kernel<<<1024, 256>>>(cw0, cw1);
    winner_kernel<<<(BATCH * NPILLAR + 255) / 256, 256>>>(idxs);
    pointnet_hmma<<<BATCH * NPILLAR / 8, 256, smemP>>>(pillars, idxs,
                                                       pn_w0, pn_b0, pn_w1, pn_b1);

    dim3 cgrid(NX / 16, NY / 8, BATCH);   // (15, 30, 4)
    conv3x3_hmma<64, false><<<cgrid, 256, smem1>>>(p_img, p_wb1, cb0, p_x1, nullptr, nullptr);
    conv3x3_hmma<128, true><<<cgrid, 256, smem2>>>(p_x1,  p_wb2, cb1, out,  cw2,     cb2);
}

// round 13
// speedup vs baseline: 6.9767x; 1.0396x over previous
#include <cuda_runtime.h>
#include <cuda_fp16.h>
#include <cstdint>
#include <math.h>
#include <float.h>

#define BATCH 4
#define NPILLAR 5000
#define NPT 100
#define CPT 8
#define NX 240
#define NY 240
#define F 64      // PN_FEAT
#define C1 128    // conv hidden channels

// ---------------- scratch (device globals; no allocation allowed) ----------------
__device__ __align__(16) __half g_img[BATCH * NX * NY * F];    // fp16 BEV image
__device__ __align__(16) __half g_x1 [BATCH * NX * NY * C1];   // fp16 conv1 output
__device__ int g_winner[BATCH * NX * NY];
// fp16 weights, K-blocked fragment-order layout [tap][k/8][co][8]
__device__ __align__(16) __half g_wb1[9 * 64 * 128];    // conv1 (CIN=64)
__device__ __align__(16) __half g_wb2[9 * 128 * 128];   // conv2 (CIN=128)

// ---------------- HMMA + ldmatrix (plain sm_75/80 PTX) ---------------------------
__device__ __forceinline__ void mma_f16(float* d, const uint32_t* a, const uint32_t* b) {
    asm volatile(
        "mma.sync.aligned.m16n8k16.row.col.f32.f16.f16.f32 "
        "{%0,%1,%2,%3}, {%4,%5,%6,%7}, {%8,%9}, {%0,%1,%2,%3};"
        : "+f"(d[0]), "+f"(d[1]), "+f"(d[2]), "+f"(d[3])
        : "r"(a[0]), "r"(a[1]), "r"(a[2]), "r"(a[3]), "r"(b[0]), "r"(b[1]));
}
__device__ __forceinline__ void mma_f16_k8(float* d, const uint32_t* a, uint32_t b) {
    asm volatile(
        "mma.sync.aligned.m16n8k8.row.col.f32.f16.f16.f32 "
        "{%0,%1,%2,%3}, {%4,%5}, {%6}, {%0,%1,%2,%3};"
        : "+f"(d[0]), "+f"(d[1]), "+f"(d[2]), "+f"(d[3])
        : "r"(a[0]), "r"(a[1]), "r"(b));
}
__device__ __forceinline__ void ldsm_x4(uint32_t* r, uint32_t addr) {
    asm volatile("ldmatrix.sync.aligned.m8n8.x4.shared.b16 {%0,%1,%2,%3}, [%4];"
        : "=r"(r[0]), "=r"(r[1]), "=r"(r[2]), "=r"(r[3]) : "r"(addr));
}
__device__ __forceinline__ uint32_t smem_u32(const void* p) {
    uint32_t a;
    asm("{ .reg .u64 t; cvta.to.shared.u64 t, %1; cvt.u32.u64 %0, t; }" : "=r"(a) : "l"(p));
    return a;
}
__device__ __forceinline__ void cpasync16(uint32_t s, const void* g) {
    asm volatile("cp.async.cg.shared.global [%0], [%1], 16;" :: "r"(s), "l"(g));
}
#define CP_COMMIT() asm volatile("cp.async.commit_group;" ::: "memory")
#define CP_WAIT(n)  asm volatile("cp.async.wait_group %0;" :: "n"(n) : "memory")
__device__ __forceinline__ float tanh_fast(float x) {
    float y;
    asm("tanh.approx.f32 %0, %1;" : "=f"(y) : "f"(x));
    return y;
}
__device__ __forceinline__ uint32_t pkh2(float a, float b) {
    __half2 h;
    h.x = __float2half_rn(a);
    h.y = __float2half_rn(b);
    return *(uint32_t*)&h;
}

// ---------------- 1) prep: zero BEV image + init winner + conv weight prep -------
__global__ void prep_kernel(const float* __restrict__ cw0, const float* __restrict__ cw1) {
    int tid = blockIdx.x * blockDim.x + threadIdx.x;
    int stride = gridDim.x * blockDim.x;
    const int n8 = BATCH * NX * NY * F / 8;
    uint4 z = make_uint4(0, 0, 0, 0);
    for (int i = tid; i < n8; i += stride)
        reinterpret_cast<uint4*>(g_img)[i] = z;
    for (int i = tid; i < BATCH * NX * NY; i += stride)
        g_winner[i] = -1;
    for (int i = tid; i < 9 * 128 * 64; i += stride) {      // conv1 weights
        int ci = i % 64, co = (i / 64) % 128, tap = i / (64 * 128);
        float v = cw0[((size_t)tap * 64 + ci) * C1 + co];
        g_wb1[((size_t)tap * 8 + (ci >> 3)) * 1024 + co * 8 + (ci & 7)] = __float2half_rn(v);
    }
    for (int i = tid; i < 9 * 128 * 128; i += stride) {     // conv2 weights
        int ci = i % 128, co = (i / 128) % 128, tap = i / (128 * 128);
        float v = cw1[((size_t)tap * 128 + ci) * C1 + co];
        g_wb2[((size_t)tap * 16 + (ci >> 3)) * 1024 + co * 8 + (ci & 7)] = __float2half_rn(v);
    }
}

// ---------------- 2) duplicate-cell winner (last update wins = max pillar idx) ---
__global__ void winner_kernel(const int* __restrict__ idxs) {
    int p = blockIdx.x * blockDim.x + threadIdx.x;
    if (p >= BATCH * NPILLAR) return;
    int b = p / NPILLAR, pl = p % NPILLAR;
    int ix = idxs[2 * p], iy = idxs[2 * p + 1];
    atomicMax(&g_winner[(b * NX + ix) * NY + iy], pl);
}

// ---------------- 3) pointnet, all-HMMA, 8 pillars/CTA, fused scatter ------------
__global__ __launch_bounds__(256) void pointnet_hmma(
    const float* __restrict__ pillars, const int* __restrict__ idxs,
    const float* __restrict__ w0, const float* __restrict__ b0,
    const float* __restrict__ w1, const float* __restrict__ b1) {

    extern __shared__ char sm[];
    __half* sX   = (__half*)sm;                       // 256 * 8  (4096 B)
    __half* sW0h = (__half*)(sm + 4096);              // 64 * 8   (1024 B)  [n][k]
    __half* sW   = (__half*)(sm + 5120);              // 4096     (8192 B)  [kb][n][8]
    float* sB0  = (float*)(sm + 13312);               // 64
    float* sB1  = sB0 + 64;                           // 64
    float* sRed = sB1 + 64;                           // 512
    int*   sCode = (int*)(sRed + 512);                // 256

    int tid = threadIdx.x, lane = tid & 31, wid = tid >> 5;

    if (tid < 64) { sB0[tid] = b0[tid]; sB1[tid] = b1[tid]; }
    for (int i = tid; i < 512; i += 256) {            // w0: [k=8][n=64] -> [n][k]
        int k = i >> 6, n = i & 63;
        sW0h[n * 8 + k] = __float2half_rn(w0[i]);
    }
    for (int i = tid; i < 4096; i += 256) {           // w1 -> K-blocked
        int k = i >> 6, n = i & 63;
        sW[(k >> 3) * 512 + n * 8 + (k & 7)] = __float2half_rn(w1[i]);
    }
    __syncthreads();

    const int gi = lane >> 2, q2 = (lane & 3) * 2;
    const int wbase = wid * 32;

    for (int it = 0; it < 4; ++it) {
        const int pbase = blockIdx.x * 8 + it * 2;

        {   // ---- stage X: one thread per row, fp16 [row][8] ----
            int row = tid;
            int pt = row & 127;
            if (pt < NPT) {
                int pil = pbase + (row >> 7);
                const float4* px = (const float4*)(pillars + ((size_t)pil * NPT + pt) * CPT);
                float4 A = __ldg(px), B = __ldg(px + 1);
                float x[8] = {A.x, A.y, A.z, A.w, B.x, B.y, B.z, B.w};
                float ss = 0.f;
                #pragma unroll
                for (int k = 0; k < 8; k++) ss += x[k] * x[k];
                sCode[row] = (ss < 1e12f) ? 0 : 1;
                uint4 v;
                v.x = pkh2(x[0], x[1]); v.y = pkh2(x[2], x[3]);
                v.z = pkh2(x[4], x[5]); v.w = pkh2(x[6], x[7]);
                *(uint4*)&sX[row * 8] = v;
            } else {
                sCode[row] = 2;
                *(uint4*)&sX[row * 8] = make_uint4(0, 0, 0, 0);
            }
        }
        __syncthreads();

        // ---- layer 0: m16n8k8, acc initialized with bias ----
        float acc0[2][8][4];
        uint32_t ax[2][2];
        #pragma unroll
        for (int mt = 0; mt < 2; mt++) {
            ax[mt][0] = *(const uint32_t*)&sX[(wbase + mt * 16 + gi) * 8 + q2];
            ax[mt][1] = *(const uint32_t*)&sX[(wbase + mt * 16 + 8 + gi) * 8 + q2];
        }
        #pragma unroll
        for (int nt = 0; nt < 8; nt++) {
            float bA = sB0[nt * 8 + q2], bB = sB0[nt * 8 + q2 + 1];
            uint32_t b = *(const uint32_t*)&sW0h[(nt * 8 + gi) * 8 + q2];
            #pragma unroll
            for (int mt = 0; mt < 2; mt++) {
                acc0[mt][nt][0] = bA; acc0[mt][nt][1] = bB;
                acc0[mt][nt][2] = bA; acc0[mt][nt][3] = bB;
                mma_f16_k8(acc0[mt][nt], ax[mt], b);
            }
        }

        // ---- tanh + repack in registers (D-frag == A-frag) ----
        uint32_t aH[2][4][4];
        #pragma unroll
        for (int mt = 0; mt < 2; mt++)
        #pragma unroll
        for (int j = 0; j < 4; j++) {
            aH[mt][j][0] = pkh2(tanh_fast(acc0[mt][2 * j][0]),     tanh_fast(acc0[mt][2 * j][1]));
            aH[mt][j][1] = pkh2(tanh_fast(acc0[mt][2 * j][2]),     tanh_fast(acc0[mt][2 * j][3]));
            aH[mt][j][2] = pkh2(tanh_fast(acc0[mt][2 * j + 1][0]), tanh_fast(acc0[mt][2 * j + 1][1]));
            aH[mt][j][3] = pkh2(tanh_fast(acc0[mt][2 * j + 1][2]), tanh_fast(acc0[mt][2 * j + 1][3]));
        }

        // ---- layer 1: m16n8k16, A from registers ----
        float acc[2][8][4] = {};
        #pragma unroll
        for (int j = 0; j < 4; j++) {
            const __half* wp = &sW[(2 * j) * 512 + q2];
            #pragma unroll
            for (int nt = 0; nt < 8; nt++) {
                const int n = nt * 8 + gi;
                uint32_t b[2];
                b[0] = *(const uint32_t*)&wp[n * 8];
                b[1] = *(const uint32_t*)&wp[n * 8 + 512];
                mma_f16(acc[0][nt], aH[0][j], b);
                mma_f16(acc[1][nt], aH[1][j], b);
            }
        }

        // ---- masked max reduction ----
        #pragma unroll
        for (int nt = 0; nt < 8; nt++) {
            int col = nt * 8 + q2;
            float bA = sB1[col], bB = sB1[col + 1];
            float vA = -FLT_MAX, vB = -FLT_MAX;
            #pragma unroll
            for (int mt = 0; mt < 2; mt++) {
                int r0 = wbase + mt * 16 + gi, r1 = r0 + 8;
                int c0 = sCode[r0], c1 = sCode[r1];
                float f;
                f = (c0 == 0) ? acc[mt][nt][0] + bA : ((c0 == 1) ? 0.f : -FLT_MAX);
                vA = fmaxf(vA, f);
                f = (c1 == 0) ? acc[mt][nt][2] + bA : ((c1 == 1) ? 0.f : -FLT_MAX);
                vA = fmaxf(vA, f);
                f = (c0 == 0) ? acc[mt][nt][1] + bB : ((c0 == 1) ? 0.f : -FLT_MAX);
                vB = fmaxf(vB, f);
                f = (c1 == 0) ? acc[mt][nt][3] + bB : ((c1 == 1) ? 0.f : -FLT_MAX);
                vB = fmaxf(vB, f);
            }
            #pragma unroll
            for (int off = 4; off < 32; off <<= 1) {
                vA = fmaxf(vA, __shfl_xor_sync(0xFFFFFFFFu, vA, off));
                vB = fmaxf(vB, __shfl_xor_sync(0xFFFFFFFFu, vB, off));
            }
            if (gi == 0) {
                sRed[wid * 64 + col]     = vA;
                sRed[wid * 64 + col + 1] = vB;
            }
        }
        __syncthreads();

        // ---- fused scatter: winner-checked direct fp16 write into BEV image ----
        if (tid < 128) {
            int pil = tid >> 6, col = tid & 63;
            const float* r = &sRed[pil * 4 * 64 + col];
            float m = fmaxf(fmaxf(r[0], r[64]), fmaxf(r[128], r[192]));
            int p = pbase + pil;
            int b = p / NPILLAR, pl = p % NPILLAR;
            int ix = __ldg(&idxs[2 * p]), iy = __ldg(&idxs[2 * p + 1]);
            int cell = (b * NX + ix) * NY + iy;
            if (g_winner[cell] == pl)
                g_img[(size_t)cell * F + col] = __float2half_rn(m);
        }
    }
}

// ---------------- 5) 3x3 conv, HMMA fp16, A in smem, B direct-LDG (fragment order)
// CTA: 8x16 px (M=128) x 128 cout. 8 warps: (mwarp 0..3) x (nwarp 0..1).
// B fragment words read straight from global (coalesced 128B lines, L1/L2-hot).
// Mainloop has ZERO barriers — one sync after the halo lands.
template <int CIN, bool FUSE>
__global__ __launch_bounds__(256, 2) void conv3x3_hmma(
    const __half* __restrict__ in, const __half* __restrict__ wb,
    const float* __restrict__ bias, void* __restrict__ out_,
    const float* __restrict__ w2, const float* __restrict__ b2) {

    constexpr int KP = CIN + 8;             // A stride in halves
    extern __shared__ char smem[];
    __half* sA = (__half*)smem;                                   // 180 * KP
    float* sbias = (float*)(smem + 180 * KP * 2);                 // 128
    float* sw2   = sbias + 128;                                   // 128
    float* sRed  = sw2 + 128;                                     // 256

    int tid = threadIdx.x, lane = tid & 31, wid = tid >> 5;
    int bb = blockIdx.z;
    int y0 = blockIdx.y * 8, x0 = blockIdx.x * 16;
    if (tid < 128) {
        sbias[tid] = bias[tid];
        if (FUSE) sw2[tid] = w2[tid];
    }
    uint32_t sA32 = smem_u32(sA);

    // ---- stage halo: 180 px x CIN fp16, straight async copy (zero OOB) ----
    constexpr int CH8 = CIN / 8;
    for (int t = tid; t < 180 * CH8; t += 256) {
        int hp = t / CH8, c0 = (t % CH8) * 8;
        int hr = hp / 18, hc = hp % 18;
        int gy = y0 - 1 + hr, gx = x0 - 1 + hc;
        if (gy >= 0 && gy < NX && gx >= 0 && gx < NY)
            cpasync16(sA32 + (hp * KP + c0) * 2,
                      in + (((size_t)bb * NX + gy) * NY + gx) * CIN + c0);
        else
            *(uint4*)&sA[hp * KP + c0] = make_uint4(0, 0, 0, 0);
    }
    CP_COMMIT();
    CP_WAIT(0);
    __syncthreads();                        // the only barrier before the epilogue

    float acc[2][8][4] = {};
    const int mwarp = wid >> 1, nwarp = wid & 1;
    const int gi = lane >> 2;
    const int q2 = (lane & 3) * 2;
    const int le = lane & 7;
    const int lt = lane >> 3;

    // per-thread global B base: fragment word (n*8 + q2) for n = nwarp*64 + gi
    const __half* wB = wb + (nwarp * 64 + gi) * 8 + q2;

    for (int tap = 0; tap < 9; ++tap) {
        const int dy = tap / 3 - 1, dx = tap % 3 - 1;
        uint32_t aBase[2];
        #pragma unroll
        for (int mt = 0; mt < 2; mt++) {
            int hr = mwarp * 2 + mt + 1 + dy;
            int pxrow = hr * 18 + (1 + dx) + le + (lt & 1) * 8;
            aBase[mt] = sA32 + (pxrow * KP + (lt >> 1) * 8) * 2;
        }
        const __half* wT = wB + (size_t)tap * CIN * 128;

        #pragma unroll
        for (int k0 = 0; k0 < CIN; k0 += 16) {
            uint32_t a[2][4];
            ldsm_x4(a[0], aBase[0] + k0 * 2);
            ldsm_x4(a[1], aBase[1] + k0 * 2);
            const __half* wK = wT + (k0 >> 3) * 1024;
            #pragma unroll
            for (int nt = 0; nt < 8; nt++) {
                uint32_t b[2];
                b[0] = __ldg((const uint32_t*)(wK + nt * 64));
                b[1] = __ldg((const uint32_t*)(wK + nt * 64 + 1024));
                mma_f16(acc[0][nt], a[0], b);
                mma_f16(acc[1][nt], a[1], b);
            }
        }
    }

    if (!FUSE) {
        // ---- epilogue: bias + fast tanh -> fp16 store (feeds conv2) ----
        __half* out = (__half*)out_;
        #pragma unroll
        for (int mt = 0; mt < 2; mt++) {
            int gy = y0 + mwarp * 2 + mt;
            #pragma unroll
            for (int half = 0; half < 2; half++) {
                int gx = x0 + gi + half * 8;
                __half* op = &out[(((size_t)bb * NX + gy) * NY + gx) * C1];
                #pragma unroll
                for (int nt = 0; nt < 8; nt++) {
                    int n = nwarp * 64 + nt * 8 + q2;
                    __half2 v;
                    v.x = __float2half_rn(tanh_fast(acc[mt][nt][half * 2 + 0] + sbias[n]));
                    v.y = __float2half_rn(tanh_fast(acc[mt][nt][half * 2 + 1] + sbias[n + 1]));
                    *(__half2*)&op[n] = v;
                }
            }
        }
    } else {
        // ---- fused epilogue: fast tanh + 1x1 conv dot + relu -> fp32 out ----
        float* out = (float*)out_;
        float part[2][2] = {};
        #pragma unroll
        for (int mt = 0; mt < 2; mt++)
        #pragma unroll
        for (int half = 0; half < 2; half++)
        #pragma unroll
        for (int nt = 0; nt < 8; nt++) {
            int n = nwarp * 64 + nt * 8 + q2;
            part[mt][half] += tanh_fast(acc[mt][nt][half * 2 + 0] + sbias[n])     * sw2[n]
                            + tanh_fast(acc[mt][nt][half * 2 + 1] + sbias[n + 1]) * sw2[n + 1];
        }
        #pragma unroll
        for (int mt = 0; mt < 2; mt++)
        #pragma unroll
        for (int half = 0; half < 2; half++) {
            float v = part[mt][half];
            v += __shfl_xor_sync(0xFFFFFFFFu, v, 1);
            v += __shfl_xor_sync(0xFFFFFFFFu, v, 2);
            if ((lane & 3) == 0) {
                int px = (mwarp * 2 + mt) * 16 + gi + half * 8;
                sRed[px * 2 + nwarp] = v;
            }
        }
        __syncthreads();
        if (tid < 128) {
            float v = sRed[tid * 2] + sRed[tid * 2 + 1] + __ldg(b2);
            int gy = y0 + (tid >> 4), gx = x0 + (tid & 15);
            out[((size_t)bb * NX + gy) * NY + gx] = fmaxf(v, 0.f);
        }
    }
}

// ---------------- host launcher ----------------
extern "C" void kernel_launch(void* const* d_in, const int* in_sizes, int n_in,
                              void* d_out, int out_size) {
    const float* pillars = (const float*)d_in[0];
    const int*   idxs    = (const int*)d_in[1];
    const float* pn_w0 = (const float*)d_in[4];
    const float* pn_b0 = (const float*)d_in[5];
    const float* pn_w1 = (const float*)d_in[6];
    const float* pn_b1 = (const float*)d_in[7];
    const float* cw0   = (const float*)d_in[8];
    const float* cb0   = (const float*)d_in[9];
    const float* cw1   = (const float*)d_in[10];
    const float* cb1   = (const float*)d_in[11];
    const float* cw2   = (const float*)d_in[12];
    const float* cb2   = (const float*)d_in[13];
    float* out = (float*)d_out;

    __half *p_img, *p_x1, *p_wb1, *p_wb2;
    cudaGetSymbolAddress((void**)&p_img, g_img);
    cudaGetSymbolAddress((void**)&p_x1, g_x1);
    cudaGetSymbolAddress((void**)&p_wb1, g_wb1);
    cudaGetSymbolAddress((void**)&p_wb2, g_wb2);

    const int smem1 = 180 * (64 + 8)  * 2 + 512 * 4;   // 27,968 B
    const int smem2 = 180 * (128 + 8) * 2 + 512 * 4;   // 51,008 B
    const int smemP = 13312 + (64 + 64 + 512) * 4 + 256 * 4;
    cudaFuncSetAttribute((const void*)conv3x3_hmma<64, false>,
                         cudaFuncAttributeMaxDynamicSharedMemorySize, smem1);
    cudaFuncSetAttribute((const void*)conv3x3_hmma<128, true>,
                         cudaFuncAttributeMaxDynamicSharedMemorySize, smem2);

    prep_kernel<<<1024, 256>>>(cw0, cw1);
    winner_kernel<<<(BATCH * NPILLAR + 255) / 256, 256>>>(idxs);
    pointnet_hmma<<<BATCH * NPILLAR / 8, 256, smemP>>>(pillars, idxs,
                                                       pn_w0, pn_b0, pn_w1, pn_b1);

    dim3 cgrid(NX / 16, NY / 8, BATCH);   // (15, 30, 4)
    conv3x3_hmma<64, false><<<cgrid, 256, smem1>>>(p_img, p_wb1, cb0, p_x1, nullptr, nullptr);
    conv3x3_hmma<128, true><<<cgrid, 256, smem2>>>(p_x1,  p_wb2, cb1, out,  cw2,     cb2);
}